// round 1
// baseline (speedup 1.0000x reference)
#include <cuda_runtime.h>
#include <cuda_bf16.h>
#include <math.h>

// Problem constants
#define TOK   4096          // B*S
#define DM    1024          // d_model
#define D3    3072          // 3*d_model
#define NHEAD 16
#define DH    64
#define DFF   4096
#define NEXP  8
#define SEQ   1024
#define NB    4

// ---------------- scratch (device globals; no allocs allowed) ----------------
__device__ float g_qkv[(size_t)TOK * D3];          // 48 MB
__device__ float g_attn[(size_t)TOK * DM];         // 16 MB
__device__ float g_proj[(size_t)TOK * DM];         // 16 MB
__device__ float g_x1[(size_t)TOK * DM];           // 16 MB
__device__ float g_H[(size_t)NEXP * TOK * DFF];    // 512 MB
__device__ float g_Y[(size_t)NEXP * TOK * DM];     // 128 MB

__device__ int   d_count[NEXP];
__device__ float d_Psum[NEXP];
__device__ int   d_list[NEXP * TOK];
__device__ int   d_slot[TOK * 2];
__device__ float d_gate[TOK * 2];

// ---------------- small init (must run every launch: graph replays) ----------
__global__ void init_kernel() {
    int i = threadIdx.x;
    if (i < NEXP) { d_count[i] = 0; d_Psum[i] = 0.0f; }
}

// ---------------- generic tiled fp32 GEMM: C = A * op(B) + bias --------------
// A: [M,K] row-major.  transB==0: B [K,N];  transB==1: B [N,K] (C=A*B^T).
// BM=BN=128, BK=16, 256 threads, 8x8 microtile.
__global__ __launch_bounds__(256) void gemm_kernel(
    const float* __restrict__ A, const float* __restrict__ B,
    const float* __restrict__ bias, float* __restrict__ C,
    int M, int N, int K, int transB, int relu)
{
    __shared__ float As[16][132];
    __shared__ float Bs[16][132];
    int tid = threadIdx.x;
    int tx = tid & 15, ty = tid >> 4;
    int m0 = blockIdx.y * 128, n0 = blockIdx.x * 128;
    float acc[8][8];
#pragma unroll
    for (int i = 0; i < 8; i++)
#pragma unroll
        for (int j = 0; j < 8; j++) acc[i][j] = 0.0f;

    for (int k0 = 0; k0 < K; k0 += 16) {
        // A tile: 128 rows x 16 cols -> As[k][m] (transposed store)
#pragma unroll
        for (int li = 0; li < 2; li++) {
            int f = tid + li * 256;
            int row = f >> 2, c4 = (f & 3) << 2;
            float4 v = make_float4(0.f, 0.f, 0.f, 0.f);
            int gr = m0 + row;
            if (gr < M) v = *(const float4*)(A + (size_t)gr * K + k0 + c4);
            As[c4 + 0][row] = v.x; As[c4 + 1][row] = v.y;
            As[c4 + 2][row] = v.z; As[c4 + 3][row] = v.w;
        }
        // B tile -> Bs[k][n]
        if (!transB) {
#pragma unroll
            for (int li = 0; li < 2; li++) {
                int f = tid + li * 256;
                int row = f >> 5, c4 = (f & 31) << 2;
                float4 v = *(const float4*)(B + (size_t)(k0 + row) * N + n0 + c4);
                *(float4*)&Bs[row][c4] = v;
            }
        } else {
#pragma unroll
            for (int li = 0; li < 2; li++) {
                int f = tid + li * 256;
                int row = f >> 2, c4 = (f & 3) << 2;
                float4 v = *(const float4*)(B + (size_t)(n0 + row) * K + k0 + c4);
                Bs[c4 + 0][row] = v.x; Bs[c4 + 1][row] = v.y;
                Bs[c4 + 2][row] = v.z; Bs[c4 + 3][row] = v.w;
            }
        }
        __syncthreads();
#pragma unroll
        for (int k = 0; k < 16; k++) {
            float av[8], bv[8];
            *(float4*)&av[0] = *(const float4*)&As[k][ty * 8];
            *(float4*)&av[4] = *(const float4*)&As[k][ty * 8 + 4];
            *(float4*)&bv[0] = *(const float4*)&Bs[k][tx * 8];
            *(float4*)&bv[4] = *(const float4*)&Bs[k][tx * 8 + 4];
#pragma unroll
            for (int i = 0; i < 8; i++)
#pragma unroll
                for (int j = 0; j < 8; j++) acc[i][j] += av[i] * bv[j];
        }
        __syncthreads();
    }
#pragma unroll
    for (int i = 0; i < 8; i++) {
        int gr = m0 + ty * 8 + i;
        if (gr >= M) continue;
#pragma unroll
        for (int j = 0; j < 8; j++) {
            int gc = n0 + tx * 8 + j;
            float v = acc[i][j] + (bias ? bias[gc] : 0.0f);
            if (relu) v = fmaxf(v, 0.0f);
            C[(size_t)gr * N + gc] = v;
        }
    }
}

// ---------------- expert (grouped) GEMM: per-expert M=count[e] ----------------
// lists != nullptr: A row gathered from Abase via lists[e*TOK + r] (w1 pass).
// lists == nullptr: A = Abase + e*TOK*K (w2 pass, reads H buffer).
// B = Bbase + e*K*N, bias = biasBase + e*N, C = Cbase + e*TOK*N.
__global__ __launch_bounds__(256) void expert_gemm_kernel(
    const float* __restrict__ Abase, const float* __restrict__ Bbase,
    const float* __restrict__ biasBase, float* __restrict__ Cbase,
    const int* __restrict__ counts, const int* __restrict__ lists,
    int N, int K, int relu)
{
    int e = blockIdx.z;
    int M = counts[e];
    int m0 = blockIdx.y * 128;
    if (m0 >= M) return;  // uniform early exit (before any sync)
    int n0 = blockIdx.x * 128;

    const float* B   = Bbase + (size_t)e * K * N;
    const float* bias = biasBase + (size_t)e * N;
    float* C = Cbase + (size_t)e * TOK * N;
    const float* A = lists ? Abase : (Abase + (size_t)e * TOK * K);
    const int* lst = lists ? (lists + (size_t)e * TOK) : nullptr;

    __shared__ float As[16][132];
    __shared__ float Bs[16][132];
    int tid = threadIdx.x;
    int tx = tid & 15, ty = tid >> 4;
    float acc[8][8];
#pragma unroll
    for (int i = 0; i < 8; i++)
#pragma unroll
        for (int j = 0; j < 8; j++) acc[i][j] = 0.0f;

    for (int k0 = 0; k0 < K; k0 += 16) {
#pragma unroll
        for (int li = 0; li < 2; li++) {
            int f = tid + li * 256;
            int row = f >> 2, c4 = (f & 3) << 2;
            float4 v = make_float4(0.f, 0.f, 0.f, 0.f);
            int gr = m0 + row;
            if (gr < M) {
                size_t arow = lst ? (size_t)lst[gr] : (size_t)gr;
                v = *(const float4*)(A + arow * K + k0 + c4);
            }
            As[c4 + 0][row] = v.x; As[c4 + 1][row] = v.y;
            As[c4 + 2][row] = v.z; As[c4 + 3][row] = v.w;
        }
#pragma unroll
        for (int li = 0; li < 2; li++) {
            int f = tid + li * 256;
            int row = f >> 5, c4 = (f & 31) << 2;
            float4 v = *(const float4*)(B + (size_t)(k0 + row) * N + n0 + c4);
            *(float4*)&Bs[row][c4] = v;
        }
        __syncthreads();
#pragma unroll
        for (int k = 0; k < 16; k++) {
            float av[8], bv[8];
            *(float4*)&av[0] = *(const float4*)&As[k][ty * 8];
            *(float4*)&av[4] = *(const float4*)&As[k][ty * 8 + 4];
            *(float4*)&bv[0] = *(const float4*)&Bs[k][tx * 8];
            *(float4*)&bv[4] = *(const float4*)&Bs[k][tx * 8 + 4];
#pragma unroll
            for (int i = 0; i < 8; i++)
#pragma unroll
                for (int j = 0; j < 8; j++) acc[i][j] += av[i] * bv[j];
        }
        __syncthreads();
    }
#pragma unroll
    for (int i = 0; i < 8; i++) {
        int gr = m0 + ty * 8 + i;
        if (gr >= M) continue;
#pragma unroll
        for (int j = 0; j < 8; j++) {
            int gc = n0 + tx * 8 + j;
            float v = acc[i][j] + bias[gc];
            if (relu) v = fmaxf(v, 0.0f);
            C[(size_t)gr * N + gc] = v;
        }
    }
}

// ---------------- attention: 4 query rows / block, one warp per row ----------
__global__ __launch_bounds__(128) void attn_kernel(
    const float* __restrict__ qkv, float* __restrict__ attn_out)
{
    __shared__ float tile[64][65];
    __shared__ float sc[4][1024];
    __shared__ float qs[4][64];

    int bh = blockIdx.x;
    int b = bh >> 4, h = bh & 15;
    int tid = threadIdx.x;
    int w = tid >> 5, lane = tid & 31;
    int qrow = blockIdx.y * 4 + w;
    size_t tq = (size_t)(b * SEQ + qrow);
    int hoff = h * DH;

    qs[w][lane]      = qkv[tq * D3 + hoff + lane];
    qs[w][lane + 32] = qkv[tq * D3 + hoff + lane + 32];

    // score pass: K tiles of 64 keys, transposed in smem
    for (int kt = 0; kt < 16; kt++) {
        __syncthreads();
        for (int idx = tid; idx < 4096; idx += 128) {
            int key = idx >> 6, d = idx & 63;
            tile[d][key] = qkv[(size_t)(b * SEQ + kt * 64 + key) * D3 + DM + hoff + d];
        }
        __syncthreads();
        int k0 = lane * 2, k1 = lane * 2 + 1;
        float s0 = 0.f, s1 = 0.f;
#pragma unroll
        for (int d = 0; d < 64; d++) {
            float qd = qs[w][d];
            s0 += qd * tile[d][k0];
            s1 += qd * tile[d][k1];
        }
        sc[w][kt * 64 + k0] = s0 * 0.125f;   // 1/sqrt(64)
        sc[w][kt * 64 + k1] = s1 * 0.125f;
    }
    // softmax over this warp's 1024 scores
    float m = -1e30f;
    for (int i = lane; i < 1024; i += 32) m = fmaxf(m, sc[w][i]);
#pragma unroll
    for (int off = 16; off; off >>= 1) m = fmaxf(m, __shfl_xor_sync(0xffffffffu, m, off));
    float sum = 0.f;
    for (int i = lane; i < 1024; i += 32) {
        float p = __expf(sc[w][i] - m);
        sc[w][i] = p;
        sum += p;
    }
#pragma unroll
    for (int off = 16; off; off >>= 1) sum += __shfl_xor_sync(0xffffffffu, sum, off);
    float inv = 1.0f / sum;

    // V pass
    float a0 = 0.f, a1 = 0.f;
    int d0 = lane * 2, d1 = lane * 2 + 1;
    for (int vt = 0; vt < 16; vt++) {
        __syncthreads();
        for (int idx = tid; idx < 4096; idx += 128) {
            int key = idx >> 6, d = idx & 63;
            tile[key][d] = qkv[(size_t)(b * SEQ + vt * 64 + key) * D3 + 2 * DM + hoff + d];
        }
        __syncthreads();
#pragma unroll
        for (int key = 0; key < 64; key++) {
            float p = sc[w][vt * 64 + key];
            a0 += p * tile[key][d0];
            a1 += p * tile[key][d1];
        }
    }
    attn_out[tq * DM + hoff + d0] = a0 * inv;
    attn_out[tq * DM + hoff + d1] = a1 * inv;
}

// ---------------- block reduce helper ----------------
__device__ __forceinline__ float blk_sum(float v, float* red) {
    int tid = threadIdx.x;
    red[tid] = v;
    __syncthreads();
#pragma unroll
    for (int s = 128; s > 0; s >>= 1) {
        if (tid < s) red[tid] += red[tid + s];
        __syncthreads();
    }
    float r = red[0];
    __syncthreads();
    return r;
}

// ---------------- add + layernorm: out = LN(a + b) ----------------
__global__ __launch_bounds__(256) void add_ln_kernel(
    const float* __restrict__ a, const float* __restrict__ b,
    const float* __restrict__ g, const float* __restrict__ bb,
    float* __restrict__ out)
{
    __shared__ float red[256];
    size_t t = blockIdx.x;
    int tid = threadIdx.x;
    float v[4];
    float s = 0.f;
#pragma unroll
    for (int i = 0; i < 4; i++) {
        int d = tid + i * 256;
        v[i] = a[t * DM + d] + b[t * DM + d];
        s += v[i];
    }
    float mu = blk_sum(s, red) * (1.0f / DM);
    float sq = 0.f;
#pragma unroll
    for (int i = 0; i < 4; i++) { float c = v[i] - mu; sq += c * c; }
    float var = blk_sum(sq, red) * (1.0f / DM);
    float rstd = rsqrtf(var + 1e-5f);
#pragma unroll
    for (int i = 0; i < 4; i++) {
        int d = tid + i * 256;
        out[t * DM + d] = (v[i] - mu) * rstd * g[d] + bb[d];
    }
}

// ---------------- router: logits, softmax, top2, lists, lb stats -------------
__global__ __launch_bounds__(256) void router_kernel(
    const float* __restrict__ x1, const float* __restrict__ rw,
    const float* __restrict__ rb)
{
    __shared__ float logits[NEXP];
    size_t t = blockIdx.x;
    int tid = threadIdx.x;
    int w = tid >> 5, lane = tid & 31;
    if (w < NEXP) {
        float s = 0.f;
        for (int k = lane; k < DM; k += 32)
            s += x1[t * DM + k] * rw[(size_t)w * DM + k];
#pragma unroll
        for (int off = 16; off; off >>= 1) s += __shfl_xor_sync(0xffffffffu, s, off);
        if (lane == 0) logits[w] = s + rb[w];
    }
    __syncthreads();
    if (tid == 0) {
        float p[NEXP];
        float mx = logits[0];
#pragma unroll
        for (int e = 1; e < NEXP; e++) mx = fmaxf(mx, logits[e]);
        float sum = 0.f;
#pragma unroll
        for (int e = 0; e < NEXP; e++) { p[e] = expf(logits[e] - mx); sum += p[e]; }
        float inv = 1.0f / sum;
#pragma unroll
        for (int e = 0; e < NEXP; e++) {
            p[e] *= inv;
            atomicAdd(&d_Psum[e], p[e]);
        }
        int i0 = 0;
#pragma unroll
        for (int e = 1; e < NEXP; e++) if (p[e] > p[i0]) i0 = e;
        int i1 = (i0 == 0) ? 1 : 0;
#pragma unroll
        for (int e = 0; e < NEXP; e++) if (e != i0 && p[e] > p[i1]) i1 = e;
        float gsum = p[i0] + p[i1];
        float g0 = p[i0] / gsum, g1 = p[i1] / gsum;

        int pos0 = atomicAdd(&d_count[i0], 1);
        d_list[i0 * TOK + pos0] = (int)t;
        d_slot[t * 2 + 0] = i0 * TOK + pos0;
        d_gate[t * 2 + 0] = g0;

        int pos1 = atomicAdd(&d_count[i1], 1);
        d_list[i1 * TOK + pos1] = (int)t;
        d_slot[t * 2 + 1] = i1 * TOK + pos1;
        d_gate[t * 2 + 1] = g1;
    }
}

// ---------------- combine gated experts + residual + LN2 -> out --------------
__global__ __launch_bounds__(256) void combine_ln_kernel(
    const float* __restrict__ Y, const float* __restrict__ x1,
    const float* __restrict__ g, const float* __restrict__ bb,
    float* __restrict__ out)
{
    __shared__ float red[256];
    size_t t = blockIdx.x;
    int tid = threadIdx.x;
    size_t s0 = (size_t)d_slot[t * 2 + 0];
    size_t s1 = (size_t)d_slot[t * 2 + 1];
    float g0 = d_gate[t * 2 + 0], g1 = d_gate[t * 2 + 1];
    float v[4];
    float s = 0.f;
#pragma unroll
    for (int i = 0; i < 4; i++) {
        int d = tid + i * 256;
        float y = g0 * Y[s0 * DM + d] + g1 * Y[s1 * DM + d];
        v[i] = x1[t * DM + d] + y;
        s += v[i];
    }
    float mu = blk_sum(s, red) * (1.0f / DM);
    float sq = 0.f;
#pragma unroll
    for (int i = 0; i < 4; i++) { float c = v[i] - mu; sq += c * c; }
    float var = blk_sum(sq, red) * (1.0f / DM);
    float rstd = rsqrtf(var + 1e-5f);
#pragma unroll
    for (int i = 0; i < 4; i++) {
        int d = tid + i * 256;
        out[t * DM + d] = (v[i] - mu) * rstd * g[d] + bb[d];
    }
}

// ---------------- load-balance loss ----------------
__global__ void lb_kernel(float* __restrict__ out, int out_size) {
    if (out_size > TOK * DM) {
        float lb = 0.f;
#pragma unroll
        for (int e = 0; e < NEXP; e++) {
            float f = (float)d_count[e] / (float)(TOK * 2);   // mask.mean/TOP_K
            float P = d_Psum[e] / (float)TOK;
            lb += f * P;
        }
        out[out_size - 1] = (float)NEXP * lb;
    }
}

// ---------------- launch ----------------
extern "C" void kernel_launch(void* const* d_in, const int* in_sizes, int n_in,
                              void* d_out, int out_size)
{
    const float* src   = (const float*)d_in[0];
    const float* in_w  = (const float*)d_in[1];
    const float* in_b  = (const float*)d_in[2];
    const float* out_w = (const float*)d_in[3];
    const float* out_b = (const float*)d_in[4];
    const float* ln1g  = (const float*)d_in[5];
    const float* ln1b  = (const float*)d_in[6];
    const float* rw    = (const float*)d_in[7];
    const float* rb    = (const float*)d_in[8];
    const float* w1    = (const float*)d_in[9];
    const float* b1    = (const float*)d_in[10];
    const float* w2    = (const float*)d_in[11];
    const float* b2    = (const float*)d_in[12];
    const float* ln2g  = (const float*)d_in[13];
    const float* ln2b  = (const float*)d_in[14];
    float* out = (float*)d_out;

    void *p_qkv, *p_attn, *p_proj, *p_x1, *p_H, *p_Y, *p_cnt, *p_list;
    cudaGetSymbolAddress(&p_qkv,  g_qkv);
    cudaGetSymbolAddress(&p_attn, g_attn);
    cudaGetSymbolAddress(&p_proj, g_proj);
    cudaGetSymbolAddress(&p_x1,   g_x1);
    cudaGetSymbolAddress(&p_H,    g_H);
    cudaGetSymbolAddress(&p_Y,    g_Y);
    cudaGetSymbolAddress(&p_cnt,  d_count);
    cudaGetSymbolAddress(&p_list, d_list);
    float* qkv  = (float*)p_qkv;
    float* attn = (float*)p_attn;
    float* proj = (float*)p_proj;
    float* x1   = (float*)p_x1;
    float* H    = (float*)p_H;
    float* Y    = (float*)p_Y;
    int* cnt    = (int*)p_cnt;
    int* list   = (int*)p_list;

    init_kernel<<<1, 32>>>();

    // QKV = src @ in_proj_w^T + b : [4096,3072]
    gemm_kernel<<<dim3(D3 / 128, TOK / 128), 256>>>(src, in_w, in_b, qkv,
                                                    TOK, D3, DM, 1, 0);
    // attention
    attn_kernel<<<dim3(NB * NHEAD, SEQ / 4), 128>>>(qkv, attn);

    // out proj: [4096,1024]
    gemm_kernel<<<dim3(DM / 128, TOK / 128), 256>>>(attn, out_w, out_b, proj,
                                                    TOK, DM, DM, 1, 0);
    // x1 = LN(src + proj)
    add_ln_kernel<<<TOK, 256>>>(src, proj, ln1g, ln1b, x1);

    // router (fills lists/slots/gates/counts/Psum)
    router_kernel<<<TOK, 256>>>(x1, rw, rb);

    // expert FFN: H = relu(gather(x1) @ w1 + b1); Y = H @ w2 + b2
    expert_gemm_kernel<<<dim3(DFF / 128, TOK / 128, NEXP), 256>>>(
        x1, w1, b1, H, cnt, list, DFF, DM, 1);
    expert_gemm_kernel<<<dim3(DM / 128, TOK / 128, NEXP), 256>>>(
        H, w2, b2, Y, cnt, nullptr, DM, DFF, 0);

    // out = LN(x1 + sum_k gate_k * Y_k)
    combine_ln_kernel<<<TOK, 256>>>(Y, x1, ln2g, ln2b, out);

    // load balance loss scalar
    lb_kernel<<<1, 1>>>(out, out_size);
}

// round 3
// speedup vs baseline: 1.9030x; 1.9030x over previous
#include <cuda_runtime.h>
#include <cuda_bf16.h>
#include <cstdint>
#include <math.h>

// Problem constants
#define TOK   4096          // B*S
#define DM    1024          // d_model
#define D3    3072          // 3*d_model
#define NHEAD 16
#define DH    64
#define DFF   4096
#define NEXP  8
#define SEQ   1024
#define NB    4
#define TOTROWS (2*TOK)     // packed expert rows (top-2)

// ============================ scratch globals ============================
__device__ __align__(16) float g_qkv[(size_t)TOK * D3];
__device__ __align__(16) float g_attn[(size_t)TOK * DM];
__device__ __align__(16) float g_proj[(size_t)TOK * DM];
__device__ __align__(16) float g_x1[(size_t)TOK * DM];
__device__ __align__(16) float g_Y[(size_t)TOTROWS * DM];

__device__ __align__(16) __nv_bfloat16 g_src_h[(size_t)TOK * DM];
__device__ __align__(16) __nv_bfloat16 g_src_l[(size_t)TOK * DM];
__device__ __align__(16) __nv_bfloat16 g_attn_h[(size_t)TOK * DM];
__device__ __align__(16) __nv_bfloat16 g_attn_l[(size_t)TOK * DM];
__device__ __align__(16) __nv_bfloat16 g_x1_h[(size_t)TOK * DM];
__device__ __align__(16) __nv_bfloat16 g_x1_l[(size_t)TOK * DM];
__device__ __align__(16) __nv_bfloat16 g_wqkv_h[(size_t)D3 * DM];
__device__ __align__(16) __nv_bfloat16 g_wqkv_l[(size_t)D3 * DM];
__device__ __align__(16) __nv_bfloat16 g_wo_h[(size_t)DM * DM];
__device__ __align__(16) __nv_bfloat16 g_wo_l[(size_t)DM * DM];
__device__ __align__(16) __nv_bfloat16 g_w1t_h[(size_t)NEXP * DFF * DM];
__device__ __align__(16) __nv_bfloat16 g_w1t_l[(size_t)NEXP * DFF * DM];
__device__ __align__(16) __nv_bfloat16 g_w2t_h[(size_t)NEXP * DM * DFF];
__device__ __align__(16) __nv_bfloat16 g_w2t_l[(size_t)NEXP * DM * DFF];
__device__ __align__(16) __nv_bfloat16 g_H_h[(size_t)TOTROWS * DFF];
__device__ __align__(16) __nv_bfloat16 g_H_l[(size_t)TOTROWS * DFF];

__device__ int   d_count[NEXP];
__device__ int   d_off[NEXP];
__device__ float d_Psum[NEXP];
__device__ int   d_list[NEXP * TOK];
__device__ int   d_slot[TOK * 2];
__device__ float d_gate[TOK * 2];

// ============================ PTX helpers (sm_80-level only) =================
__device__ __forceinline__ uint32_t smem_u32(const void* p) {
    uint32_t a;
    asm("{ .reg .u64 t; cvta.to.shared.u64 t, %1; cvt.u32.u64 %0, t; }"
        : "=r"(a) : "l"(p));
    return a;
}
__device__ __forceinline__ void cp16(uint32_t dst, const void* src, int sz) {
    asm volatile("cp.async.cg.shared.global [%0], [%1], 16, %2;"
                 :: "r"(dst), "l"(src), "r"(sz) : "memory");
}
#define CP_COMMIT() asm volatile("cp.async.commit_group;" ::: "memory")
template<int N_>
__device__ __forceinline__ void cp_wait() {
    asm volatile("cp.async.wait_group %0;" :: "n"(N_) : "memory");
}
__device__ __forceinline__ void mma16816(float* c, const uint32_t* a, const uint32_t* b) {
    asm volatile("mma.sync.aligned.m16n8k16.row.col.f32.bf16.bf16.f32 "
                 "{%0,%1,%2,%3}, {%4,%5,%6,%7}, {%8,%9}, {%0,%1,%2,%3};"
                 : "+f"(c[0]), "+f"(c[1]), "+f"(c[2]), "+f"(c[3])
                 : "r"(a[0]), "r"(a[1]), "r"(a[2]), "r"(a[3]),
                   "r"(b[0]), "r"(b[1]));
}

// ============================ warp-MMA GEMM ============================
// C[M,N] = (Ahi+Alo)[M,K] @ (Bhi+Blo)[N,K]^T + bias, split-bf16 3-term.
// MODE 0: dense, fp32 out.  MODE 1: expert gather A rows + relu + bf16-split out.
// MODE 2: expert offset A rows, fp32 out.
#define BM 128
#define BN 128
#define BK 32
#define RS 40                    // padded smem row stride (bf16 units)
#define AR_ELT (BM * RS)         // 5120 bf16 per array
#define OA_H 0                   // byte offsets inside a stage
#define OA_L 10240
#define OB_H 20480
#define OB_L 30720
#define STG_BYTES 40960
#define GEMM_SMEM (2 * STG_BYTES)

template<int MODE>
__global__ __launch_bounds__(256) void mma_gemm(
    const __nv_bfloat16* __restrict__ AH, const __nv_bfloat16* __restrict__ AL,
    const __nv_bfloat16* __restrict__ BH, const __nv_bfloat16* __restrict__ BL,
    const float* __restrict__ biasBase,
    float* __restrict__ Cf, __nv_bfloat16* __restrict__ CH, __nv_bfloat16* __restrict__ CL,
    const int* __restrict__ counts, const int* __restrict__ offs,
    const int* __restrict__ listBase,
    int Mfix, int N, int K)
{
    extern __shared__ __nv_bfloat16 smbf[];
    const int tid = threadIdx.x;
    const int lane = tid & 31, wid = tid >> 5;
    const int wm = wid & 3, wn = wid >> 2;       // 4 x 2 warp grid
    const int g = lane >> 2, tig = lane & 3;
    const int m0 = blockIdx.y * BM, n0 = blockIdx.x * BN;
    const int e = blockIdx.z;

    int M = Mfix;
    const __nv_bfloat16 *bhp = BH, *blp = BL;
    const float* bias = biasBase;
    const int* lst = nullptr;
    int arow0 = 0, crow0 = 0;
    if (MODE == 1) {
        M = counts[e];
        bhp += (size_t)e * N * K; blp += (size_t)e * N * K;
        bias += (size_t)e * N;
        lst = listBase + e * TOK;
        crow0 = offs[e];
    } else if (MODE == 2) {
        M = counts[e];
        bhp += (size_t)e * N * K; blp += (size_t)e * N * K;
        bias += (size_t)e * N;
        arow0 = offs[e]; crow0 = offs[e];
    }
    if (m0 >= M) return;

    const uint32_t sb = smem_u32(smbf);

    float acc[2][8][4];
#pragma unroll
    for (int mt = 0; mt < 2; mt++)
#pragma unroll
        for (int nt = 0; nt < 8; nt++)
#pragma unroll
            for (int i = 0; i < 4; i++) acc[mt][nt][i] = 0.0f;

    auto load_stage = [&](int st, int k0) {
        uint32_t sbase = sb + st * STG_BYTES;
#pragma unroll
        for (int i = 0; i < 2; i++) {
            int ch = tid + i * 256;                  // 0..511
            int row = ch >> 2, seg = ch & 3;
            uint32_t doff = (uint32_t)(row * RS + seg * 8) * 2;
            int gr = m0 + row;
            size_t arow; int sz;
            if (MODE == 1) {
                bool ok = gr < M;
                arow = ok ? (size_t)lst[gr] : 0; sz = ok ? 16 : 0;
            } else if (MODE == 2) {
                bool ok = gr < M;
                arow = (size_t)(arow0 + (ok ? gr : 0)); sz = ok ? 16 : 0;
            } else { arow = (size_t)gr; sz = 16; }
            size_t aoff = arow * (size_t)K + k0 + seg * 8;
            cp16(sbase + OA_H + doff, AH + aoff, sz);
            cp16(sbase + OA_L + doff, AL + aoff, sz);
            size_t boff = (size_t)(n0 + row) * K + k0 + seg * 8;
            cp16(sbase + OB_H + doff, bhp + boff, 16);
            cp16(sbase + OB_L + doff, blp + boff, 16);
        }
    };

    auto compute = [&](int st) {
        const __nv_bfloat16* pA  = smbf + st * (STG_BYTES / 2);
        const __nv_bfloat16* pAl = pA + AR_ELT;
        const __nv_bfloat16* pB  = pA + 2 * AR_ELT;
        const __nv_bfloat16* pBl = pA + 3 * AR_ELT;
#pragma unroll
        for (int ks = 0; ks < 2; ks++) {
            int kf = ks * 16 + 2 * tig;
            uint32_t bh[8][2], bl[8][2];
#pragma unroll
            for (int nt = 0; nt < 8; nt++) {
                int r = wn * 64 + nt * 8 + g;
                bh[nt][0] = *(const uint32_t*)(pB  + r * RS + kf);
                bh[nt][1] = *(const uint32_t*)(pB  + r * RS + kf + 8);
                bl[nt][0] = *(const uint32_t*)(pBl + r * RS + kf);
                bl[nt][1] = *(const uint32_t*)(pBl + r * RS + kf + 8);
            }
            uint32_t ah[2][4], al[2][4];
#pragma unroll
            for (int mt = 0; mt < 2; mt++) {
                int r = wm * 32 + mt * 16 + g;
                ah[mt][0] = *(const uint32_t*)(pA  + r * RS + kf);
                ah[mt][1] = *(const uint32_t*)(pA  + (r + 8) * RS + kf);
                ah[mt][2] = *(const uint32_t*)(pA  + r * RS + kf + 8);
                ah[mt][3] = *(const uint32_t*)(pA  + (r + 8) * RS + kf + 8);
                al[mt][0] = *(const uint32_t*)(pAl + r * RS + kf);
                al[mt][1] = *(const uint32_t*)(pAl + (r + 8) * RS + kf);
                al[mt][2] = *(const uint32_t*)(pAl + r * RS + kf + 8);
                al[mt][3] = *(const uint32_t*)(pAl + (r + 8) * RS + kf + 8);
            }
#pragma unroll
            for (int mt = 0; mt < 2; mt++)
#pragma unroll
                for (int nt = 0; nt < 8; nt++) {
                    mma16816(acc[mt][nt], ah[mt], bh[nt]);
                    mma16816(acc[mt][nt], ah[mt], bl[nt]);
                    mma16816(acc[mt][nt], al[mt], bh[nt]);
                }
        }
    };

    const int nk = K / BK;
    load_stage(0, 0);
    CP_COMMIT();
    for (int c = 0; c < nk; c++) {
        if (c + 1 < nk) {
            load_stage((c + 1) & 1, (c + 1) * BK);
            CP_COMMIT();
            cp_wait<1>();
        } else {
            cp_wait<0>();
        }
        __syncthreads();
        compute(c & 1);
        __syncthreads();
    }

    // ---- epilogue ----
#pragma unroll
    for (int nt = 0; nt < 8; nt++) {
        int col = n0 + wn * 64 + nt * 8 + 2 * tig;
        float b0 = bias[col], b1 = bias[col + 1];
#pragma unroll
        for (int mt = 0; mt < 2; mt++) {
            int r0 = m0 + wm * 32 + mt * 16 + g;
            float* c = acc[mt][nt];
#pragma unroll
            for (int hh = 0; hh < 2; hh++) {
                int r = r0 + hh * 8;
                if (r < M) {
                    float v0 = c[hh * 2 + 0] + b0;
                    float v1 = c[hh * 2 + 1] + b1;
                    if (MODE == 1) {
                        v0 = fmaxf(v0, 0.0f); v1 = fmaxf(v1, 0.0f);
                        __nv_bfloat16 h0 = __float2bfloat16(v0);
                        __nv_bfloat16 h1 = __float2bfloat16(v1);
                        size_t o = (size_t)(crow0 + r) * N + col;
                        *(__nv_bfloat162*)(CH + o) = __halves2bfloat162(h0, h1);
                        *(__nv_bfloat162*)(CL + o) = __halves2bfloat162(
                            __float2bfloat16(v0 - __bfloat162float(h0)),
                            __float2bfloat16(v1 - __bfloat162float(h1)));
                    } else if (MODE == 2) {
                        size_t o = (size_t)(crow0 + r) * N + col;
                        *(float2*)(Cf + o) = make_float2(v0, v1);
                    } else {
                        *(float2*)(Cf + (size_t)r * N + col) = make_float2(v0, v1);
                    }
                }
            }
        }
    }
}

// ============================ small kernels ============================
__global__ void init_kernel() {
    int i = threadIdx.x;
    if (i < NEXP) { d_count[i] = 0; d_Psum[i] = 0.0f; }
}

__global__ void offsets_kernel() {
    if (threadIdx.x == 0) {
        int a = 0;
#pragma unroll
        for (int e = 0; e < NEXP; e++) { d_off[e] = a; a += d_count[e]; }
    }
}

__global__ __launch_bounds__(256) void split_cvt_kernel(
    const float* __restrict__ x, __nv_bfloat16* __restrict__ h,
    __nv_bfloat16* __restrict__ l, int n4)
{
    int i = blockIdx.x * 256 + threadIdx.x;
    if (i >= n4) return;
    float4 v = ((const float4*)x)[i];
    float vs[4] = {v.x, v.y, v.z, v.w};
    __nv_bfloat16 hv[4], lv[4];
#pragma unroll
    for (int j = 0; j < 4; j++) {
        hv[j] = __float2bfloat16(vs[j]);
        lv[j] = __float2bfloat16(vs[j] - __bfloat162float(hv[j]));
    }
    *(uint2*)(h + i * 4) = *(uint2*)hv;
    *(uint2*)(l + i * 4) = *(uint2*)lv;
}

// per-expert transpose + split: W[e][K][N] -> T[e][N][K] (hi/lo)
__global__ __launch_bounds__(256) void transpose_split_kernel(
    const float* __restrict__ W, __nv_bfloat16* __restrict__ Th,
    __nv_bfloat16* __restrict__ Tl, int K, int N)
{
    __shared__ float t[32][33];
    int e = blockIdx.z;
    const float* w = W + (size_t)e * K * N;
    __nv_bfloat16* th = Th + (size_t)e * N * K;
    __nv_bfloat16* tl = Tl + (size_t)e * N * K;
    int n0 = blockIdx.x * 32, k0 = blockIdx.y * 32;
    int x = threadIdx.x, y = threadIdx.y;
#pragma unroll
    for (int i = 0; i < 32; i += 8)
        t[y + i][x] = w[(size_t)(k0 + y + i) * N + n0 + x];
    __syncthreads();
#pragma unroll
    for (int i = 0; i < 32; i += 8) {
        float v = t[x][y + i];
        __nv_bfloat16 hi = __float2bfloat16(v);
        th[(size_t)(n0 + y + i) * K + k0 + x] = hi;
        tl[(size_t)(n0 + y + i) * K + k0 + x] = __float2bfloat16(v - __bfloat162float(hi));
    }
}

// ============================ attention ============================
#define ATTN_SMEM ((64 * 65 + 16 * 1024 + 16 * 64) * 4)

__global__ __launch_bounds__(128) void attn_kernel(
    const float* __restrict__ qkv, float* __restrict__ attn_out)
{
    extern __shared__ float sm[];
    float (*tile)[65] = (float(*)[65])sm;
    float (*sc)[1024] = (float(*)[1024])(sm + 64 * 65);
    float (*qs)[64]   = (float(*)[64])(sm + 64 * 65 + 16 * 1024);

    int bh = blockIdx.x;
    int b = bh >> 4, h = bh & 15;
    int tid = threadIdx.x, w = tid >> 5, lane = tid & 31;
    int q0 = blockIdx.y * 16;
    int hoff = h * DH;
    int rb = w * 4;

    for (int i = tid; i < 16 * 64; i += 128) {
        int r = i >> 6, d = i & 63;
        qs[r][d] = qkv[(size_t)(b * SEQ + q0 + r) * D3 + hoff + d] * 0.125f;
    }

    for (int kt = 0; kt < 16; kt++) {
        __syncthreads();
        for (int idx = tid; idx < 4096; idx += 128) {
            int key = idx >> 6, d = idx & 63;
            tile[d][key] = qkv[(size_t)(b * SEQ + kt * 64 + key) * D3 + DM + hoff + d];
        }
        __syncthreads();
        int k0 = lane, k1 = lane + 32;
        float s00 = 0.f, s01 = 0.f, s10 = 0.f, s11 = 0.f;
        float s20 = 0.f, s21 = 0.f, s30 = 0.f, s31 = 0.f;
#pragma unroll 8
        for (int d = 0; d < 64; d++) {
            float t0 = tile[d][k0], t1 = tile[d][k1];
            float q0v = qs[rb + 0][d], q1v = qs[rb + 1][d];
            float q2v = qs[rb + 2][d], q3v = qs[rb + 3][d];
            s00 += q0v * t0; s01 += q0v * t1;
            s10 += q1v * t0; s11 += q1v * t1;
            s20 += q2v * t0; s21 += q2v * t1;
            s30 += q3v * t0; s31 += q3v * t1;
        }
        sc[rb + 0][kt * 64 + k0] = s00; sc[rb + 0][kt * 64 + k1] = s01;
        sc[rb + 1][kt * 64 + k0] = s10; sc[rb + 1][kt * 64 + k1] = s11;
        sc[rb + 2][kt * 64 + k0] = s20; sc[rb + 2][kt * 64 + k1] = s21;
        sc[rb + 3][kt * 64 + k0] = s30; sc[rb + 3][kt * 64 + k1] = s31;
    }

    float inv[4];
#pragma unroll
    for (int rr = 0; rr < 4; rr++) {
        int r = rb + rr;
        float m = -1e30f;
        for (int i = lane; i < 1024; i += 32) m = fmaxf(m, sc[r][i]);
#pragma unroll
        for (int off = 16; off; off >>= 1) m = fmaxf(m, __shfl_xor_sync(0xffffffffu, m, off));
        float sum = 0.f;
        for (int i = lane; i < 1024; i += 32) {
            float p = __expf(sc[r][i] - m);
            sc[r][i] = p;
            sum += p;
        }
#pragma unroll
        for (int off = 16; off; off >>= 1) sum += __shfl_xor_sync(0xffffffffu, sum, off);
        inv[rr] = 1.0f / sum;
    }

    int d0 = lane, d1 = lane + 32;
    float a00 = 0.f, a01 = 0.f, a10 = 0.f, a11 = 0.f;
    float a20 = 0.f, a21 = 0.f, a30 = 0.f, a31 = 0.f;
    for (int vt = 0; vt < 16; vt++) {
        __syncthreads();
        for (int idx = tid; idx < 4096; idx += 128) {
            int key = idx >> 6, d = idx & 63;
            tile[key][d] = qkv[(size_t)(b * SEQ + vt * 64 + key) * D3 + 2 * DM + hoff + d];
        }
        __syncthreads();
#pragma unroll 8
        for (int key = 0; key < 64; key++) {
            float v0 = tile[key][d0], v1 = tile[key][d1];
            float p0 = sc[rb + 0][vt * 64 + key], p1 = sc[rb + 1][vt * 64 + key];
            float p2 = sc[rb + 2][vt * 64 + key], p3 = sc[rb + 3][vt * 64 + key];
            a00 += p0 * v0; a01 += p0 * v1;
            a10 += p1 * v0; a11 += p1 * v1;
            a20 += p2 * v0; a21 += p2 * v1;
            a30 += p3 * v0; a31 += p3 * v1;
        }
    }
    size_t base = (size_t)(b * SEQ + q0 + rb) * DM + hoff;
    attn_out[base + 0 * DM + d0] = a00 * inv[0]; attn_out[base + 0 * DM + d1] = a01 * inv[0];
    attn_out[base + 1 * DM + d0] = a10 * inv[1]; attn_out[base + 1 * DM + d1] = a11 * inv[1];
    attn_out[base + 2 * DM + d0] = a20 * inv[2]; attn_out[base + 2 * DM + d1] = a21 * inv[2];
    attn_out[base + 3 * DM + d0] = a30 * inv[3]; attn_out[base + 3 * DM + d1] = a31 * inv[3];
}

// ============================ LN / router / combine / lb ============================
__device__ __forceinline__ float blk_sum(float v, float* red) {
    int tid = threadIdx.x;
    red[tid] = v;
    __syncthreads();
#pragma unroll
    for (int s = 128; s > 0; s >>= 1) {
        if (tid < s) red[tid] += red[tid + s];
        __syncthreads();
    }
    float r = red[0];
    __syncthreads();
    return r;
}

__global__ __launch_bounds__(256) void add_ln_kernel(
    const float* __restrict__ a, const float* __restrict__ b,
    const float* __restrict__ g, const float* __restrict__ bb,
    float* __restrict__ out)
{
    __shared__ float red[256];
    size_t t = blockIdx.x;
    int tid = threadIdx.x;
    float v[4];
    float s = 0.f;
#pragma unroll
    for (int i = 0; i < 4; i++) {
        int d = tid + i * 256;
        v[i] = a[t * DM + d] + b[t * DM + d];
        s += v[i];
    }
    float mu = blk_sum(s, red) * (1.0f / DM);
    float sq = 0.f;
#pragma unroll
    for (int i = 0; i < 4; i++) { float c = v[i] - mu; sq += c * c; }
    float var = blk_sum(sq, red) * (1.0f / DM);
    float rstd = rsqrtf(var + 1e-5f);
#pragma unroll
    for (int i = 0; i < 4; i++) {
        int d = tid + i * 256;
        out[t * DM + d] = (v[i] - mu) * rstd * g[d] + bb[d];
    }
}

__global__ __launch_bounds__(256) void router_kernel(
    const float* __restrict__ x1, const float* __restrict__ rw,
    const float* __restrict__ rb)
{
    __shared__ float logits[NEXP];
    size_t t = blockIdx.x;
    int tid = threadIdx.x;
    int w = tid >> 5, lane = tid & 31;
    if (w < NEXP) {
        float s = 0.f;
        for (int k = lane; k < DM; k += 32)
            s += x1[t * DM + k] * rw[(size_t)w * DM + k];
#pragma unroll
        for (int off = 16; off; off >>= 1) s += __shfl_xor_sync(0xffffffffu, s, off);
        if (lane == 0) logits[w] = s + rb[w];
    }
    __syncthreads();
    if (tid == 0) {
        float p[NEXP];
        float mx = logits[0];
#pragma unroll
        for (int e = 1; e < NEXP; e++) mx = fmaxf(mx, logits[e]);
        float sum = 0.f;
#pragma unroll
        for (int e = 0; e < NEXP; e++) { p[e] = expf(logits[e] - mx); sum += p[e]; }
        float invs = 1.0f / sum;
#pragma unroll
        for (int e = 0; e < NEXP; e++) {
            p[e] *= invs;
            atomicAdd(&d_Psum[e], p[e]);
        }
        int i0 = 0;
#pragma unroll
        for (int e = 1; e < NEXP; e++) if (p[e] > p[i0]) i0 = e;
        int i1 = (i0 == 0) ? 1 : 0;
#pragma unroll
        for (int e = 0; e < NEXP; e++) if (e != i0 && p[e] > p[i1]) i1 = e;
        float gsum = p[i0] + p[i1];

        int pos0 = atomicAdd(&d_count[i0], 1);
        d_list[i0 * TOK + pos0] = (int)t;
        d_slot[t * 2 + 0] = i0 * TOK + pos0;
        d_gate[t * 2 + 0] = p[i0] / gsum;

        int pos1 = atomicAdd(&d_count[i1], 1);
        d_list[i1 * TOK + pos1] = (int)t;
        d_slot[t * 2 + 1] = i1 * TOK + pos1;
        d_gate[t * 2 + 1] = p[i1] / gsum;
    }
}

__global__ __launch_bounds__(256) void combine_ln_kernel(
    const float* __restrict__ Y, const float* __restrict__ x1,
    const float* __restrict__ g, const float* __restrict__ bb,
    float* __restrict__ out)
{
    __shared__ float red[256];
    size_t t = blockIdx.x;
    int tid = threadIdx.x;
    int sl0 = d_slot[t * 2 + 0], sl1 = d_slot[t * 2 + 1];
    size_t r0 = (size_t)d_off[sl0 / TOK] + (sl0 % TOK);
    size_t r1 = (size_t)d_off[sl1 / TOK] + (sl1 % TOK);
    float g0 = d_gate[t * 2 + 0], g1 = d_gate[t * 2 + 1];
    float v[4];
    float s = 0.f;
#pragma unroll
    for (int i = 0; i < 4; i++) {
        int d = tid + i * 256;
        float y = g0 * Y[r0 * DM + d] + g1 * Y[r1 * DM + d];
        v[i] = x1[t * DM + d] + y;
        s += v[i];
    }
    float mu = blk_sum(s, red) * (1.0f / DM);
    float sq = 0.f;
#pragma unroll
    for (int i = 0; i < 4; i++) { float c = v[i] - mu; sq += c * c; }
    float var = blk_sum(sq, red) * (1.0f / DM);
    float rstd = rsqrtf(var + 1e-5f);
#pragma unroll
    for (int i = 0; i < 4; i++) {
        int d = tid + i * 256;
        out[t * DM + d] = (v[i] - mu) * rstd * g[d] + bb[d];
    }
}

__global__ void lb_kernel(float* __restrict__ out, int out_size) {
    if (out_size > TOK * DM) {
        float lb = 0.f;
#pragma unroll
        for (int e = 0; e < NEXP; e++) {
            float f = (float)d_count[e] / (float)(TOK * 2);
            float P = d_Psum[e] / (float)TOK;
            lb += f * P;
        }
        out[out_size - 1] = (float)NEXP * lb;
    }
}

// ============================ launch ============================
extern "C" void kernel_launch(void* const* d_in, const int* in_sizes, int n_in,
                              void* d_out, int out_size)
{
    const float* src   = (const float*)d_in[0];
    const float* in_w  = (const float*)d_in[1];
    const float* in_b  = (const float*)d_in[2];
    const float* out_w = (const float*)d_in[3];
    const float* out_b = (const float*)d_in[4];
    const float* ln1g  = (const float*)d_in[5];
    const float* ln1b  = (const float*)d_in[6];
    const float* rw    = (const float*)d_in[7];
    const float* rb    = (const float*)d_in[8];
    const float* w1    = (const float*)d_in[9];
    const float* b1    = (const float*)d_in[10];
    const float* w2    = (const float*)d_in[11];
    const float* b2    = (const float*)d_in[12];
    const float* ln2g  = (const float*)d_in[13];
    const float* ln2b  = (const float*)d_in[14];
    float* out = (float*)d_out;

#define GETP(T, sym) ({ void* _p; cudaGetSymbolAddress(&_p, sym); (T*)_p; })
    float* qkv  = GETP(float, g_qkv);
    float* attn = GETP(float, g_attn);
    float* proj = GETP(float, g_proj);
    float* x1   = GETP(float, g_x1);
    float* Y    = GETP(float, g_Y);
    __nv_bfloat16* src_h  = GETP(__nv_bfloat16, g_src_h);
    __nv_bfloat16* src_l  = GETP(__nv_bfloat16, g_src_l);
    __nv_bfloat16* attn_h = GETP(__nv_bfloat16, g_attn_h);
    __nv_bfloat16* attn_l = GETP(__nv_bfloat16, g_attn_l);
    __nv_bfloat16* x1_h   = GETP(__nv_bfloat16, g_x1_h);
    __nv_bfloat16* x1_l   = GETP(__nv_bfloat16, g_x1_l);
    __nv_bfloat16* wqkv_h = GETP(__nv_bfloat16, g_wqkv_h);
    __nv_bfloat16* wqkv_l = GETP(__nv_bfloat16, g_wqkv_l);
    __nv_bfloat16* wo_h   = GETP(__nv_bfloat16, g_wo_h);
    __nv_bfloat16* wo_l   = GETP(__nv_bfloat16, g_wo_l);
    __nv_bfloat16* w1t_h  = GETP(__nv_bfloat16, g_w1t_h);
    __nv_bfloat16* w1t_l  = GETP(__nv_bfloat16, g_w1t_l);
    __nv_bfloat16* w2t_h  = GETP(__nv_bfloat16, g_w2t_h);
    __nv_bfloat16* w2t_l  = GETP(__nv_bfloat16, g_w2t_l);
    __nv_bfloat16* H_h    = GETP(__nv_bfloat16, g_H_h);
    __nv_bfloat16* H_l    = GETP(__nv_bfloat16, g_H_l);
    int* cnt  = GETP(int, d_count);
    int* offp = GETP(int, d_off);
    int* list = GETP(int, d_list);

    static bool attr_done = false;
    if (!attr_done) {
        cudaFuncSetAttribute(mma_gemm<0>, cudaFuncAttributeMaxDynamicSharedMemorySize, GEMM_SMEM);
        cudaFuncSetAttribute(mma_gemm<1>, cudaFuncAttributeMaxDynamicSharedMemorySize, GEMM_SMEM);
        cudaFuncSetAttribute(mma_gemm<2>, cudaFuncAttributeMaxDynamicSharedMemorySize, GEMM_SMEM);
        cudaFuncSetAttribute(attn_kernel, cudaFuncAttributeMaxDynamicSharedMemorySize, ATTN_SMEM);
        attr_done = true;
    }

    init_kernel<<<1, 32>>>();

    // conversions (src + weights)
    split_cvt_kernel<<<(TOK * DM / 4 + 255) / 256, 256>>>(src, src_h, src_l, TOK * DM / 4);
    split_cvt_kernel<<<(D3 * DM / 4 + 255) / 256, 256>>>(in_w, wqkv_h, wqkv_l, D3 * DM / 4);
    split_cvt_kernel<<<(DM * DM / 4 + 255) / 256, 256>>>(out_w, wo_h, wo_l, DM * DM / 4);
    transpose_split_kernel<<<dim3(DFF / 32, DM / 32, NEXP), dim3(32, 8)>>>(w1, w1t_h, w1t_l, DM, DFF);
    transpose_split_kernel<<<dim3(DM / 32, DFF / 32, NEXP), dim3(32, 8)>>>(w2, w2t_h, w2t_l, DFF, DM);

    // QKV = src @ in_w^T + b
    mma_gemm<0><<<dim3(D3 / BN, TOK / BM), 256, GEMM_SMEM>>>(
        src_h, src_l, wqkv_h, wqkv_l, in_b, qkv, nullptr, nullptr,
        nullptr, nullptr, nullptr, TOK, D3, DM);

    attn_kernel<<<dim3(NB * NHEAD, SEQ / 16), 128, ATTN_SMEM>>>(qkv, attn);
    split_cvt_kernel<<<(TOK * DM / 4 + 255) / 256, 256>>>(attn, attn_h, attn_l, TOK * DM / 4);

    // proj = attn @ out_w^T + b
    mma_gemm<0><<<dim3(DM / BN, TOK / BM), 256, GEMM_SMEM>>>(
        attn_h, attn_l, wo_h, wo_l, out_b, proj, nullptr, nullptr,
        nullptr, nullptr, nullptr, TOK, DM, DM);

    add_ln_kernel<<<TOK, 256>>>(src, proj, ln1g, ln1b, x1);
    split_cvt_kernel<<<(TOK * DM / 4 + 255) / 256, 256>>>(x1, x1_h, x1_l, TOK * DM / 4);

    router_kernel<<<TOK, 256>>>(x1, rw, rb);
    offsets_kernel<<<1, 32>>>();

    // H = relu(gather(x1) @ w1 + b1)  [split bf16 out]
    mma_gemm<1><<<dim3(DFF / BN, TOK / BM, NEXP), 256, GEMM_SMEM>>>(
        x1_h, x1_l, w1t_h, w1t_l, b1, nullptr, H_h, H_l,
        cnt, offp, list, 0, DFF, DM);
    // Y = H @ w2 + b2
    mma_gemm<2><<<dim3(DM / BN, TOK / BM, NEXP), 256, GEMM_SMEM>>>(
        H_h, H_l, w2t_h, w2t_l, b2, Y, nullptr, nullptr,
        cnt, offp, nullptr, 0, DM, DFF);

    combine_ln_kernel<<<TOK, 256>>>(Y, x1, ln2g, ln2b, out);
    lb_kernel<<<1, 1>>>(out, out_size);
}

// round 4
// speedup vs baseline: 2.0866x; 1.0965x over previous
#include <cuda_runtime.h>
#include <cuda_bf16.h>
#include <cstdint>
#include <math.h>

// Problem constants
#define TOK   4096          // B*S
#define DM    1024          // d_model
#define D3    3072          // 3*d_model
#define NHEAD 16
#define DH    64
#define DFF   4096
#define NEXP  8
#define SEQ   1024
#define NB    4
#define TOTROWS (2*TOK)     // packed expert rows (top-2)

// ============================ scratch globals ============================
__device__ __align__(16) float g_qkv[(size_t)TOK * D3];
__device__ __align__(16) float g_proj[(size_t)TOK * DM];
__device__ __align__(16) float g_x1[(size_t)TOK * DM];
__device__ __align__(16) float g_Y[(size_t)TOTROWS * DM];

__device__ __align__(16) __nv_bfloat16 g_src_h[(size_t)TOK * DM];
__device__ __align__(16) __nv_bfloat16 g_src_l[(size_t)TOK * DM];
__device__ __align__(16) __nv_bfloat16 g_attn_h[(size_t)TOK * DM];
__device__ __align__(16) __nv_bfloat16 g_attn_l[(size_t)TOK * DM];
__device__ __align__(16) __nv_bfloat16 g_x1_h[(size_t)TOK * DM];
__device__ __align__(16) __nv_bfloat16 g_x1_l[(size_t)TOK * DM];
__device__ __align__(16) __nv_bfloat16 g_wqkv_h[(size_t)D3 * DM];
__device__ __align__(16) __nv_bfloat16 g_wqkv_l[(size_t)D3 * DM];
__device__ __align__(16) __nv_bfloat16 g_wo_h[(size_t)DM * DM];
__device__ __align__(16) __nv_bfloat16 g_wo_l[(size_t)DM * DM];
__device__ __align__(16) __nv_bfloat16 g_w1t_h[(size_t)NEXP * DFF * DM];
__device__ __align__(16) __nv_bfloat16 g_w1t_l[(size_t)NEXP * DFF * DM];
__device__ __align__(16) __nv_bfloat16 g_w2t_h[(size_t)NEXP * DM * DFF];
__device__ __align__(16) __nv_bfloat16 g_w2t_l[(size_t)NEXP * DM * DFF];
__device__ __align__(16) __nv_bfloat16 g_H_h[(size_t)TOTROWS * DFF];
__device__ __align__(16) __nv_bfloat16 g_H_l[(size_t)TOTROWS * DFF];

__device__ int   d_count[NEXP];
__device__ int   d_off[NEXP];
__device__ float d_Psum[NEXP];
__device__ int   d_list[NEXP * TOK];
__device__ int   d_slot[TOK * 2];
__device__ float d_gate[TOK * 2];

// ============================ PTX helpers (sm_80-level only) =================
__device__ __forceinline__ uint32_t smem_u32(const void* p) {
    uint32_t a;
    asm("{ .reg .u64 t; cvta.to.shared.u64 t, %1; cvt.u32.u64 %0, t; }"
        : "=r"(a) : "l"(p));
    return a;
}
__device__ __forceinline__ void cp16(uint32_t dst, const void* src, int sz) {
    asm volatile("cp.async.cg.shared.global [%0], [%1], 16, %2;"
                 :: "r"(dst), "l"(src), "r"(sz) : "memory");
}
#define CP_COMMIT() asm volatile("cp.async.commit_group;" ::: "memory")
template<int N_>
__device__ __forceinline__ void cp_wait() {
    asm volatile("cp.async.wait_group %0;" :: "n"(N_) : "memory");
}
__device__ __forceinline__ void ldsm4(uint32_t* r, uint32_t addr) {
    asm volatile("ldmatrix.sync.aligned.m8n8.x4.shared.b16 {%0,%1,%2,%3}, [%4];"
                 : "=r"(r[0]), "=r"(r[1]), "=r"(r[2]), "=r"(r[3]) : "r"(addr));
}
__device__ __forceinline__ void mma16816(float* c, const uint32_t* a, const uint32_t* b) {
    asm volatile("mma.sync.aligned.m16n8k16.row.col.f32.bf16.bf16.f32 "
                 "{%0,%1,%2,%3}, {%4,%5,%6,%7}, {%8,%9}, {%0,%1,%2,%3};"
                 : "+f"(c[0]), "+f"(c[1]), "+f"(c[2]), "+f"(c[3])
                 : "r"(a[0]), "r"(a[1]), "r"(a[2]), "r"(a[3]),
                   "r"(b[0]), "r"(b[1]));
}

// ============================ warp-MMA GEMM ============================
// C[M,N] = (Ahi+Alo)[M,K] @ (Bhi+Blo)[N,K]^T + bias, split-bf16 3-term.
// MODE 0: dense, fp32 out.  MODE 1: expert gather A rows + relu + bf16-split out.
// MODE 2: expert offset A rows, fp32 out.
#define BM 128
#define BN 128
#define BK 32
#define RS 40                    // padded smem row stride (bf16 units)
#define AR_ELT (BM * RS)         // 5120 bf16 per array
#define OA_H 0                   // byte offsets inside a stage
#define OA_L 10240
#define OB_H 20480
#define OB_L 30720
#define STG_BYTES 40960
#define NSTG 3
#define GEMM_SMEM (NSTG * STG_BYTES)

template<int MODE>
__global__ __launch_bounds__(256) void mma_gemm(
    const __nv_bfloat16* __restrict__ AH, const __nv_bfloat16* __restrict__ AL,
    const __nv_bfloat16* __restrict__ BH, const __nv_bfloat16* __restrict__ BL,
    const float* __restrict__ biasBase,
    float* __restrict__ Cf, __nv_bfloat16* __restrict__ CH, __nv_bfloat16* __restrict__ CL,
    const int* __restrict__ counts, const int* __restrict__ offs,
    const int* __restrict__ listBase,
    int Mfix, int N, int K)
{
    extern __shared__ __nv_bfloat16 smbf[];
    const int tid = threadIdx.x;
    const int lane = tid & 31, wid = tid >> 5;
    const int wm = wid & 3, wn = wid >> 2;       // 4 x 2 warp grid
    const int g = lane >> 2, tig = lane & 3;
    const int m0 = blockIdx.y * BM, n0 = blockIdx.x * BN;
    const int e = blockIdx.z;

    int M = Mfix;
    const __nv_bfloat16 *bhp = BH, *blp = BL;
    const float* bias = biasBase;
    const int* lst = nullptr;
    int arow0 = 0, crow0 = 0;
    if (MODE == 1) {
        M = counts[e];
        bhp += (size_t)e * N * K; blp += (size_t)e * N * K;
        bias += (size_t)e * N;
        lst = listBase + e * TOK;
        crow0 = offs[e];
    } else if (MODE == 2) {
        M = counts[e];
        bhp += (size_t)e * N * K; blp += (size_t)e * N * K;
        bias += (size_t)e * N;
        arow0 = offs[e]; crow0 = offs[e];
    }
    if (m0 >= M) return;

    const uint32_t sb = smem_u32(smbf);

    float acc[2][8][4];
#pragma unroll
    for (int mt = 0; mt < 2; mt++)
#pragma unroll
        for (int nt = 0; nt < 8; nt++)
#pragma unroll
            for (int i = 0; i < 4; i++) acc[mt][nt][i] = 0.0f;

    auto load_stage = [&](int st, int k0) {
        uint32_t sbase = sb + st * STG_BYTES;
#pragma unroll
        for (int i = 0; i < 2; i++) {
            int ch = tid + i * 256;                  // 0..511
            int row = ch >> 2, seg = ch & 3;
            uint32_t doff = (uint32_t)(row * RS + seg * 8) * 2;
            int gr = m0 + row;
            size_t arow; int sz;
            if (MODE == 1) {
                bool ok = gr < M;
                arow = ok ? (size_t)lst[gr] : 0; sz = ok ? 16 : 0;
            } else if (MODE == 2) {
                bool ok = gr < M;
                arow = (size_t)(arow0 + (ok ? gr : 0)); sz = ok ? 16 : 0;
            } else { arow = (size_t)gr; sz = 16; }
            size_t aoff = arow * (size_t)K + k0 + seg * 8;
            cp16(sbase + OA_H + doff, AH + aoff, sz);
            cp16(sbase + OA_L + doff, AL + aoff, sz);
            size_t boff = (size_t)(n0 + row) * K + k0 + seg * 8;
            cp16(sbase + OB_H + doff, bhp + boff, 16);
            cp16(sbase + OB_L + doff, blp + boff, 16);
        }
    };

    // ldmatrix lane address components
    const int a_row_in = (lane & 15);
    const int a_col_in = (lane >> 4) << 3;               // 0 or 8
    const int b_row_in = (lane & 7) + ((lane & 16) ? 8 : 0);
    const int b_col_in = (lane & 8) ? 8 : 0;

    auto compute = [&](int st) {
        uint32_t sbase = sb + st * STG_BYTES;
#pragma unroll
        for (int ks = 0; ks < 2; ks++) {
            const int kf = ks * 16;
            uint32_t ah[2][4], al[2][4];
#pragma unroll
            for (int mt = 0; mt < 2; mt++) {
                int row = wm * 32 + mt * 16 + a_row_in;
                uint32_t off = (uint32_t)(row * RS + kf + a_col_in) * 2;
                ldsm4(ah[mt], sbase + OA_H + off);
                ldsm4(al[mt], sbase + OA_L + off);
            }
#pragma unroll
            for (int ntp = 0; ntp < 4; ntp++) {
                int row = wn * 64 + ntp * 16 + b_row_in;
                uint32_t off = (uint32_t)(row * RS + kf + b_col_in) * 2;
                uint32_t bh[4], bl[4];
                ldsm4(bh, sbase + OB_H + off);
                ldsm4(bl, sbase + OB_L + off);
#pragma unroll
                for (int half = 0; half < 2; half++) {
                    int nt = ntp * 2 + half;
#pragma unroll
                    for (int mt = 0; mt < 2; mt++) {
                        mma16816(acc[mt][nt], ah[mt], bh + half * 2);
                        mma16816(acc[mt][nt], ah[mt], bl + half * 2);
                        mma16816(acc[mt][nt], al[mt], bh + half * 2);
                    }
                }
            }
        }
    };

    const int nk = K / BK;   // >= 2 always (K is 1024 or 4096)
    load_stage(0, 0);
    CP_COMMIT();
    load_stage(1, BK);
    CP_COMMIT();
    for (int c = 0; c < nk; c++) {
        cp_wait<1>();
        __syncthreads();
        compute(c % NSTG);
        int cn = c + 2;
        if (cn < nk) load_stage(cn % NSTG, cn * BK);
        CP_COMMIT();
    }

    // ---- epilogue ----
#pragma unroll
    for (int nt = 0; nt < 8; nt++) {
        int col = n0 + wn * 64 + nt * 8 + 2 * tig;
        float b0 = bias[col], b1 = bias[col + 1];
#pragma unroll
        for (int mt = 0; mt < 2; mt++) {
            int r0 = m0 + wm * 32 + mt * 16 + g;
            float* c = acc[mt][nt];
#pragma unroll
            for (int hh = 0; hh < 2; hh++) {
                int r = r0 + hh * 8;
                if (r < M) {
                    float v0 = c[hh * 2 + 0] + b0;
                    float v1 = c[hh * 2 + 1] + b1;
                    if (MODE == 1) {
                        v0 = fmaxf(v0, 0.0f); v1 = fmaxf(v1, 0.0f);
                        __nv_bfloat16 h0 = __float2bfloat16(v0);
                        __nv_bfloat16 h1 = __float2bfloat16(v1);
                        size_t o = (size_t)(crow0 + r) * N + col;
                        *(__nv_bfloat162*)(CH + o) = __halves2bfloat162(h0, h1);
                        *(__nv_bfloat162*)(CL + o) = __halves2bfloat162(
                            __float2bfloat16(v0 - __bfloat162float(h0)),
                            __float2bfloat16(v1 - __bfloat162float(h1)));
                    } else if (MODE == 2) {
                        size_t o = (size_t)(crow0 + r) * N + col;
                        *(float2*)(Cf + o) = make_float2(v0, v1);
                    } else {
                        *(float2*)(Cf + (size_t)r * N + col) = make_float2(v0, v1);
                    }
                }
            }
        }
    }
}

// ============================ small kernels ============================
__global__ void init_kernel() {
    int i = threadIdx.x;
    if (i < NEXP) { d_count[i] = 0; d_Psum[i] = 0.0f; }
}

__global__ void offsets_kernel() {
    if (threadIdx.x == 0) {
        int a = 0;
#pragma unroll
        for (int e = 0; e < NEXP; e++) { d_off[e] = a; a += d_count[e]; }
    }
}

__global__ __launch_bounds__(256) void split_cvt_kernel(
    const float* __restrict__ x, __nv_bfloat16* __restrict__ h,
    __nv_bfloat16* __restrict__ l, int n4)
{
    int i = blockIdx.x * 256 + threadIdx.x;
    if (i >= n4) return;
    float4 v = ((const float4*)x)[i];
    float vs[4] = {v.x, v.y, v.z, v.w};
    __nv_bfloat16 hv[4], lv[4];
#pragma unroll
    for (int j = 0; j < 4; j++) {
        hv[j] = __float2bfloat16(vs[j]);
        lv[j] = __float2bfloat16(vs[j] - __bfloat162float(hv[j]));
    }
    *(uint2*)(h + i * 4) = *(uint2*)hv;
    *(uint2*)(l + i * 4) = *(uint2*)lv;
}

// per-expert transpose + split: W[e][K][N] -> T[e][N][K] (hi/lo)
__global__ __launch_bounds__(256) void transpose_split_kernel(
    const float* __restrict__ W, __nv_bfloat16* __restrict__ Th,
    __nv_bfloat16* __restrict__ Tl, int K, int N)
{
    __shared__ float t[32][33];
    int e = blockIdx.z;
    const float* w = W + (size_t)e * K * N;
    __nv_bfloat16* th = Th + (size_t)e * N * K;
    __nv_bfloat16* tl = Tl + (size_t)e * N * K;
    int n0 = blockIdx.x * 32, k0 = blockIdx.y * 32;
    int x = threadIdx.x, y = threadIdx.y;
#pragma unroll
    for (int i = 0; i < 32; i += 8)
        t[y + i][x] = w[(size_t)(k0 + y + i) * N + n0 + x];
    __syncthreads();
#pragma unroll
    for (int i = 0; i < 32; i += 8) {
        float v = t[x][y + i];
        __nv_bfloat16 hi = __float2bfloat16(v);
        th[(size_t)(n0 + y + i) * K + k0 + x] = hi;
        tl[(size_t)(n0 + y + i) * K + k0 + x] = __float2bfloat16(v - __bfloat162float(hi));
    }
}

// ============================ attention ============================
// 16 query rows per block; writes bf16 hi/lo split directly.
#define ATTN_SMEM ((64 * 65 + 16 * 1024 + 16 * 64) * 4)

__global__ __launch_bounds__(128) void attn_kernel(
    const float* __restrict__ qkv,
    __nv_bfloat16* __restrict__ oh, __nv_bfloat16* __restrict__ ol)
{
    extern __shared__ float sm[];
    float (*tile)[65] = (float(*)[65])sm;
    float (*sc)[1024] = (float(*)[1024])(sm + 64 * 65);
    float (*qs)[64]   = (float(*)[64])(sm + 64 * 65 + 16 * 1024);

    int bh = blockIdx.x;
    int b = bh >> 4, h = bh & 15;
    int tid = threadIdx.x, w = tid >> 5, lane = tid & 31;
    int q0 = blockIdx.y * 16;
    int hoff = h * DH;
    int rb = w * 4;

    for (int i = tid; i < 16 * 64; i += 128) {
        int r = i >> 6, d = i & 63;
        qs[r][d] = qkv[(size_t)(b * SEQ + q0 + r) * D3 + hoff + d] * 0.125f;
    }

    for (int kt = 0; kt < 16; kt++) {
        __syncthreads();
        for (int idx = tid; idx < 4096; idx += 128) {
            int key = idx >> 6, d = idx & 63;
            tile[d][key] = qkv[(size_t)(b * SEQ + kt * 64 + key) * D3 + DM + hoff + d];
        }
        __syncthreads();
        int k0 = lane, k1 = lane + 32;
        float s00 = 0.f, s01 = 0.f, s10 = 0.f, s11 = 0.f;
        float s20 = 0.f, s21 = 0.f, s30 = 0.f, s31 = 0.f;
#pragma unroll 8
        for (int d = 0; d < 64; d++) {
            float t0 = tile[d][k0], t1 = tile[d][k1];
            float q0v = qs[rb + 0][d], q1v = qs[rb + 1][d];
            float q2v = qs[rb + 2][d], q3v = qs[rb + 3][d];
            s00 += q0v * t0; s01 += q0v * t1;
            s10 += q1v * t0; s11 += q1v * t1;
            s20 += q2v * t0; s21 += q2v * t1;
            s30 += q3v * t0; s31 += q3v * t1;
        }
        sc[rb + 0][kt * 64 + k0] = s00; sc[rb + 0][kt * 64 + k1] = s01;
        sc[rb + 1][kt * 64 + k0] = s10; sc[rb + 1][kt * 64 + k1] = s11;
        sc[rb + 2][kt * 64 + k0] = s20; sc[rb + 2][kt * 64 + k1] = s21;
        sc[rb + 3][kt * 64 + k0] = s30; sc[rb + 3][kt * 64 + k1] = s31;
    }

    float inv[4];
#pragma unroll
    for (int rr = 0; rr < 4; rr++) {
        int r = rb + rr;
        float m = -1e30f;
        for (int i = lane; i < 1024; i += 32) m = fmaxf(m, sc[r][i]);
#pragma unroll
        for (int off = 16; off; off >>= 1) m = fmaxf(m, __shfl_xor_sync(0xffffffffu, m, off));
        float sum = 0.f;
        for (int i = lane; i < 1024; i += 32) {
            float p = __expf(sc[r][i] - m);
            sc[r][i] = p;
            sum += p;
        }
#pragma unroll
        for (int off = 16; off; off >>= 1) sum += __shfl_xor_sync(0xffffffffu, sum, off);
        inv[rr] = 1.0f / sum;
    }

    int d0 = lane, d1 = lane + 32;
    float a00 = 0.f, a01 = 0.f, a10 = 0.f, a11 = 0.f;
    float a20 = 0.f, a21 = 0.f, a30 = 0.f, a31 = 0.f;
    for (int vt = 0; vt < 16; vt++) {
        __syncthreads();
        for (int idx = tid; idx < 4096; idx += 128) {
            int key = idx >> 6, d = idx & 63;
            tile[key][d] = qkv[(size_t)(b * SEQ + vt * 64 + key) * D3 + 2 * DM + hoff + d];
        }
        __syncthreads();
#pragma unroll 8
        for (int key = 0; key < 64; key++) {
            float v0 = tile[key][d0], v1 = tile[key][d1];
            float p0 = sc[rb + 0][vt * 64 + key], p1 = sc[rb + 1][vt * 64 + key];
            float p2 = sc[rb + 2][vt * 64 + key], p3 = sc[rb + 3][vt * 64 + key];
            a00 += p0 * v0; a01 += p0 * v1;
            a10 += p1 * v0; a11 += p1 * v1;
            a20 += p2 * v0; a21 += p2 * v1;
            a30 += p3 * v0; a31 += p3 * v1;
        }
    }
    size_t base = (size_t)(b * SEQ + q0 + rb) * DM + hoff;
    float rv[4][2] = {{a00 * inv[0], a01 * inv[0]}, {a10 * inv[1], a11 * inv[1]},
                      {a20 * inv[2], a21 * inv[2]}, {a30 * inv[3], a31 * inv[3]}};
#pragma unroll
    for (int rr = 0; rr < 4; rr++) {
        __nv_bfloat16 h0 = __float2bfloat16(rv[rr][0]);
        __nv_bfloat16 h1 = __float2bfloat16(rv[rr][1]);
        oh[base + rr * DM + d0] = h0;
        oh[base + rr * DM + d1] = h1;
        ol[base + rr * DM + d0] = __float2bfloat16(rv[rr][0] - __bfloat162float(h0));
        ol[base + rr * DM + d1] = __float2bfloat16(rv[rr][1] - __bfloat162float(h1));
    }
}

// ============================ LN / router / combine / lb ============================
__device__ __forceinline__ float blk_sum(float v, float* red) {
    int tid = threadIdx.x;
    red[tid] = v;
    __syncthreads();
#pragma unroll
    for (int s = 128; s > 0; s >>= 1) {
        if (tid < s) red[tid] += red[tid + s];
        __syncthreads();
    }
    float r = red[0];
    __syncthreads();
    return r;
}

// x1 = LN(a + b); also writes bf16 hi/lo split of x1
__global__ __launch_bounds__(256) void add_ln_split_kernel(
    const float* __restrict__ a, const float* __restrict__ b,
    const float* __restrict__ g, const float* __restrict__ bb,
    float* __restrict__ out,
    __nv_bfloat16* __restrict__ oh, __nv_bfloat16* __restrict__ ol)
{
    __shared__ float red[256];
    size_t t = blockIdx.x;
    int tid = threadIdx.x;
    float v[4];
    float s = 0.f;
#pragma unroll
    for (int i = 0; i < 4; i++) {
        int d = tid + i * 256;
        v[i] = a[t * DM + d] + b[t * DM + d];
        s += v[i];
    }
    float mu = blk_sum(s, red) * (1.0f / DM);
    float sq = 0.f;
#pragma unroll
    for (int i = 0; i < 4; i++) { float c = v[i] - mu; sq += c * c; }
    float var = blk_sum(sq, red) * (1.0f / DM);
    float rstd = rsqrtf(var + 1e-5f);
#pragma unroll
    for (int i = 0; i < 4; i++) {
        int d = tid + i * 256;
        float y = (v[i] - mu) * rstd * g[d] + bb[d];
        out[t * DM + d] = y;
        __nv_bfloat16 hi = __float2bfloat16(y);
        oh[t * DM + d] = hi;
        ol[t * DM + d] = __float2bfloat16(y - __bfloat162float(hi));
    }
}

__global__ __launch_bounds__(256) void router_kernel(
    const float* __restrict__ x1, const float* __restrict__ rw,
    const float* __restrict__ rb)
{
    __shared__ float logits[NEXP];
    size_t t = blockIdx.x;
    int tid = threadIdx.x;
    int w = tid >> 5, lane = tid & 31;
    if (w < NEXP) {
        float s = 0.f;
        for (int k = lane; k < DM; k += 32)
            s += x1[t * DM + k] * rw[(size_t)w * DM + k];
#pragma unroll
        for (int off = 16; off; off >>= 1) s += __shfl_xor_sync(0xffffffffu, s, off);
        if (lane == 0) logits[w] = s + rb[w];
    }
    __syncthreads();
    if (tid == 0) {
        float p[NEXP];
        float mx = logits[0];
#pragma unroll
        for (int e = 1; e < NEXP; e++) mx = fmaxf(mx, logits[e]);
        float sum = 0.f;
#pragma unroll
        for (int e = 0; e < NEXP; e++) { p[e] = expf(logits[e] - mx); sum += p[e]; }
        float invs = 1.0f / sum;
#pragma unroll
        for (int e = 0; e < NEXP; e++) {
            p[e] *= invs;
            atomicAdd(&d_Psum[e], p[e]);
        }
        int i0 = 0;
#pragma unroll
        for (int e = 1; e < NEXP; e++) if (p[e] > p[i0]) i0 = e;
        int i1 = (i0 == 0) ? 1 : 0;
#pragma unroll
        for (int e = 0; e < NEXP; e++) if (e != i0 && p[e] > p[i1]) i1 = e;
        float gsum = p[i0] + p[i1];

        int pos0 = atomicAdd(&d_count[i0], 1);
        d_list[i0 * TOK + pos0] = (int)t;
        d_slot[t * 2 + 0] = i0 * TOK + pos0;
        d_gate[t * 2 + 0] = p[i0] / gsum;

        int pos1 = atomicAdd(&d_count[i1], 1);
        d_list[i1 * TOK + pos1] = (int)t;
        d_slot[t * 2 + 1] = i1 * TOK + pos1;
        d_gate[t * 2 + 1] = p[i1] / gsum;
    }
}

__global__ __launch_bounds__(256) void combine_ln_kernel(
    const float* __restrict__ Y, const float* __restrict__ x1,
    const float* __restrict__ g, const float* __restrict__ bb,
    float* __restrict__ out)
{
    __shared__ float red[256];
    size_t t = blockIdx.x;
    int tid = threadIdx.x;
    int sl0 = d_slot[t * 2 + 0], sl1 = d_slot[t * 2 + 1];
    size_t r0 = (size_t)d_off[sl0 / TOK] + (sl0 % TOK);
    size_t r1 = (size_t)d_off[sl1 / TOK] + (sl1 % TOK);
    float g0 = d_gate[t * 2 + 0], g1 = d_gate[t * 2 + 1];
    float v[4];
    float s = 0.f;
#pragma unroll
    for (int i = 0; i < 4; i++) {
        int d = tid + i * 256;
        float y = g0 * Y[r0 * DM + d] + g1 * Y[r1 * DM + d];
        v[i] = x1[t * DM + d] + y;
        s += v[i];
    }
    float mu = blk_sum(s, red) * (1.0f / DM);
    float sq = 0.f;
#pragma unroll
    for (int i = 0; i < 4; i++) { float c = v[i] - mu; sq += c * c; }
    float var = blk_sum(sq, red) * (1.0f / DM);
    float rstd = rsqrtf(var + 1e-5f);
#pragma unroll
    for (int i = 0; i < 4; i++) {
        int d = tid + i * 256;
        out[t * DM + d] = (v[i] - mu) * rstd * g[d] + bb[d];
    }
}

__global__ void lb_kernel(float* __restrict__ out, int out_size) {
    if (out_size > TOK * DM) {
        float lb = 0.f;
#pragma unroll
        for (int e = 0; e < NEXP; e++) {
            float f = (float)d_count[e] / (float)(TOK * 2);
            float P = d_Psum[e] / (float)TOK;
            lb += f * P;
        }
        out[out_size - 1] = (float)NEXP * lb;
    }
}

// ============================ launch ============================
extern "C" void kernel_launch(void* const* d_in, const int* in_sizes, int n_in,
                              void* d_out, int out_size)
{
    const float* src   = (const float*)d_in[0];
    const float* in_w  = (const float*)d_in[1];
    const float* in_b  = (const float*)d_in[2];
    const float* out_w = (const float*)d_in[3];
    const float* out_b = (const float*)d_in[4];
    const float* ln1g  = (const float*)d_in[5];
    const float* ln1b  = (const float*)d_in[6];
    const float* rw    = (const float*)d_in[7];
    const float* rb    = (const float*)d_in[8];
    const float* w1    = (const float*)d_in[9];
    const float* b1    = (const float*)d_in[10];
    const float* w2    = (const float*)d_in[11];
    const float* b2    = (const float*)d_in[12];
    const float* ln2g  = (const float*)d_in[13];
    const float* ln2b  = (const float*)d_in[14];
    float* out = (float*)d_out;

#define GETP(T, sym) ({ void* _p; cudaGetSymbolAddress(&_p, sym); (T*)_p; })
    float* qkv  = GETP(float, g_qkv);
    float* proj = GETP(float, g_proj);
    float* x1   = GETP(float, g_x1);
    float* Y    = GETP(float, g_Y);
    __nv_bfloat16* src_h  = GETP(__nv_bfloat16, g_src_h);
    __nv_bfloat16* src_l  = GETP(__nv_bfloat16, g_src_l);
    __nv_bfloat16* attn_h = GETP(__nv_bfloat16, g_attn_h);
    __nv_bfloat16* attn_l = GETP(__nv_bfloat16, g_attn_l);
    __nv_bfloat16* x1_h   = GETP(__nv_bfloat16, g_x1_h);
    __nv_bfloat16* x1_l   = GETP(__nv_bfloat16, g_x1_l);
    __nv_bfloat16* wqkv_h = GETP(__nv_bfloat16, g_wqkv_h);
    __nv_bfloat16* wqkv_l = GETP(__nv_bfloat16, g_wqkv_l);
    __nv_bfloat16* wo_h   = GETP(__nv_bfloat16, g_wo_h);
    __nv_bfloat16* wo_l   = GETP(__nv_bfloat16, g_wo_l);
    __nv_bfloat16* w1t_h  = GETP(__nv_bfloat16, g_w1t_h);
    __nv_bfloat16* w1t_l  = GETP(__nv_bfloat16, g_w1t_l);
    __nv_bfloat16* w2t_h  = GETP(__nv_bfloat16, g_w2t_h);
    __nv_bfloat16* w2t_l  = GETP(__nv_bfloat16, g_w2t_l);
    __nv_bfloat16* H_h    = GETP(__nv_bfloat16, g_H_h);
    __nv_bfloat16* H_l    = GETP(__nv_bfloat16, g_H_l);
    int* cnt  = GETP(int, d_count);
    int* offp = GETP(int, d_off);
    int* list = GETP(int, d_list);

    static bool attr_done = false;
    if (!attr_done) {
        cudaFuncSetAttribute(mma_gemm<0>, cudaFuncAttributeMaxDynamicSharedMemorySize, GEMM_SMEM);
        cudaFuncSetAttribute(mma_gemm<1>, cudaFuncAttributeMaxDynamicSharedMemorySize, GEMM_SMEM);
        cudaFuncSetAttribute(mma_gemm<2>, cudaFuncAttributeMaxDynamicSharedMemorySize, GEMM_SMEM);
        cudaFuncSetAttribute(attn_kernel, cudaFuncAttributeMaxDynamicSharedMemorySize, ATTN_SMEM);
        attr_done = true;
    }

    init_kernel<<<1, 32>>>();

    // conversions (src + weights)
    split_cvt_kernel<<<(TOK * DM / 4 + 255) / 256, 256>>>(src, src_h, src_l, TOK * DM / 4);
    split_cvt_kernel<<<(D3 * DM / 4 + 255) / 256, 256>>>(in_w, wqkv_h, wqkv_l, D3 * DM / 4);
    split_cvt_kernel<<<(DM * DM / 4 + 255) / 256, 256>>>(out_w, wo_h, wo_l, DM * DM / 4);
    transpose_split_kernel<<<dim3(DFF / 32, DM / 32, NEXP), dim3(32, 8)>>>(w1, w1t_h, w1t_l, DM, DFF);
    transpose_split_kernel<<<dim3(DM / 32, DFF / 32, NEXP), dim3(32, 8)>>>(w2, w2t_h, w2t_l, DFF, DM);

    // QKV = src @ in_w^T + b
    mma_gemm<0><<<dim3(D3 / BN, TOK / BM), 256, GEMM_SMEM>>>(
        src_h, src_l, wqkv_h, wqkv_l, in_b, qkv, nullptr, nullptr,
        nullptr, nullptr, nullptr, TOK, D3, DM);

    // attention (writes bf16 split directly)
    attn_kernel<<<dim3(NB * NHEAD, SEQ / 16), 128, ATTN_SMEM>>>(qkv, attn_h, attn_l);

    // proj = attn @ out_w^T + b
    mma_gemm<0><<<dim3(DM / BN, TOK / BM), 256, GEMM_SMEM>>>(
        attn_h, attn_l, wo_h, wo_l, out_b, proj, nullptr, nullptr,
        nullptr, nullptr, nullptr, TOK, DM, DM);

    // x1 = LN(src + proj), with fused split
    add_ln_split_kernel<<<TOK, 256>>>(src, proj, ln1g, ln1b, x1, x1_h, x1_l);

    router_kernel<<<TOK, 256>>>(x1, rw, rb);
    offsets_kernel<<<1, 32>>>();

    // H = relu(gather(x1) @ w1 + b1)  [split bf16 out]
    mma_gemm<1><<<dim3(DFF / BN, TOK / BM, NEXP), 256, GEMM_SMEM>>>(
        x1_h, x1_l, w1t_h, w1t_l, b1, nullptr, H_h, H_l,
        cnt, offp, list, 0, DFF, DM);
    // Y = H @ w2 + b2
    mma_gemm<2><<<dim3(DM / BN, TOK / BM, NEXP), 256, GEMM_SMEM>>>(
        H_h, H_l, w2t_h, w2t_l, b2, Y, nullptr, nullptr,
        cnt, offp, nullptr, 0, DM, DFF);

    combine_ln_kernel<<<TOK, 256>>>(Y, x1, ln2g, ln2b, out);
    lb_kernel<<<1, 1>>>(out, out_size);
}

// round 5
// speedup vs baseline: 2.6703x; 1.2797x over previous
#include <cuda_runtime.h>
#include <cuda_bf16.h>
#include <cstdint>
#include <math.h>

// Problem constants
#define TOK   4096          // B*S
#define DM    1024          // d_model
#define D3    3072          // 3*d_model
#define NHEAD 16
#define DH    64
#define DFF   4096
#define NEXP  8
#define SEQ   1024
#define NB    4
#define TOTROWS (2*TOK)     // packed expert rows (top-2)

// ============================ scratch globals ============================
__device__ __align__(16) float g_qkv[(size_t)TOK * D3];
__device__ __align__(16) float g_proj[(size_t)TOK * DM];
__device__ __align__(16) float g_x1[(size_t)TOK * DM];
__device__ __align__(16) float g_Y[(size_t)TOTROWS * DM];

__device__ __align__(16) __nv_bfloat16 g_src_h[(size_t)TOK * DM];
__device__ __align__(16) __nv_bfloat16 g_src_l[(size_t)TOK * DM];
__device__ __align__(16) __nv_bfloat16 g_attn_h[(size_t)TOK * DM];
__device__ __align__(16) __nv_bfloat16 g_attn_l[(size_t)TOK * DM];
__device__ __align__(16) __nv_bfloat16 g_x1_h[(size_t)TOK * DM];
__device__ __align__(16) __nv_bfloat16 g_x1_l[(size_t)TOK * DM];
__device__ __align__(16) __nv_bfloat16 g_wqkv_h[(size_t)D3 * DM];
__device__ __align__(16) __nv_bfloat16 g_wqkv_l[(size_t)D3 * DM];
__device__ __align__(16) __nv_bfloat16 g_wo_h[(size_t)DM * DM];
__device__ __align__(16) __nv_bfloat16 g_wo_l[(size_t)DM * DM];
__device__ __align__(16) __nv_bfloat16 g_w1t_h[(size_t)NEXP * DFF * DM];
__device__ __align__(16) __nv_bfloat16 g_w1t_l[(size_t)NEXP * DFF * DM];
__device__ __align__(16) __nv_bfloat16 g_w2t_h[(size_t)NEXP * DM * DFF];
__device__ __align__(16) __nv_bfloat16 g_w2t_l[(size_t)NEXP * DM * DFF];
__device__ __align__(16) __nv_bfloat16 g_H_h[(size_t)TOTROWS * DFF];
__device__ __align__(16) __nv_bfloat16 g_H_l[(size_t)TOTROWS * DFF];

__device__ int   d_count[NEXP];
__device__ int   d_off[NEXP];
__device__ float d_Psum[NEXP];
__device__ int   d_list[NEXP * TOK];
__device__ int   d_slot[TOK * 2];
__device__ float d_gate[TOK * 2];

// ============================ PTX helpers (sm_80-level only) =================
__device__ __forceinline__ uint32_t smem_u32(const void* p) {
    uint32_t a;
    asm("{ .reg .u64 t; cvta.to.shared.u64 t, %1; cvt.u32.u64 %0, t; }"
        : "=r"(a) : "l"(p));
    return a;
}
__device__ __forceinline__ void cp16(uint32_t dst, const void* src, int sz) {
    asm volatile("cp.async.cg.shared.global [%0], [%1], 16, %2;"
                 :: "r"(dst), "l"(src), "r"(sz) : "memory");
}
#define CP_COMMIT() asm volatile("cp.async.commit_group;" ::: "memory")
template<int N_>
__device__ __forceinline__ void cp_wait() {
    asm volatile("cp.async.wait_group %0;" :: "n"(N_) : "memory");
}
__device__ __forceinline__ void ldsm4(uint32_t* r, uint32_t addr) {
    asm volatile("ldmatrix.sync.aligned.m8n8.x4.shared.b16 {%0,%1,%2,%3}, [%4];"
                 : "=r"(r[0]), "=r"(r[1]), "=r"(r[2]), "=r"(r[3]) : "r"(addr));
}
__device__ __forceinline__ void mma16816(float* c, const uint32_t* a, const uint32_t* b) {
    asm volatile("mma.sync.aligned.m16n8k16.row.col.f32.bf16.bf16.f32 "
                 "{%0,%1,%2,%3}, {%4,%5,%6,%7}, {%8,%9}, {%0,%1,%2,%3};"
                 : "+f"(c[0]), "+f"(c[1]), "+f"(c[2]), "+f"(c[3])
                 : "r"(a[0]), "r"(a[1]), "r"(a[2]), "r"(a[3]),
                   "r"(b[0]), "r"(b[1]));
}

// ============================ warp-MMA GEMM ============================
// C[M,N] = (Ahi+Alo)[M,K] @ (Bhi+Blo)[N,K]^T + bias, split-bf16 3-term.
// smem layout per stage: A tile 128 rows x 128B ([hi 32bf16 | lo 32bf16], XOR
// swizzled segs), then B tile same. 2 stages, 2 CTAs/SM.
#define BM 128
#define BN 128
#define BK 32
#define A_BYTES 16384
#define STG_BYTES 32768
#define NSTG 2
#define GEMM_SMEM (NSTG * STG_BYTES)

template<int MODE>
__global__ __launch_bounds__(256, 2) void mma_gemm(
    const __nv_bfloat16* __restrict__ AH, const __nv_bfloat16* __restrict__ AL,
    const __nv_bfloat16* __restrict__ BH, const __nv_bfloat16* __restrict__ BL,
    const float* __restrict__ biasBase,
    float* __restrict__ Cf, __nv_bfloat16* __restrict__ CH, __nv_bfloat16* __restrict__ CL,
    const int* __restrict__ counts, const int* __restrict__ offs,
    const int* __restrict__ listBase,
    int Mfix, int N, int K)
{
    extern __shared__ __nv_bfloat16 smbf[];
    const int tid = threadIdx.x;
    const int lane = tid & 31, wid = tid >> 5;
    const int wm = wid & 3, wn = wid >> 2;       // 4 x 2 warp grid
    const int g = lane >> 2, tig = lane & 3;
    const int m0 = blockIdx.y * BM, n0 = blockIdx.x * BN;
    const int e = blockIdx.z;

    int M = Mfix;
    const __nv_bfloat16 *bhp = BH, *blp = BL;
    const float* bias = biasBase;
    const int* lst = nullptr;
    int arow0 = 0, crow0 = 0;
    if (MODE == 1) {
        M = counts[e];
        bhp += (size_t)e * N * K; blp += (size_t)e * N * K;
        bias += (size_t)e * N;
        lst = listBase + e * TOK;
        crow0 = offs[e];
    } else if (MODE == 2) {
        M = counts[e];
        bhp += (size_t)e * N * K; blp += (size_t)e * N * K;
        bias += (size_t)e * N;
        arow0 = offs[e]; crow0 = offs[e];
    }
    if (m0 >= M) return;

    const uint32_t sb = smem_u32(smbf);

    float acc[2][8][4];
#pragma unroll
    for (int mt = 0; mt < 2; mt++)
#pragma unroll
        for (int nt = 0; nt < 8; nt++)
#pragma unroll
            for (int i = 0; i < 4; i++) acc[mt][nt][i] = 0.0f;

    auto load_stage = [&](int st, int k0) {
        uint32_t sbase = sb + st * STG_BYTES;
#pragma unroll
        for (int i = 0; i < 4; i++) {
            int u = tid + i * 256;           // 0..1023 (uniform A/B per i)
            int isB = u >> 9;
            int idx = u & 511;
            int row = idx >> 2, seg = idx & 3;
            int phh = seg ^ (row & 7);
            int phl = (seg + 4) ^ (row & 7);
            uint32_t dbase = sbase + isB * A_BYTES + row * 128;
            if (!isB) {
                int gr = m0 + row;
                size_t arow; int sz;
                if (MODE == 1) {
                    bool ok = gr < M;
                    arow = ok ? (size_t)lst[gr] : 0; sz = ok ? 16 : 0;
                } else if (MODE == 2) {
                    bool ok = gr < M;
                    arow = (size_t)(arow0 + (ok ? gr : 0)); sz = ok ? 16 : 0;
                } else { arow = (size_t)gr; sz = 16; }
                size_t aoff = arow * (size_t)K + k0 + seg * 8;
                cp16(dbase + phh * 16, AH + aoff, sz);
                cp16(dbase + phl * 16, AL + aoff, sz);
            } else {
                size_t boff = (size_t)(n0 + row) * K + k0 + seg * 8;
                cp16(dbase + phh * 16, bhp + boff, 16);
                cp16(dbase + phl * 16, blp + boff, 16);
            }
        }
    };

    // ldmatrix lane address components
    const int a_row_in = (lane & 15);
    const int a_seg_in = (lane >> 4);                    // 0 or 1 (x8 bf16)
    const int b_row_in = (lane & 7) + ((lane & 16) ? 8 : 0);
    const int b_seg_in = (lane & 8) ? 1 : 0;

    auto compute = [&](int st) {
        uint32_t sA = sb + st * STG_BYTES;
        uint32_t sB = sA + A_BYTES;
#pragma unroll
        for (int ks = 0; ks < 2; ks++) {
            const int kseg = ks * 2;                     // logical seg base
            uint32_t ah[2][4], al[2][4];
#pragma unroll
            for (int mt = 0; mt < 2; mt++) {
                int row = wm * 32 + mt * 16 + a_row_in;
                int sl = kseg + a_seg_in;
                uint32_t base = sA + row * 128;
                ldsm4(ah[mt], base + ((sl ^ (row & 7)) << 4));
                ldsm4(al[mt], base + (((sl + 4) ^ (row & 7)) << 4));
            }
#pragma unroll
            for (int ntp = 0; ntp < 4; ntp++) {
                int row = wn * 64 + ntp * 16 + b_row_in;
                int sl = kseg + b_seg_in;
                uint32_t base = sB + row * 128;
                uint32_t bh[4], bl[4];
                ldsm4(bh, base + ((sl ^ (row & 7)) << 4));
                ldsm4(bl, base + (((sl + 4) ^ (row & 7)) << 4));
#pragma unroll
                for (int half = 0; half < 2; half++) {
                    int nt = ntp * 2 + half;
#pragma unroll
                    for (int mt = 0; mt < 2; mt++) {
                        mma16816(acc[mt][nt], ah[mt], bh + half * 2);
                        mma16816(acc[mt][nt], ah[mt], bl + half * 2);
                        mma16816(acc[mt][nt], al[mt], bh + half * 2);
                    }
                }
            }
        }
    };

    const int nk = K / BK;
    load_stage(0, 0);
    CP_COMMIT();
    for (int c = 0; c < nk; c++) {
        if (c + 1 < nk) load_stage((c + 1) & 1, (c + 1) * BK);
        CP_COMMIT();
        cp_wait<1>();
        __syncthreads();
        compute(c & 1);
        __syncthreads();
    }

    // ---- epilogue ----
#pragma unroll
    for (int nt = 0; nt < 8; nt++) {
        int col = n0 + wn * 64 + nt * 8 + 2 * tig;
        float b0 = bias[col], b1 = bias[col + 1];
#pragma unroll
        for (int mt = 0; mt < 2; mt++) {
            int r0 = m0 + wm * 32 + mt * 16 + g;
            float* c = acc[mt][nt];
#pragma unroll
            for (int hh = 0; hh < 2; hh++) {
                int r = r0 + hh * 8;
                if (r < M) {
                    float v0 = c[hh * 2 + 0] + b0;
                    float v1 = c[hh * 2 + 1] + b1;
                    if (MODE == 1) {
                        v0 = fmaxf(v0, 0.0f); v1 = fmaxf(v1, 0.0f);
                        __nv_bfloat16 h0 = __float2bfloat16(v0);
                        __nv_bfloat16 h1 = __float2bfloat16(v1);
                        size_t o = (size_t)(crow0 + r) * N + col;
                        *(__nv_bfloat162*)(CH + o) = __halves2bfloat162(h0, h1);
                        *(__nv_bfloat162*)(CL + o) = __halves2bfloat162(
                            __float2bfloat16(v0 - __bfloat162float(h0)),
                            __float2bfloat16(v1 - __bfloat162float(h1)));
                    } else if (MODE == 2) {
                        size_t o = (size_t)(crow0 + r) * N + col;
                        *(float2*)(Cf + o) = make_float2(v0, v1);
                    } else {
                        *(float2*)(Cf + (size_t)r * N + col) = make_float2(v0, v1);
                    }
                }
            }
        }
    }
}

// ============================ small kernels ============================
__global__ void init_kernel() {
    int i = threadIdx.x;
    if (i < NEXP) { d_count[i] = 0; d_Psum[i] = 0.0f; }
}

__global__ void offsets_kernel() {
    if (threadIdx.x == 0) {
        int a = 0;
#pragma unroll
        for (int e = 0; e < NEXP; e++) { d_off[e] = a; a += d_count[e]; }
    }
}

__global__ __launch_bounds__(256) void split_cvt_kernel(
    const float* __restrict__ x, __nv_bfloat16* __restrict__ h,
    __nv_bfloat16* __restrict__ l, int n4)
{
    int i = blockIdx.x * 256 + threadIdx.x;
    if (i >= n4) return;
    float4 v = ((const float4*)x)[i];
    float vs[4] = {v.x, v.y, v.z, v.w};
    __nv_bfloat16 hv[4], lv[4];
#pragma unroll
    for (int j = 0; j < 4; j++) {
        hv[j] = __float2bfloat16(vs[j]);
        lv[j] = __float2bfloat16(vs[j] - __bfloat162float(hv[j]));
    }
    *(uint2*)(h + i * 4) = *(uint2*)hv;
    *(uint2*)(l + i * 4) = *(uint2*)lv;
}

// per-expert transpose + split: W[e][K][N] -> T[e][N][K] (hi/lo)
__global__ __launch_bounds__(256) void transpose_split_kernel(
    const float* __restrict__ W, __nv_bfloat16* __restrict__ Th,
    __nv_bfloat16* __restrict__ Tl, int K, int N)
{
    __shared__ float t[32][33];
    int e = blockIdx.z;
    const float* w = W + (size_t)e * K * N;
    __nv_bfloat16* th = Th + (size_t)e * N * K;
    __nv_bfloat16* tl = Tl + (size_t)e * N * K;
    int n0 = blockIdx.x * 32, k0 = blockIdx.y * 32;
    int x = threadIdx.x, y = threadIdx.y;
#pragma unroll
    for (int i = 0; i < 32; i += 8)
        t[y + i][x] = w[(size_t)(k0 + y + i) * N + n0 + x];
    __syncthreads();
#pragma unroll
    for (int i = 0; i < 32; i += 8) {
        float v = t[x][y + i];
        __nv_bfloat16 hi = __float2bfloat16(v);
        th[(size_t)(n0 + y + i) * K + k0 + x] = hi;
        tl[(size_t)(n0 + y + i) * K + k0 + x] = __float2bfloat16(v - __bfloat162float(hi));
    }
}

// ============================ attention ============================
// 16 query rows per block (4 warps x 4 rows), vectorized loads.
#define ATS_K 66
#define ATS_V 68
#define TILE_FLOATS (64 * ATS_V)
#define ATTN_SMEM ((TILE_FLOATS + 16 * 1024 + 16 * 64) * 4)

__global__ __launch_bounds__(128) void attn_kernel(
    const float* __restrict__ qkv,
    __nv_bfloat16* __restrict__ oh, __nv_bfloat16* __restrict__ ol)
{
    extern __shared__ float sm[];
    float* tile = sm;                                   // K:[d][key]s66  V:[key][d]s68
    float (*sc)[1024] = (float(*)[1024])(sm + TILE_FLOATS);
    float (*qs)[64]   = (float(*)[64])(sm + TILE_FLOATS + 16 * 1024);

    int bh = blockIdx.x;
    int b = bh >> 4, h = bh & 15;
    int tid = threadIdx.x, w = tid >> 5, lane = tid & 31;
    int q0 = blockIdx.y * 16;
    int hoff = h * DH;
    int rb = w * 4;

    // q preload (scaled)
    for (int i4 = tid; i4 < 256; i4 += 128) {
        int r = i4 >> 4, ds = i4 & 15;
        float4 v = *(const float4*)(qkv + (size_t)(b * SEQ + q0 + r) * D3 + hoff + ds * 4);
        float4* dst = (float4*)&qs[r][ds * 4];
        *dst = make_float4(v.x * 0.125f, v.y * 0.125f, v.z * 0.125f, v.w * 0.125f);
    }

    // ---- scores ----
    int k0 = 2 * lane;
    for (int kt = 0; kt < 16; kt++) {
        __syncthreads();
        for (int i4 = tid; i4 < 1024; i4 += 128) {
            int key = i4 >> 4, ds = i4 & 15;
            float4 v = *(const float4*)(qkv + (size_t)(b * SEQ + kt * 64 + key) * D3 + DM + hoff + ds * 4);
            tile[(ds * 4 + 0) * ATS_K + key] = v.x;
            tile[(ds * 4 + 1) * ATS_K + key] = v.y;
            tile[(ds * 4 + 2) * ATS_K + key] = v.z;
            tile[(ds * 4 + 3) * ATS_K + key] = v.w;
        }
        __syncthreads();
        float s[4][2] = {{0.f,0.f},{0.f,0.f},{0.f,0.f},{0.f,0.f}};
#pragma unroll 4
        for (int d4 = 0; d4 < 16; d4++) {
            float4 q0v = *(const float4*)&qs[rb + 0][d4 * 4];
            float4 q1v = *(const float4*)&qs[rb + 1][d4 * 4];
            float4 q2v = *(const float4*)&qs[rb + 2][d4 * 4];
            float4 q3v = *(const float4*)&qs[rb + 3][d4 * 4];
            const float* qa[4] = {(float*)&q0v, (float*)&q1v, (float*)&q2v, (float*)&q3v};
#pragma unroll
            for (int dd = 0; dd < 4; dd++) {
                float2 t = *(const float2*)&tile[(d4 * 4 + dd) * ATS_K + k0];
#pragma unroll
                for (int r = 0; r < 4; r++) {
                    s[r][0] += qa[r][dd] * t.x;
                    s[r][1] += qa[r][dd] * t.y;
                }
            }
        }
#pragma unroll
        for (int r = 0; r < 4; r++) {
            sc[rb + r][kt * 64 + k0]     = s[r][0];
            sc[rb + r][kt * 64 + k0 + 1] = s[r][1];
        }
    }

    // ---- softmax (warp-private rows) ----
    float inv[4];
#pragma unroll
    for (int rr = 0; rr < 4; rr++) {
        int r = rb + rr;
        float m = -1e30f;
        for (int i = lane; i < 1024; i += 32) m = fmaxf(m, sc[r][i]);
#pragma unroll
        for (int off = 16; off; off >>= 1) m = fmaxf(m, __shfl_xor_sync(0xffffffffu, m, off));
        float sum = 0.f;
        for (int i = lane; i < 1024; i += 32) {
            float p = __expf(sc[r][i] - m);
            sc[r][i] = p;
            sum += p;
        }
#pragma unroll
        for (int off = 16; off; off >>= 1) sum += __shfl_xor_sync(0xffffffffu, sum, off);
        inv[rr] = 1.0f / sum;
    }

    // ---- V pass ----
    int d0 = lane, d1 = lane + 32;
    float a[4][2] = {{0.f,0.f},{0.f,0.f},{0.f,0.f},{0.f,0.f}};
    for (int vt = 0; vt < 16; vt++) {
        __syncthreads();
        for (int i4 = tid; i4 < 1024; i4 += 128) {
            int key = i4 >> 4, ds = i4 & 15;
            float4 v = *(const float4*)(qkv + (size_t)(b * SEQ + vt * 64 + key) * D3 + 2 * DM + hoff + ds * 4);
            *(float4*)&tile[key * ATS_V + ds * 4] = v;
        }
        __syncthreads();
#pragma unroll 4
        for (int k4 = 0; k4 < 16; k4++) {
            float4 p0v = *(const float4*)&sc[rb + 0][vt * 64 + k4 * 4];
            float4 p1v = *(const float4*)&sc[rb + 1][vt * 64 + k4 * 4];
            float4 p2v = *(const float4*)&sc[rb + 2][vt * 64 + k4 * 4];
            float4 p3v = *(const float4*)&sc[rb + 3][vt * 64 + k4 * 4];
            const float* pa[4] = {(float*)&p0v, (float*)&p1v, (float*)&p2v, (float*)&p3v};
#pragma unroll
            for (int kk = 0; kk < 4; kk++) {
                int key = k4 * 4 + kk;
                float v0 = tile[key * ATS_V + d0];
                float v1 = tile[key * ATS_V + d1];
#pragma unroll
                for (int r = 0; r < 4; r++) {
                    a[r][0] += pa[r][kk] * v0;
                    a[r][1] += pa[r][kk] * v1;
                }
            }
        }
    }
    size_t base = (size_t)(b * SEQ + q0 + rb) * DM + hoff;
#pragma unroll
    for (int rr = 0; rr < 4; rr++) {
        float r0 = a[rr][0] * inv[rr], r1 = a[rr][1] * inv[rr];
        __nv_bfloat16 h0 = __float2bfloat16(r0);
        __nv_bfloat16 h1 = __float2bfloat16(r1);
        oh[base + rr * DM + d0] = h0;
        oh[base + rr * DM + d1] = h1;
        ol[base + rr * DM + d0] = __float2bfloat16(r0 - __bfloat162float(h0));
        ol[base + rr * DM + d1] = __float2bfloat16(r1 - __bfloat162float(h1));
    }
}

// ============================ LN / router / combine / lb ============================
__device__ __forceinline__ float blk_sum(float v, float* red) {
    int tid = threadIdx.x;
    red[tid] = v;
    __syncthreads();
#pragma unroll
    for (int s = 128; s > 0; s >>= 1) {
        if (tid < s) red[tid] += red[tid + s];
        __syncthreads();
    }
    float r = red[0];
    __syncthreads();
    return r;
}

// x1 = LN(a + b); also writes bf16 hi/lo split of x1
__global__ __launch_bounds__(256) void add_ln_split_kernel(
    const float* __restrict__ a, const float* __restrict__ b,
    const float* __restrict__ g, const float* __restrict__ bb,
    float* __restrict__ out,
    __nv_bfloat16* __restrict__ oh, __nv_bfloat16* __restrict__ ol)
{
    __shared__ float red[256];
    size_t t = blockIdx.x;
    int tid = threadIdx.x;
    float v[4];
    float s = 0.f;
#pragma unroll
    for (int i = 0; i < 4; i++) {
        int d = tid + i * 256;
        v[i] = a[t * DM + d] + b[t * DM + d];
        s += v[i];
    }
    float mu = blk_sum(s, red) * (1.0f / DM);
    float sq = 0.f;
#pragma unroll
    for (int i = 0; i < 4; i++) { float c = v[i] - mu; sq += c * c; }
    float var = blk_sum(sq, red) * (1.0f / DM);
    float rstd = rsqrtf(var + 1e-5f);
#pragma unroll
    for (int i = 0; i < 4; i++) {
        int d = tid + i * 256;
        float y = (v[i] - mu) * rstd * g[d] + bb[d];
        out[t * DM + d] = y;
        __nv_bfloat16 hi = __float2bfloat16(y);
        oh[t * DM + d] = hi;
        ol[t * DM + d] = __float2bfloat16(y - __bfloat162float(hi));
    }
}

__global__ __launch_bounds__(256) void router_kernel(
    const float* __restrict__ x1, const float* __restrict__ rw,
    const float* __restrict__ rb)
{
    __shared__ float logits[NEXP];
    size_t t = blockIdx.x;
    int tid = threadIdx.x;
    int w = tid >> 5, lane = tid & 31;
    if (w < NEXP) {
        float s = 0.f;
        for (int k = lane; k < DM; k += 32)
            s += x1[t * DM + k] * rw[(size_t)w * DM + k];
#pragma unroll
        for (int off = 16; off; off >>= 1) s += __shfl_xor_sync(0xffffffffu, s, off);
        if (lane == 0) logits[w] = s + rb[w];
    }
    __syncthreads();
    if (tid == 0) {
        float p[NEXP];
        float mx = logits[0];
#pragma unroll
        for (int e = 1; e < NEXP; e++) mx = fmaxf(mx, logits[e]);
        float sum = 0.f;
#pragma unroll
        for (int e = 0; e < NEXP; e++) { p[e] = expf(logits[e] - mx); sum += p[e]; }
        float invs = 1.0f / sum;
#pragma unroll
        for (int e = 0; e < NEXP; e++) {
            p[e] *= invs;
            atomicAdd(&d_Psum[e], p[e]);
        }
        int i0 = 0;
#pragma unroll
        for (int e = 1; e < NEXP; e++) if (p[e] > p[i0]) i0 = e;
        int i1 = (i0 == 0) ? 1 : 0;
#pragma unroll
        for (int e = 0; e < NEXP; e++) if (e != i0 && p[e] > p[i1]) i1 = e;
        float gsum = p[i0] + p[i1];

        int pos0 = atomicAdd(&d_count[i0], 1);
        d_list[i0 * TOK + pos0] = (int)t;
        d_slot[t * 2 + 0] = i0 * TOK + pos0;
        d_gate[t * 2 + 0] = p[i0] / gsum;

        int pos1 = atomicAdd(&d_count[i1], 1);
        d_list[i1 * TOK + pos1] = (int)t;
        d_slot[t * 2 + 1] = i1 * TOK + pos1;
        d_gate[t * 2 + 1] = p[i1] / gsum;
    }
}

__global__ __launch_bounds__(256) void combine_ln_kernel(
    const float* __restrict__ Y, const float* __restrict__ x1,
    const float* __restrict__ g, const float* __restrict__ bb,
    float* __restrict__ out)
{
    __shared__ float red[256];
    size_t t = blockIdx.x;
    int tid = threadIdx.x;
    int sl0 = d_slot[t * 2 + 0], sl1 = d_slot[t * 2 + 1];
    size_t r0 = (size_t)d_off[sl0 / TOK] + (sl0 % TOK);
    size_t r1 = (size_t)d_off[sl1 / TOK] + (sl1 % TOK);
    float g0 = d_gate[t * 2 + 0], g1 = d_gate[t * 2 + 1];
    float v[4];
    float s = 0.f;
#pragma unroll
    for (int i = 0; i < 4; i++) {
        int d = tid + i * 256;
        float y = g0 * Y[r0 * DM + d] + g1 * Y[r1 * DM + d];
        v[i] = x1[t * DM + d] + y;
        s += v[i];
    }
    float mu = blk_sum(s, red) * (1.0f / DM);
    float sq = 0.f;
#pragma unroll
    for (int i = 0; i < 4; i++) { float c = v[i] - mu; sq += c * c; }
    float var = blk_sum(sq, red) * (1.0f / DM);
    float rstd = rsqrtf(var + 1e-5f);
#pragma unroll
    for (int i = 0; i < 4; i++) {
        int d = tid + i * 256;
        out[t * DM + d] = (v[i] - mu) * rstd * g[d] + bb[d];
    }
}

__global__ void lb_kernel(float* __restrict__ out, int out_size) {
    if (out_size > TOK * DM) {
        float lb = 0.f;
#pragma unroll
        for (int e = 0; e < NEXP; e++) {
            float f = (float)d_count[e] / (float)(TOK * 2);
            float P = d_Psum[e] / (float)TOK;
            lb += f * P;
        }
        out[out_size - 1] = (float)NEXP * lb;
    }
}

// ============================ launch ============================
extern "C" void kernel_launch(void* const* d_in, const int* in_sizes, int n_in,
                              void* d_out, int out_size)
{
    const float* src   = (const float*)d_in[0];
    const float* in_w  = (const float*)d_in[1];
    const float* in_b  = (const float*)d_in[2];
    const float* out_w = (const float*)d_in[3];
    const float* out_b = (const float*)d_in[4];
    const float* ln1g  = (const float*)d_in[5];
    const float* ln1b  = (const float*)d_in[6];
    const float* rw    = (const float*)d_in[7];
    const float* rb    = (const float*)d_in[8];
    const float* w1    = (const float*)d_in[9];
    const float* b1    = (const float*)d_in[10];
    const float* w2    = (const float*)d_in[11];
    const float* b2    = (const float*)d_in[12];
    const float* ln2g  = (const float*)d_in[13];
    const float* ln2b  = (const float*)d_in[14];
    float* out = (float*)d_out;

#define GETP(T, sym) ({ void* _p; cudaGetSymbolAddress(&_p, sym); (T*)_p; })
    float* qkv  = GETP(float, g_qkv);
    float* proj = GETP(float, g_proj);
    float* x1   = GETP(float, g_x1);
    float* Y    = GETP(float, g_Y);
    __nv_bfloat16* src_h  = GETP(__nv_bfloat16, g_src_h);
    __nv_bfloat16* src_l  = GETP(__nv_bfloat16, g_src_l);
    __nv_bfloat16* attn_h = GETP(__nv_bfloat16, g_attn_h);
    __nv_bfloat16* attn_l = GETP(__nv_bfloat16, g_attn_l);
    __nv_bfloat16* x1_h   = GETP(__nv_bfloat16, g_x1_h);
    __nv_bfloat16* x1_l   = GETP(__nv_bfloat16, g_x1_l);
    __nv_bfloat16* wqkv_h = GETP(__nv_bfloat16, g_wqkv_h);
    __nv_bfloat16* wqkv_l = GETP(__nv_bfloat16, g_wqkv_l);
    __nv_bfloat16* wo_h   = GETP(__nv_bfloat16, g_wo_h);
    __nv_bfloat16* wo_l   = GETP(__nv_bfloat16, g_wo_l);
    __nv_bfloat16* w1t_h  = GETP(__nv_bfloat16, g_w1t_h);
    __nv_bfloat16* w1t_l  = GETP(__nv_bfloat16, g_w1t_l);
    __nv_bfloat16* w2t_h  = GETP(__nv_bfloat16, g_w2t_h);
    __nv_bfloat16* w2t_l  = GETP(__nv_bfloat16, g_w2t_l);
    __nv_bfloat16* H_h    = GETP(__nv_bfloat16, g_H_h);
    __nv_bfloat16* H_l    = GETP(__nv_bfloat16, g_H_l);
    int* cnt  = GETP(int, d_count);
    int* offp = GETP(int, d_off);
    int* list = GETP(int, d_list);

    static bool attr_done = false;
    if (!attr_done) {
        cudaFuncSetAttribute(mma_gemm<0>, cudaFuncAttributeMaxDynamicSharedMemorySize, GEMM_SMEM);
        cudaFuncSetAttribute(mma_gemm<1>, cudaFuncAttributeMaxDynamicSharedMemorySize, GEMM_SMEM);
        cudaFuncSetAttribute(mma_gemm<2>, cudaFuncAttributeMaxDynamicSharedMemorySize, GEMM_SMEM);
        cudaFuncSetAttribute(attn_kernel, cudaFuncAttributeMaxDynamicSharedMemorySize, ATTN_SMEM);
        attr_done = true;
    }

    init_kernel<<<1, 32>>>();

    // conversions (src + weights)
    split_cvt_kernel<<<(TOK * DM / 4 + 255) / 256, 256>>>(src, src_h, src_l, TOK * DM / 4);
    split_cvt_kernel<<<(D3 * DM / 4 + 255) / 256, 256>>>(in_w, wqkv_h, wqkv_l, D3 * DM / 4);
    split_cvt_kernel<<<(DM * DM / 4 + 255) / 256, 256>>>(out_w, wo_h, wo_l, DM * DM / 4);
    transpose_split_kernel<<<dim3(DFF / 32, DM / 32, NEXP), dim3(32, 8)>>>(w1, w1t_h, w1t_l, DM, DFF);
    transpose_split_kernel<<<dim3(DM / 32, DFF / 32, NEXP), dim3(32, 8)>>>(w2, w2t_h, w2t_l, DFF, DM);

    // QKV = src @ in_w^T + b
    mma_gemm<0><<<dim3(D3 / BN, TOK / BM), 256, GEMM_SMEM>>>(
        src_h, src_l, wqkv_h, wqkv_l, in_b, qkv, nullptr, nullptr,
        nullptr, nullptr, nullptr, TOK, D3, DM);

    // attention (writes bf16 split directly)
    attn_kernel<<<dim3(NB * NHEAD, SEQ / 16), 128, ATTN_SMEM>>>(qkv, attn_h, attn_l);

    // proj = attn @ out_w^T + b
    mma_gemm<0><<<dim3(DM / BN, TOK / BM), 256, GEMM_SMEM>>>(
        attn_h, attn_l, wo_h, wo_l, out_b, proj, nullptr, nullptr,
        nullptr, nullptr, nullptr, TOK, DM, DM);

    // x1 = LN(src + proj), with fused split
    add_ln_split_kernel<<<TOK, 256>>>(src, proj, ln1g, ln1b, x1, x1_h, x1_l);

    router_kernel<<<TOK, 256>>>(x1, rw, rb);
    offsets_kernel<<<1, 32>>>();

    // H = relu(gather(x1) @ w1 + b1)  [split bf16 out]
    mma_gemm<1><<<dim3(DFF / BN, TOK / BM, NEXP), 256, GEMM_SMEM>>>(
        x1_h, x1_l, w1t_h, w1t_l, b1, nullptr, H_h, H_l,
        cnt, offp, list, 0, DFF, DM);
    // Y = H @ w2 + b2
    mma_gemm<2><<<dim3(DM / BN, TOK / BM, NEXP), 256, GEMM_SMEM>>>(
        H_h, H_l, w2t_h, w2t_l, b2, Y, nullptr, nullptr,
        cnt, offp, nullptr, 0, DM, DFF);

    combine_ln_kernel<<<TOK, 256>>>(Y, x1, ln2g, ln2b, out);
    lb_kernel<<<1, 1>>>(out, out_size);
}

// round 6
// speedup vs baseline: 3.2024x; 1.1993x over previous
#include <cuda_runtime.h>
#include <cuda_bf16.h>
#include <cuda_fp16.h>
#include <cstdint>
#include <math.h>

// Problem constants
#define TOK   4096          // B*S
#define DM    1024          // d_model
#define D3    3072          // 3*d_model
#define NHEAD 16
#define DH    64
#define DFF   4096
#define NEXP  8
#define SEQ   1024
#define NB    4
#define TOTROWS (2*TOK)     // packed expert rows (top-2)

// ============================ scratch globals ============================
__device__ __align__(16) float g_qkv[(size_t)TOK * D3];
__device__ __align__(16) float g_proj[(size_t)TOK * DM];
__device__ __align__(16) float g_x1[(size_t)TOK * DM];
__device__ __align__(16) float g_Y[(size_t)TOTROWS * DM];

__device__ __align__(16) __nv_bfloat16 g_src_h[(size_t)TOK * DM];
__device__ __align__(16) __nv_bfloat16 g_src_l[(size_t)TOK * DM];
__device__ __align__(16) __nv_bfloat16 g_attn_h[(size_t)TOK * DM];
__device__ __align__(16) __nv_bfloat16 g_attn_l[(size_t)TOK * DM];
__device__ __align__(16) __nv_bfloat16 g_wqkv_h[(size_t)D3 * DM];
__device__ __align__(16) __nv_bfloat16 g_wqkv_l[(size_t)D3 * DM];
__device__ __align__(16) __nv_bfloat16 g_wo_h[(size_t)DM * DM];
__device__ __align__(16) __nv_bfloat16 g_wo_l[(size_t)DM * DM];

// fp16 MoE path
__device__ __align__(16) __half g_x1h[(size_t)TOK * DM];
__device__ __align__(16) __half g_x1l[(size_t)TOK * DM];
__device__ __align__(16) __half g_w1t[(size_t)NEXP * DFF * DM];
__device__ __align__(16) __half g_w2t[(size_t)NEXP * DM * DFF];
__device__ __align__(16) __half g_Hh[(size_t)TOTROWS * DFF];
__device__ __align__(16) __half g_Hl[(size_t)TOTROWS * DFF];

__device__ int   d_count[NEXP];
__device__ int   d_off[NEXP];
__device__ float d_Psum[NEXP];
__device__ int   d_list[NEXP * TOK];
__device__ int   d_slot[TOK * 2];
__device__ float d_gate[TOK * 2];

// ============================ PTX helpers (sm_80-level only) =================
__device__ __forceinline__ uint32_t smem_u32(const void* p) {
    uint32_t a;
    asm("{ .reg .u64 t; cvta.to.shared.u64 t, %1; cvt.u32.u64 %0, t; }"
        : "=r"(a) : "l"(p));
    return a;
}
__device__ __forceinline__ void cp16(uint32_t dst, const void* src, int sz) {
    asm volatile("cp.async.cg.shared.global [%0], [%1], 16, %2;"
                 :: "r"(dst), "l"(src), "r"(sz) : "memory");
}
#define CP_COMMIT() asm volatile("cp.async.commit_group;" ::: "memory")
template<int N_>
__device__ __forceinline__ void cp_wait() {
    asm volatile("cp.async.wait_group %0;" :: "n"(N_) : "memory");
}
__device__ __forceinline__ void ldsm4(uint32_t* r, uint32_t addr) {
    asm volatile("ldmatrix.sync.aligned.m8n8.x4.shared.b16 {%0,%1,%2,%3}, [%4];"
                 : "=r"(r[0]), "=r"(r[1]), "=r"(r[2]), "=r"(r[3]) : "r"(addr));
}
__device__ __forceinline__ void mma16816(float* c, const uint32_t* a, const uint32_t* b) {
    asm volatile("mma.sync.aligned.m16n8k16.row.col.f32.bf16.bf16.f32 "
                 "{%0,%1,%2,%3}, {%4,%5,%6,%7}, {%8,%9}, {%0,%1,%2,%3};"
                 : "+f"(c[0]), "+f"(c[1]), "+f"(c[2]), "+f"(c[3])
                 : "r"(a[0]), "r"(a[1]), "r"(a[2]), "r"(a[3]),
                   "r"(b[0]), "r"(b[1]));
}
__device__ __forceinline__ void mma16816h(float* c, const uint32_t* a, const uint32_t* b) {
    asm volatile("mma.sync.aligned.m16n8k16.row.col.f32.f16.f16.f32 "
                 "{%0,%1,%2,%3}, {%4,%5,%6,%7}, {%8,%9}, {%0,%1,%2,%3};"
                 : "+f"(c[0]), "+f"(c[1]), "+f"(c[2]), "+f"(c[3])
                 : "r"(a[0]), "r"(a[1]), "r"(a[2]), "r"(a[3]),
                   "r"(b[0]), "r"(b[1]));
}

// ============================ dense warp-MMA GEMM (bf16 3-term) ==============
#define BM 128
#define BN 128
#define BK 32
#define A_BYTES 16384
#define STG_BYTES 32768
#define GEMM_SMEM (2 * STG_BYTES)

__global__ __launch_bounds__(256, 2) void mma_gemm(
    const __nv_bfloat16* __restrict__ AH, const __nv_bfloat16* __restrict__ AL,
    const __nv_bfloat16* __restrict__ BH, const __nv_bfloat16* __restrict__ BL,
    const float* __restrict__ bias, float* __restrict__ Cf, int N, int K)
{
    extern __shared__ __nv_bfloat16 smbf[];
    const int tid = threadIdx.x;
    const int lane = tid & 31, wid = tid >> 5;
    const int wm = wid & 3, wn = wid >> 2;
    const int g = lane >> 2, tig = lane & 3;
    const int m0 = blockIdx.y * BM, n0 = blockIdx.x * BN;

    const uint32_t sb = smem_u32(smbf);

    float acc[2][8][4];
#pragma unroll
    for (int mt = 0; mt < 2; mt++)
#pragma unroll
        for (int nt = 0; nt < 8; nt++)
#pragma unroll
            for (int i = 0; i < 4; i++) acc[mt][nt][i] = 0.0f;

    auto load_stage = [&](int st, int k0) {
        uint32_t sbase = sb + st * STG_BYTES;
#pragma unroll
        for (int i = 0; i < 4; i++) {
            int u = tid + i * 256;
            int isB = u >> 9;
            int idx = u & 511;
            int row = idx >> 2, seg = idx & 3;
            int phh = seg ^ (row & 7);
            int phl = (seg + 4) ^ (row & 7);
            uint32_t dbase = sbase + isB * A_BYTES + row * 128;
            if (!isB) {
                size_t aoff = (size_t)(m0 + row) * K + k0 + seg * 8;
                cp16(dbase + phh * 16, AH + aoff, 16);
                cp16(dbase + phl * 16, AL + aoff, 16);
            } else {
                size_t boff = (size_t)(n0 + row) * K + k0 + seg * 8;
                cp16(dbase + phh * 16, BH + boff, 16);
                cp16(dbase + phl * 16, BL + boff, 16);
            }
        }
    };

    const int a_row_in = (lane & 15);
    const int a_seg_in = (lane >> 4);
    const int b_row_in = (lane & 7) + ((lane & 16) ? 8 : 0);
    const int b_seg_in = (lane & 8) ? 1 : 0;

    auto compute = [&](int st) {
        uint32_t sA = sb + st * STG_BYTES;
        uint32_t sB = sA + A_BYTES;
#pragma unroll
        for (int ks = 0; ks < 2; ks++) {
            const int kseg = ks * 2;
            uint32_t ah[2][4], al[2][4];
#pragma unroll
            for (int mt = 0; mt < 2; mt++) {
                int row = wm * 32 + mt * 16 + a_row_in;
                int sl = kseg + a_seg_in;
                uint32_t base = sA + row * 128;
                ldsm4(ah[mt], base + ((sl ^ (row & 7)) << 4));
                ldsm4(al[mt], base + (((sl + 4) ^ (row & 7)) << 4));
            }
#pragma unroll
            for (int ntp = 0; ntp < 4; ntp++) {
                int row = wn * 64 + ntp * 16 + b_row_in;
                int sl = kseg + b_seg_in;
                uint32_t base = sB + row * 128;
                uint32_t bh[4], bl[4];
                ldsm4(bh, base + ((sl ^ (row & 7)) << 4));
                ldsm4(bl, base + (((sl + 4) ^ (row & 7)) << 4));
#pragma unroll
                for (int half = 0; half < 2; half++) {
                    int nt = ntp * 2 + half;
#pragma unroll
                    for (int mt = 0; mt < 2; mt++) {
                        mma16816(acc[mt][nt], ah[mt], bh + half * 2);
                        mma16816(acc[mt][nt], ah[mt], bl + half * 2);
                        mma16816(acc[mt][nt], al[mt], bh + half * 2);
                    }
                }
            }
        }
    };

    const int nk = K / BK;
    load_stage(0, 0);
    CP_COMMIT();
    for (int c = 0; c < nk; c++) {
        if (c + 1 < nk) load_stage((c + 1) & 1, (c + 1) * BK);
        CP_COMMIT();
        cp_wait<1>();
        __syncthreads();
        compute(c & 1);
        __syncthreads();
    }

#pragma unroll
    for (int nt = 0; nt < 8; nt++) {
        int col = n0 + wn * 64 + nt * 8 + 2 * tig;
        float b0 = bias[col], b1 = bias[col + 1];
#pragma unroll
        for (int mt = 0; mt < 2; mt++) {
            int r0 = m0 + wm * 32 + mt * 16 + g;
            float* c = acc[mt][nt];
#pragma unroll
            for (int hh = 0; hh < 2; hh++) {
                int r = r0 + hh * 8;
                *(float2*)(Cf + (size_t)r * N + col) =
                    make_float2(c[hh * 2 + 0] + b0, c[hh * 2 + 1] + b1);
            }
        }
    }
}

// ============================ MoE GEMM (fp16 2-term, BK=64) ==================
// C = (Ah+Al)[M,K] @ Bh[N,K]^T + bias.
// MODE 1: gather A rows via list, relu, fp16 hi/lo out (H).
// MODE 2: offset A rows, fp32 out (Y).
// stage: A 128 rows x 256B ([Ah 128B | Al 128B], swizzled), B 128 rows x 128B.
#define MBK 64
#define MA_BYTES 32768
#define MSTG_BYTES 49152
#define MOE_SMEM (2 * MSTG_BYTES)

template<int MODE>
__global__ __launch_bounds__(256, 2) void moe_gemm(
    const __half* __restrict__ AH, const __half* __restrict__ AL,
    const __half* __restrict__ BH,
    const float* __restrict__ biasBase,
    float* __restrict__ Cf, __half* __restrict__ CH, __half* __restrict__ CL,
    const int* __restrict__ counts, const int* __restrict__ offs,
    const int* __restrict__ listBase,
    int N, int K)
{
    extern __shared__ __half smh[];
    const int tid = threadIdx.x;
    const int lane = tid & 31, wid = tid >> 5;
    const int wm = wid & 3, wn = wid >> 2;
    const int g = lane >> 2, tig = lane & 3;
    const int m0 = blockIdx.y * BM, n0 = blockIdx.x * BN;
    const int e = blockIdx.z;

    const int M = counts[e];
    if (m0 >= M) return;
    const __half* bhp = BH + (size_t)e * N * K;
    const float* bias = biasBase + (size_t)e * N;
    const int* lst = (MODE == 1) ? (listBase + e * TOK) : nullptr;
    const int arow0 = offs[e];
    const int crow0 = offs[e];

    const uint32_t sb = smem_u32(smh);

    float acc[2][8][4];
#pragma unroll
    for (int mt = 0; mt < 2; mt++)
#pragma unroll
        for (int nt = 0; nt < 8; nt++)
#pragma unroll
            for (int i = 0; i < 4; i++) acc[mt][nt][i] = 0.0f;

    auto load_stage = [&](int st, int k0) {
        uint32_t sbase = sb + st * MSTG_BYTES;
#pragma unroll
        for (int i = 0; i < 4; i++) {
            int idx = tid + i * 256;            // 0..1023
            int row = idx >> 3, seg = idx & 7;
            uint32_t ph = (uint32_t)((seg ^ (row & 7)) << 4);
            int gr = m0 + row;
            bool ok = gr < M;
            size_t arow = (MODE == 1) ? (ok ? (size_t)lst[gr] : 0)
                                      : (size_t)(arow0 + (ok ? gr : 0));
            int sz = ok ? 16 : 0;
            size_t aoff = arow * (size_t)K + k0 + seg * 8;
            cp16(sbase + row * 256 + ph, AH + aoff, sz);
            cp16(sbase + row * 256 + 128 + ph, AL + aoff, sz);
            size_t boff = (size_t)(n0 + row) * K + k0 + seg * 8;
            cp16(sbase + MA_BYTES + row * 128 + ph, bhp + boff, 16);
        }
    };

    const int a_row_in = (lane & 15);
    const int a_seg_in = (lane >> 4);
    const int b_row_in = (lane & 7) + ((lane & 16) ? 8 : 0);
    const int b_seg_in = (lane & 8) ? 1 : 0;

    auto compute = [&](int st) {
        uint32_t sA = sb + st * MSTG_BYTES;
        uint32_t sB = sA + MA_BYTES;
#pragma unroll
        for (int ks = 0; ks < 4; ks++) {
            const int kseg = ks * 2;
            uint32_t ah[2][4], al[2][4];
#pragma unroll
            for (int mt = 0; mt < 2; mt++) {
                int row = wm * 32 + mt * 16 + a_row_in;
                int sl = kseg + a_seg_in;
                uint32_t base = sA + row * 256;
                uint32_t sw = (uint32_t)((sl ^ (row & 7)) << 4);
                ldsm4(ah[mt], base + sw);
                ldsm4(al[mt], base + 128 + sw);
            }
#pragma unroll
            for (int ntp = 0; ntp < 4; ntp++) {
                int row = wn * 64 + ntp * 16 + b_row_in;
                int sl = kseg + b_seg_in;
                uint32_t bh[4];
                ldsm4(bh, sB + row * 128 + ((sl ^ (row & 7)) << 4));
#pragma unroll
                for (int half = 0; half < 2; half++) {
                    int nt = ntp * 2 + half;
#pragma unroll
                    for (int mt = 0; mt < 2; mt++) {
                        mma16816h(acc[mt][nt], ah[mt], bh + half * 2);
                        mma16816h(acc[mt][nt], al[mt], bh + half * 2);
                    }
                }
            }
        }
    };

    const int nk = K / MBK;
    load_stage(0, 0);
    CP_COMMIT();
    for (int c = 0; c < nk; c++) {
        if (c + 1 < nk) load_stage((c + 1) & 1, (c + 1) * MBK);
        CP_COMMIT();
        cp_wait<1>();
        __syncthreads();
        compute(c & 1);
        __syncthreads();
    }

#pragma unroll
    for (int nt = 0; nt < 8; nt++) {
        int col = n0 + wn * 64 + nt * 8 + 2 * tig;
        float b0 = bias[col], b1 = bias[col + 1];
#pragma unroll
        for (int mt = 0; mt < 2; mt++) {
            int r0 = m0 + wm * 32 + mt * 16 + g;
            float* c = acc[mt][nt];
#pragma unroll
            for (int hh = 0; hh < 2; hh++) {
                int r = r0 + hh * 8;
                if (r < M) {
                    float v0 = c[hh * 2 + 0] + b0;
                    float v1 = c[hh * 2 + 1] + b1;
                    size_t o = (size_t)(crow0 + r) * N + col;
                    if (MODE == 1) {
                        v0 = fmaxf(v0, 0.0f); v1 = fmaxf(v1, 0.0f);
                        __half h0 = __float2half_rn(v0);
                        __half h1 = __float2half_rn(v1);
                        *(__half2*)(CH + o) = __halves2half2(h0, h1);
                        *(__half2*)(CL + o) = __halves2half2(
                            __float2half_rn(v0 - __half2float(h0)),
                            __float2half_rn(v1 - __half2float(h1)));
                    } else {
                        *(float2*)(Cf + o) = make_float2(v0, v1);
                    }
                }
            }
        }
    }
}

// ============================ small kernels ============================
__global__ void init_kernel() {
    int i = threadIdx.x;
    if (i < NEXP) { d_count[i] = 0; d_Psum[i] = 0.0f; }
}

__global__ void offsets_kernel() {
    if (threadIdx.x == 0) {
        int a = 0;
#pragma unroll
        for (int e = 0; e < NEXP; e++) { d_off[e] = a; a += d_count[e]; }
    }
}

__global__ __launch_bounds__(256) void split_cvt_kernel(
    const float* __restrict__ x, __nv_bfloat16* __restrict__ h,
    __nv_bfloat16* __restrict__ l, int n4)
{
    int i = blockIdx.x * 256 + threadIdx.x;
    if (i >= n4) return;
    float4 v = ((const float4*)x)[i];
    float vs[4] = {v.x, v.y, v.z, v.w};
    __nv_bfloat16 hv[4], lv[4];
#pragma unroll
    for (int j = 0; j < 4; j++) {
        hv[j] = __float2bfloat16(vs[j]);
        lv[j] = __float2bfloat16(vs[j] - __bfloat162float(hv[j]));
    }
    *(uint2*)(h + i * 4) = *(uint2*)hv;
    *(uint2*)(l + i * 4) = *(uint2*)lv;
}

// per-expert transpose to single fp16: W[e][K][N] -> T[e][N][K]
__global__ __launch_bounds__(256) void transpose_half_kernel(
    const float* __restrict__ W, __half* __restrict__ Th, int K, int N)
{
    __shared__ float t[32][33];
    int e = blockIdx.z;
    const float* w = W + (size_t)e * K * N;
    __half* th = Th + (size_t)e * N * K;
    int n0 = blockIdx.x * 32, k0 = blockIdx.y * 32;
    int x = threadIdx.x, y = threadIdx.y;
#pragma unroll
    for (int i = 0; i < 32; i += 8)
        t[y + i][x] = w[(size_t)(k0 + y + i) * N + n0 + x];
    __syncthreads();
#pragma unroll
    for (int i = 0; i < 32; i += 8)
        th[(size_t)(n0 + y + i) * K + k0 + x] = __float2half_rn(t[x][y + i]);
}

// ============================ attention ============================
#define ATS_K 66
#define ATS_V 68
#define TILE_FLOATS (64 * ATS_V)
#define ATTN_SMEM ((TILE_FLOATS + 16 * 1024 + 16 * 64) * 4)

__global__ __launch_bounds__(128) void attn_kernel(
    const float* __restrict__ qkv,
    __nv_bfloat16* __restrict__ oh, __nv_bfloat16* __restrict__ ol)
{
    extern __shared__ float sm[];
    float* tile = sm;
    float (*sc)[1024] = (float(*)[1024])(sm + TILE_FLOATS);
    float (*qs)[64]   = (float(*)[64])(sm + TILE_FLOATS + 16 * 1024);

    int bh = blockIdx.x;
    int b = bh >> 4, h = bh & 15;
    int tid = threadIdx.x, w = tid >> 5, lane = tid & 31;
    int q0 = blockIdx.y * 16;
    int hoff = h * DH;
    int rb = w * 4;

    for (int i4 = tid; i4 < 256; i4 += 128) {
        int r = i4 >> 4, ds = i4 & 15;
        float4 v = *(const float4*)(qkv + (size_t)(b * SEQ + q0 + r) * D3 + hoff + ds * 4);
        float4* dst = (float4*)&qs[r][ds * 4];
        *dst = make_float4(v.x * 0.125f, v.y * 0.125f, v.z * 0.125f, v.w * 0.125f);
    }

    int k0 = 2 * lane;
    for (int kt = 0; kt < 16; kt++) {
        __syncthreads();
        for (int i4 = tid; i4 < 1024; i4 += 128) {
            int key = i4 >> 4, ds = i4 & 15;
            float4 v = *(const float4*)(qkv + (size_t)(b * SEQ + kt * 64 + key) * D3 + DM + hoff + ds * 4);
            tile[(ds * 4 + 0) * ATS_K + key] = v.x;
            tile[(ds * 4 + 1) * ATS_K + key] = v.y;
            tile[(ds * 4 + 2) * ATS_K + key] = v.z;
            tile[(ds * 4 + 3) * ATS_K + key] = v.w;
        }
        __syncthreads();
        float s[4][2] = {{0.f,0.f},{0.f,0.f},{0.f,0.f},{0.f,0.f}};
#pragma unroll 4
        for (int d4 = 0; d4 < 16; d4++) {
            float4 q0v = *(const float4*)&qs[rb + 0][d4 * 4];
            float4 q1v = *(const float4*)&qs[rb + 1][d4 * 4];
            float4 q2v = *(const float4*)&qs[rb + 2][d4 * 4];
            float4 q3v = *(const float4*)&qs[rb + 3][d4 * 4];
            const float* qa[4] = {(float*)&q0v, (float*)&q1v, (float*)&q2v, (float*)&q3v};
#pragma unroll
            for (int dd = 0; dd < 4; dd++) {
                float2 t = *(const float2*)&tile[(d4 * 4 + dd) * ATS_K + k0];
#pragma unroll
                for (int r = 0; r < 4; r++) {
                    s[r][0] += qa[r][dd] * t.x;
                    s[r][1] += qa[r][dd] * t.y;
                }
            }
        }
#pragma unroll
        for (int r = 0; r < 4; r++) {
            sc[rb + r][kt * 64 + k0]     = s[r][0];
            sc[rb + r][kt * 64 + k0 + 1] = s[r][1];
        }
    }

    float inv[4];
#pragma unroll
    for (int rr = 0; rr < 4; rr++) {
        int r = rb + rr;
        float m = -1e30f;
        for (int i = lane; i < 1024; i += 32) m = fmaxf(m, sc[r][i]);
#pragma unroll
        for (int off = 16; off; off >>= 1) m = fmaxf(m, __shfl_xor_sync(0xffffffffu, m, off));
        float sum = 0.f;
        for (int i = lane; i < 1024; i += 32) {
            float p = __expf(sc[r][i] - m);
            sc[r][i] = p;
            sum += p;
        }
#pragma unroll
        for (int off = 16; off; off >>= 1) sum += __shfl_xor_sync(0xffffffffu, sum, off);
        inv[rr] = 1.0f / sum;
    }

    int d0 = lane, d1 = lane + 32;
    float a[4][2] = {{0.f,0.f},{0.f,0.f},{0.f,0.f},{0.f,0.f}};
    for (int vt = 0; vt < 16; vt++) {
        __syncthreads();
        for (int i4 = tid; i4 < 1024; i4 += 128) {
            int key = i4 >> 4, ds = i4 & 15;
            float4 v = *(const float4*)(qkv + (size_t)(b * SEQ + vt * 64 + key) * D3 + 2 * DM + hoff + ds * 4);
            *(float4*)&tile[key * ATS_V + ds * 4] = v;
        }
        __syncthreads();
#pragma unroll 4
        for (int k4 = 0; k4 < 16; k4++) {
            float4 p0v = *(const float4*)&sc[rb + 0][vt * 64 + k4 * 4];
            float4 p1v = *(const float4*)&sc[rb + 1][vt * 64 + k4 * 4];
            float4 p2v = *(const float4*)&sc[rb + 2][vt * 64 + k4 * 4];
            float4 p3v = *(const float4*)&sc[rb + 3][vt * 64 + k4 * 4];
            const float* pa[4] = {(float*)&p0v, (float*)&p1v, (float*)&p2v, (float*)&p3v};
#pragma unroll
            for (int kk = 0; kk < 4; kk++) {
                int key = k4 * 4 + kk;
                float v0 = tile[key * ATS_V + d0];
                float v1 = tile[key * ATS_V + d1];
#pragma unroll
                for (int r = 0; r < 4; r++) {
                    a[r][0] += pa[r][kk] * v0;
                    a[r][1] += pa[r][kk] * v1;
                }
            }
        }
    }
    size_t base = (size_t)(b * SEQ + q0 + rb) * DM + hoff;
#pragma unroll
    for (int rr = 0; rr < 4; rr++) {
        float r0 = a[rr][0] * inv[rr], r1 = a[rr][1] * inv[rr];
        __nv_bfloat16 h0 = __float2bfloat16(r0);
        __nv_bfloat16 h1 = __float2bfloat16(r1);
        oh[base + rr * DM + d0] = h0;
        oh[base + rr * DM + d1] = h1;
        ol[base + rr * DM + d0] = __float2bfloat16(r0 - __bfloat162float(h0));
        ol[base + rr * DM + d1] = __float2bfloat16(r1 - __bfloat162float(h1));
    }
}

// ============================ LN / router / combine / lb ============================
__device__ __forceinline__ float blk_sum(float v, float* red) {
    int tid = threadIdx.x;
    red[tid] = v;
    __syncthreads();
#pragma unroll
    for (int s = 128; s > 0; s >>= 1) {
        if (tid < s) red[tid] += red[tid + s];
        __syncthreads();
    }
    float r = red[0];
    __syncthreads();
    return r;
}

// x1 = LN(a + b); also writes fp16 hi/lo split of x1
__global__ __launch_bounds__(256) void add_ln_split_kernel(
    const float* __restrict__ a, const float* __restrict__ b,
    const float* __restrict__ g, const float* __restrict__ bb,
    float* __restrict__ out,
    __half* __restrict__ oh, __half* __restrict__ ol)
{
    __shared__ float red[256];
    size_t t = blockIdx.x;
    int tid = threadIdx.x;
    float v[4];
    float s = 0.f;
#pragma unroll
    for (int i = 0; i < 4; i++) {
        int d = tid + i * 256;
        v[i] = a[t * DM + d] + b[t * DM + d];
        s += v[i];
    }
    float mu = blk_sum(s, red) * (1.0f / DM);
    float sq = 0.f;
#pragma unroll
    for (int i = 0; i < 4; i++) { float c = v[i] - mu; sq += c * c; }
    float var = blk_sum(sq, red) * (1.0f / DM);
    float rstd = rsqrtf(var + 1e-5f);
#pragma unroll
    for (int i = 0; i < 4; i++) {
        int d = tid + i * 256;
        float y = (v[i] - mu) * rstd * g[d] + bb[d];
        out[t * DM + d] = y;
        __half hi = __float2half_rn(y);
        oh[t * DM + d] = hi;
        ol[t * DM + d] = __float2half_rn(y - __half2float(hi));
    }
}

__global__ __launch_bounds__(256) void router_kernel(
    const float* __restrict__ x1, const float* __restrict__ rw,
    const float* __restrict__ rb)
{
    __shared__ float logits[NEXP];
    size_t t = blockIdx.x;
    int tid = threadIdx.x;
    int w = tid >> 5, lane = tid & 31;
    if (w < NEXP) {
        float s = 0.f;
        for (int k = lane; k < DM; k += 32)
            s += x1[t * DM + k] * rw[(size_t)w * DM + k];
#pragma unroll
        for (int off = 16; off; off >>= 1) s += __shfl_xor_sync(0xffffffffu, s, off);
        if (lane == 0) logits[w] = s + rb[w];
    }
    __syncthreads();
    if (tid == 0) {
        float p[NEXP];
        float mx = logits[0];
#pragma unroll
        for (int e = 1; e < NEXP; e++) mx = fmaxf(mx, logits[e]);
        float sum = 0.f;
#pragma unroll
        for (int e = 0; e < NEXP; e++) { p[e] = expf(logits[e] - mx); sum += p[e]; }
        float invs = 1.0f / sum;
#pragma unroll
        for (int e = 0; e < NEXP; e++) {
            p[e] *= invs;
            atomicAdd(&d_Psum[e], p[e]);
        }
        int i0 = 0;
#pragma unroll
        for (int e = 1; e < NEXP; e++) if (p[e] > p[i0]) i0 = e;
        int i1 = (i0 == 0) ? 1 : 0;
#pragma unroll
        for (int e = 0; e < NEXP; e++) if (e != i0 && p[e] > p[i1]) i1 = e;
        float gsum = p[i0] + p[i1];

        int pos0 = atomicAdd(&d_count[i0], 1);
        d_list[i0 * TOK + pos0] = (int)t;
        d_slot[t * 2 + 0] = i0 * TOK + pos0;
        d_gate[t * 2 + 0] = p[i0] / gsum;

        int pos1 = atomicAdd(&d_count[i1], 1);
        d_list[i1 * TOK + pos1] = (int)t;
        d_slot[t * 2 + 1] = i1 * TOK + pos1;
        d_gate[t * 2 + 1] = p[i1] / gsum;
    }
}

__global__ __launch_bounds__(256) void combine_ln_kernel(
    const float* __restrict__ Y, const float* __restrict__ x1,
    const float* __restrict__ g, const float* __restrict__ bb,
    float* __restrict__ out)
{
    __shared__ float red[256];
    size_t t = blockIdx.x;
    int tid = threadIdx.x;
    int sl0 = d_slot[t * 2 + 0], sl1 = d_slot[t * 2 + 1];
    size_t r0 = (size_t)d_off[sl0 / TOK] + (sl0 % TOK);
    size_t r1 = (size_t)d_off[sl1 / TOK] + (sl1 % TOK);
    float g0 = d_gate[t * 2 + 0], g1 = d_gate[t * 2 + 1];
    float v[4];
    float s = 0.f;
#pragma unroll
    for (int i = 0; i < 4; i++) {
        int d = tid + i * 256;
        float y = g0 * Y[r0 * DM + d] + g1 * Y[r1 * DM + d];
        v[i] = x1[t * DM + d] + y;
        s += v[i];
    }
    float mu = blk_sum(s, red) * (1.0f / DM);
    float sq = 0.f;
#pragma unroll
    for (int i = 0; i < 4; i++) { float c = v[i] - mu; sq += c * c; }
    float var = blk_sum(sq, red) * (1.0f / DM);
    float rstd = rsqrtf(var + 1e-5f);
#pragma unroll
    for (int i = 0; i < 4; i++) {
        int d = tid + i * 256;
        out[t * DM + d] = (v[i] - mu) * rstd * g[d] + bb[d];
    }
}

__global__ void lb_kernel(float* __restrict__ out, int out_size) {
    if (out_size > TOK * DM) {
        float lb = 0.f;
#pragma unroll
        for (int e = 0; e < NEXP; e++) {
            float f = (float)d_count[e] / (float)(TOK * 2);
            float P = d_Psum[e] / (float)TOK;
            lb += f * P;
        }
        out[out_size - 1] = (float)NEXP * lb;
    }
}

// ============================ launch ============================
extern "C" void kernel_launch(void* const* d_in, const int* in_sizes, int n_in,
                              void* d_out, int out_size)
{
    const float* src   = (const float*)d_in[0];
    const float* in_w  = (const float*)d_in[1];
    const float* in_b  = (const float*)d_in[2];
    const float* out_w = (const float*)d_in[3];
    const float* out_b = (const float*)d_in[4];
    const float* ln1g  = (const float*)d_in[5];
    const float* ln1b  = (const float*)d_in[6];
    const float* rw    = (const float*)d_in[7];
    const float* rb    = (const float*)d_in[8];
    const float* w1    = (const float*)d_in[9];
    const float* b1    = (const float*)d_in[10];
    const float* w2    = (const float*)d_in[11];
    const float* b2    = (const float*)d_in[12];
    const float* ln2g  = (const float*)d_in[13];
    const float* ln2b  = (const float*)d_in[14];
    float* out = (float*)d_out;

#define GETP(T, sym) ({ void* _p; cudaGetSymbolAddress(&_p, sym); (T*)_p; })
    float* qkv  = GETP(float, g_qkv);
    float* proj = GETP(float, g_proj);
    float* x1   = GETP(float, g_x1);
    float* Y    = GETP(float, g_Y);
    __nv_bfloat16* src_h  = GETP(__nv_bfloat16, g_src_h);
    __nv_bfloat16* src_l  = GETP(__nv_bfloat16, g_src_l);
    __nv_bfloat16* attn_h = GETP(__nv_bfloat16, g_attn_h);
    __nv_bfloat16* attn_l = GETP(__nv_bfloat16, g_attn_l);
    __nv_bfloat16* wqkv_h = GETP(__nv_bfloat16, g_wqkv_h);
    __nv_bfloat16* wqkv_l = GETP(__nv_bfloat16, g_wqkv_l);
    __nv_bfloat16* wo_h   = GETP(__nv_bfloat16, g_wo_h);
    __nv_bfloat16* wo_l   = GETP(__nv_bfloat16, g_wo_l);
    __half* x1h = GETP(__half, g_x1h);
    __half* x1l = GETP(__half, g_x1l);
    __half* w1t = GETP(__half, g_w1t);
    __half* w2t = GETP(__half, g_w2t);
    __half* Hh  = GETP(__half, g_Hh);
    __half* Hl  = GETP(__half, g_Hl);
    int* cnt  = GETP(int, d_count);
    int* offp = GETP(int, d_off);
    int* list = GETP(int, d_list);

    static bool attr_done = false;
    if (!attr_done) {
        cudaFuncSetAttribute(mma_gemm, cudaFuncAttributeMaxDynamicSharedMemorySize, GEMM_SMEM);
        cudaFuncSetAttribute(moe_gemm<1>, cudaFuncAttributeMaxDynamicSharedMemorySize, MOE_SMEM);
        cudaFuncSetAttribute(moe_gemm<2>, cudaFuncAttributeMaxDynamicSharedMemorySize, MOE_SMEM);
        cudaFuncSetAttribute(attn_kernel, cudaFuncAttributeMaxDynamicSharedMemorySize, ATTN_SMEM);
        attr_done = true;
    }

    init_kernel<<<1, 32>>>();

    // conversions (src + weights)
    split_cvt_kernel<<<(TOK * DM / 4 + 255) / 256, 256>>>(src, src_h, src_l, TOK * DM / 4);
    split_cvt_kernel<<<(D3 * DM / 4 + 255) / 256, 256>>>(in_w, wqkv_h, wqkv_l, D3 * DM / 4);
    split_cvt_kernel<<<(DM * DM / 4 + 255) / 256, 256>>>(out_w, wo_h, wo_l, DM * DM / 4);
    transpose_half_kernel<<<dim3(DFF / 32, DM / 32, NEXP), dim3(32, 8)>>>(w1, w1t, DM, DFF);
    transpose_half_kernel<<<dim3(DM / 32, DFF / 32, NEXP), dim3(32, 8)>>>(w2, w2t, DFF, DM);

    // QKV = src @ in_w^T + b (bf16 3-term)
    mma_gemm<<<dim3(D3 / BN, TOK / BM), 256, GEMM_SMEM>>>(
        src_h, src_l, wqkv_h, wqkv_l, in_b, qkv, D3, DM);

    // attention (writes bf16 split directly)
    attn_kernel<<<dim3(NB * NHEAD, SEQ / 16), 128, ATTN_SMEM>>>(qkv, attn_h, attn_l);

    // proj = attn @ out_w^T + b (bf16 3-term)
    mma_gemm<<<dim3(DM / BN, TOK / BM), 256, GEMM_SMEM>>>(
        attn_h, attn_l, wo_h, wo_l, out_b, proj, DM, DM);

    // x1 = LN(src + proj), with fused fp16 split
    add_ln_split_kernel<<<TOK, 256>>>(src, proj, ln1g, ln1b, x1, x1h, x1l);

    router_kernel<<<TOK, 256>>>(x1, rw, rb);
    offsets_kernel<<<1, 32>>>();

    // H = relu(gather(x1) @ w1 + b1)  [fp16 2-term, fp16-split out]
    moe_gemm<1><<<dim3(DFF / BN, TOK / BM, NEXP), 256, MOE_SMEM>>>(
        x1h, x1l, w1t, b1, nullptr, Hh, Hl, cnt, offp, list, DFF, DM);
    // Y = H @ w2 + b2  [fp16 2-term, fp32 out]
    moe_gemm<2><<<dim3(DM / BN, TOK / BM, NEXP), 256, MOE_SMEM>>>(
        Hh, Hl, w2t, b2, Y, nullptr, nullptr, cnt, offp, nullptr, DM, DFF);

    combine_ln_kernel<<<TOK, 256>>>(Y, x1, ln2g, ln2b, out);
    lb_kernel<<<1, 1>>>(out, out_size);
}

// round 7
// speedup vs baseline: 3.3645x; 1.0506x over previous
#include <cuda_runtime.h>
#include <cuda_bf16.h>
#include <cuda_fp16.h>
#include <cstdint>
#include <math.h>

// Problem constants
#define TOK   4096          // B*S
#define DM    1024          // d_model
#define D3    3072          // 3*d_model
#define NHEAD 16
#define DH    64
#define DFF   4096
#define NEXP  8
#define SEQ   1024
#define NB    4
#define TOTROWS (2*TOK)     // packed expert rows (top-2)

// ============================ scratch globals ============================
__device__ __align__(16) float g_qkv[(size_t)TOK * D3];
__device__ __align__(16) float g_proj[(size_t)TOK * DM];
__device__ __align__(16) float g_x1[(size_t)TOK * DM];
__device__ __align__(16) float g_Y[(size_t)TOTROWS * DM];

__device__ __align__(16) __half g_srch[(size_t)TOK * DM];
__device__ __align__(16) __half g_srcl[(size_t)TOK * DM];
__device__ __align__(16) __half g_attnh[(size_t)TOK * DM];
__device__ __align__(16) __half g_attnl[(size_t)TOK * DM];
__device__ __align__(16) __half g_wqkv[(size_t)D3 * DM];
__device__ __align__(16) __half g_wo[(size_t)DM * DM];
__device__ __align__(16) __half g_x1h[(size_t)TOK * DM];
__device__ __align__(16) __half g_x1l[(size_t)TOK * DM];
__device__ __align__(16) __half g_w1t[(size_t)NEXP * DFF * DM];
__device__ __align__(16) __half g_w2t[(size_t)NEXP * DM * DFF];
__device__ __align__(16) __half g_Hh[(size_t)TOTROWS * DFF];
__device__ __align__(16) __half g_Hl[(size_t)TOTROWS * DFF];

__device__ int   d_count[NEXP];
__device__ int   d_off[NEXP];
__device__ float d_Psum[NEXP];
__device__ int   d_list[NEXP * TOK];
__device__ int   d_slot[TOK * 2];
__device__ float d_gate[TOK * 2];

// ============================ PTX helpers (sm_80-level only) =================
__device__ __forceinline__ uint32_t smem_u32(const void* p) {
    uint32_t a;
    asm("{ .reg .u64 t; cvta.to.shared.u64 t, %1; cvt.u32.u64 %0, t; }"
        : "=r"(a) : "l"(p));
    return a;
}
__device__ __forceinline__ void cp16(uint32_t dst, const void* src, int sz) {
    asm volatile("cp.async.cg.shared.global [%0], [%1], 16, %2;"
                 :: "r"(dst), "l"(src), "r"(sz) : "memory");
}
#define CP_COMMIT() asm volatile("cp.async.commit_group;" ::: "memory")
template<int N_>
__device__ __forceinline__ void cp_wait() {
    asm volatile("cp.async.wait_group %0;" :: "n"(N_) : "memory");
}
__device__ __forceinline__ void ldsm4(uint32_t* r, uint32_t addr) {
    asm volatile("ldmatrix.sync.aligned.m8n8.x4.shared.b16 {%0,%1,%2,%3}, [%4];"
                 : "=r"(r[0]), "=r"(r[1]), "=r"(r[2]), "=r"(r[3]) : "r"(addr));
}
__device__ __forceinline__ void mma16816h(float* c, const uint32_t* a, const uint32_t* b) {
    asm volatile("mma.sync.aligned.m16n8k16.row.col.f32.f16.f16.f32 "
                 "{%0,%1,%2,%3}, {%4,%5,%6,%7}, {%8,%9}, {%0,%1,%2,%3};"
                 : "+f"(c[0]), "+f"(c[1]), "+f"(c[2]), "+f"(c[3])
                 : "r"(a[0]), "r"(a[1]), "r"(a[2]), "r"(a[3]),
                   "r"(b[0]), "r"(b[1]));
}

// ============================ unified fp16 GEMM (2-term A, BK=64) ============
// C = (Ah+Al)[M,K] @ Bh[N,K]^T + bias.
// MODE 0: dense (M=Mfix), fp32 out.
// MODE 1: expert gather A rows via list, relu, fp16 hi/lo out.
// MODE 2: expert offset A rows, fp32 out.
// stage: A 128 rows x 256B ([Ah 128B | Al 128B], seg^row swizzle), B 128x128B.
#define BM 128
#define BN 128
#define MBK 64
#define MA_BYTES 32768
#define MSTG_BYTES 49152
#define MOE_SMEM (2 * MSTG_BYTES)

template<int MODE>
__global__ __launch_bounds__(256, 2) void hgemm(
    const __half* __restrict__ AH, const __half* __restrict__ AL,
    const __half* __restrict__ BH,
    const float* __restrict__ biasBase,
    float* __restrict__ Cf, __half* __restrict__ CH, __half* __restrict__ CL,
    const int* __restrict__ counts, const int* __restrict__ offs,
    const int* __restrict__ listBase,
    int Mfix, int N, int K)
{
    extern __shared__ __half smh[];
    const int tid = threadIdx.x;
    const int lane = tid & 31, wid = tid >> 5;
    const int wm = wid & 3, wn = wid >> 2;
    const int g = lane >> 2, tig = lane & 3;
    const int m0 = blockIdx.y * BM, n0 = blockIdx.x * BN;
    const int e = blockIdx.z;

    int M = Mfix;
    const __half* bhp = BH;
    const float* bias = biasBase;
    const int* lst = nullptr;
    int arow0 = 0, crow0 = 0;
    if (MODE == 1) {
        M = counts[e];
        bhp += (size_t)e * N * K;
        bias += (size_t)e * N;
        lst = listBase + e * TOK;
        crow0 = offs[e];
    } else if (MODE == 2) {
        M = counts[e];
        bhp += (size_t)e * N * K;
        bias += (size_t)e * N;
        arow0 = offs[e]; crow0 = offs[e];
    }
    if (m0 >= M) return;

    const uint32_t sb = smem_u32(smh);

    float acc[2][8][4];
#pragma unroll
    for (int mt = 0; mt < 2; mt++)
#pragma unroll
        for (int nt = 0; nt < 8; nt++)
#pragma unroll
            for (int i = 0; i < 4; i++) acc[mt][nt][i] = 0.0f;

    auto load_stage = [&](int st, int k0) {
        uint32_t sbase = sb + st * MSTG_BYTES;
#pragma unroll
        for (int i = 0; i < 4; i++) {
            int idx = tid + i * 256;            // 0..1023
            int row = idx >> 3, seg = idx & 7;
            uint32_t ph = (uint32_t)((seg ^ (row & 7)) << 4);
            int gr = m0 + row;
            size_t arow; int sz;
            if (MODE == 0) {
                arow = (size_t)gr; sz = 16;
            } else if (MODE == 1) {
                bool ok = gr < M;
                arow = ok ? (size_t)lst[gr] : 0; sz = ok ? 16 : 0;
            } else {
                bool ok = gr < M;
                arow = (size_t)(arow0 + (ok ? gr : 0)); sz = ok ? 16 : 0;
            }
            size_t aoff = arow * (size_t)K + k0 + seg * 8;
            cp16(sbase + row * 256 + ph, AH + aoff, sz);
            cp16(sbase + row * 256 + 128 + ph, AL + aoff, sz);
            size_t boff = (size_t)(n0 + row) * K + k0 + seg * 8;
            cp16(sbase + MA_BYTES + row * 128 + ph, bhp + boff, 16);
        }
    };

    const int a_row_in = (lane & 15);
    const int a_seg_in = (lane >> 4);
    const int b_row_in = (lane & 7) + ((lane & 16) ? 8 : 0);
    const int b_seg_in = (lane & 8) ? 1 : 0;

    auto compute = [&](int st) {
        uint32_t sA = sb + st * MSTG_BYTES;
        uint32_t sB = sA + MA_BYTES;
#pragma unroll
        for (int ks = 0; ks < 4; ks++) {
            const int kseg = ks * 2;
            uint32_t ah[2][4], al[2][4];
#pragma unroll
            for (int mt = 0; mt < 2; mt++) {
                int row = wm * 32 + mt * 16 + a_row_in;
                int sl = kseg + a_seg_in;
                uint32_t base = sA + row * 256;
                uint32_t sw = (uint32_t)((sl ^ (row & 7)) << 4);
                ldsm4(ah[mt], base + sw);
                ldsm4(al[mt], base + 128 + sw);
            }
#pragma unroll
            for (int ntp = 0; ntp < 4; ntp++) {
                int row = wn * 64 + ntp * 16 + b_row_in;
                int sl = kseg + b_seg_in;
                uint32_t bh[4];
                ldsm4(bh, sB + row * 128 + ((sl ^ (row & 7)) << 4));
#pragma unroll
                for (int half = 0; half < 2; half++) {
                    int nt = ntp * 2 + half;
#pragma unroll
                    for (int mt = 0; mt < 2; mt++) {
                        mma16816h(acc[mt][nt], ah[mt], bh + half * 2);
                        mma16816h(acc[mt][nt], al[mt], bh + half * 2);
                    }
                }
            }
        }
    };

    const int nk = K / MBK;
    load_stage(0, 0);
    CP_COMMIT();
    for (int c = 0; c < nk; c++) {
        if (c + 1 < nk) load_stage((c + 1) & 1, (c + 1) * MBK);
        CP_COMMIT();
        cp_wait<1>();
        __syncthreads();
        compute(c & 1);
        __syncthreads();
    }

#pragma unroll
    for (int nt = 0; nt < 8; nt++) {
        int col = n0 + wn * 64 + nt * 8 + 2 * tig;
        float b0 = bias[col], b1 = bias[col + 1];
#pragma unroll
        for (int mt = 0; mt < 2; mt++) {
            int r0 = m0 + wm * 32 + mt * 16 + g;
            float* c = acc[mt][nt];
#pragma unroll
            for (int hh = 0; hh < 2; hh++) {
                int r = r0 + hh * 8;
                if (MODE == 0 || r < M) {
                    float v0 = c[hh * 2 + 0] + b0;
                    float v1 = c[hh * 2 + 1] + b1;
                    size_t o = (size_t)(crow0 + r) * N + col;
                    if (MODE == 1) {
                        v0 = fmaxf(v0, 0.0f); v1 = fmaxf(v1, 0.0f);
                        __half h0 = __float2half_rn(v0);
                        __half h1 = __float2half_rn(v1);
                        *(__half2*)(CH + o) = __halves2half2(h0, h1);
                        *(__half2*)(CL + o) = __halves2half2(
                            __float2half_rn(v0 - __half2float(h0)),
                            __float2half_rn(v1 - __half2float(h1)));
                    } else {
                        *(float2*)(Cf + o) = make_float2(v0, v1);
                    }
                }
            }
        }
    }
}

// ============================ small kernels ============================
__global__ void init_kernel() {
    int i = threadIdx.x;
    if (i < NEXP) { d_count[i] = 0; d_Psum[i] = 0.0f; }
}

__global__ void offsets_kernel() {
    if (threadIdx.x == 0) {
        int a = 0;
#pragma unroll
        for (int e = 0; e < NEXP; e++) { d_off[e] = a; a += d_count[e]; }
    }
}

// fp32 -> fp16 hi/lo split
__global__ __launch_bounds__(256) void split_cvt_h_kernel(
    const float* __restrict__ x, __half* __restrict__ h,
    __half* __restrict__ l, int n4)
{
    int i = blockIdx.x * 256 + threadIdx.x;
    if (i >= n4) return;
    float4 v = ((const float4*)x)[i];
    float vs[4] = {v.x, v.y, v.z, v.w};
    __half hv[4], lv[4];
#pragma unroll
    for (int j = 0; j < 4; j++) {
        hv[j] = __float2half_rn(vs[j]);
        lv[j] = __float2half_rn(vs[j] - __half2float(hv[j]));
    }
    *(uint2*)(h + i * 4) = *(uint2*)hv;
    *(uint2*)(l + i * 4) = *(uint2*)lv;
}

// fp32 -> fp16 (single)
__global__ __launch_bounds__(256) void cvt_h_kernel(
    const float* __restrict__ x, __half* __restrict__ h, int n4)
{
    int i = blockIdx.x * 256 + threadIdx.x;
    if (i >= n4) return;
    float4 v = ((const float4*)x)[i];
    __half hv[4] = {__float2half_rn(v.x), __float2half_rn(v.y),
                    __float2half_rn(v.z), __float2half_rn(v.w)};
    *(uint2*)(h + i * 4) = *(uint2*)hv;
}

// per-expert transpose to single fp16: W[e][K][N] -> T[e][N][K]
__global__ __launch_bounds__(256) void transpose_half_kernel(
    const float* __restrict__ W, __half* __restrict__ Th, int K, int N)
{
    __shared__ float t[32][33];
    int e = blockIdx.z;
    const float* w = W + (size_t)e * K * N;
    __half* th = Th + (size_t)e * N * K;
    int n0 = blockIdx.x * 32, k0 = blockIdx.y * 32;
    int x = threadIdx.x, y = threadIdx.y;
#pragma unroll
    for (int i = 0; i < 32; i += 8)
        t[y + i][x] = w[(size_t)(k0 + y + i) * N + n0 + x];
    __syncthreads();
#pragma unroll
    for (int i = 0; i < 32; i += 8)
        th[(size_t)(n0 + y + i) * K + k0 + x] = __float2half_rn(t[x][y + i]);
}

// ============================ attention ============================
#define ATS_K 66
#define ATS_V 68
#define TILE_FLOATS (64 * ATS_V)
#define ATTN_SMEM ((TILE_FLOATS + 16 * 1024 + 16 * 64) * 4)

__global__ __launch_bounds__(128) void attn_kernel(
    const float* __restrict__ qkv,
    __half* __restrict__ oh, __half* __restrict__ ol)
{
    extern __shared__ float sm[];
    float* tile = sm;
    float (*sc)[1024] = (float(*)[1024])(sm + TILE_FLOATS);
    float (*qs)[64]   = (float(*)[64])(sm + TILE_FLOATS + 16 * 1024);

    int bh = blockIdx.x;
    int b = bh >> 4, h = bh & 15;
    int tid = threadIdx.x, w = tid >> 5, lane = tid & 31;
    int q0 = blockIdx.y * 16;
    int hoff = h * DH;
    int rb = w * 4;

    for (int i4 = tid; i4 < 256; i4 += 128) {
        int r = i4 >> 4, ds = i4 & 15;
        float4 v = *(const float4*)(qkv + (size_t)(b * SEQ + q0 + r) * D3 + hoff + ds * 4);
        float4* dst = (float4*)&qs[r][ds * 4];
        *dst = make_float4(v.x * 0.125f, v.y * 0.125f, v.z * 0.125f, v.w * 0.125f);
    }

    int k0 = 2 * lane;
    for (int kt = 0; kt < 16; kt++) {
        __syncthreads();
        for (int i4 = tid; i4 < 1024; i4 += 128) {
            int key = i4 >> 4, ds = i4 & 15;
            float4 v = *(const float4*)(qkv + (size_t)(b * SEQ + kt * 64 + key) * D3 + DM + hoff + ds * 4);
            tile[(ds * 4 + 0) * ATS_K + key] = v.x;
            tile[(ds * 4 + 1) * ATS_K + key] = v.y;
            tile[(ds * 4 + 2) * ATS_K + key] = v.z;
            tile[(ds * 4 + 3) * ATS_K + key] = v.w;
        }
        __syncthreads();
        float s[4][2] = {{0.f,0.f},{0.f,0.f},{0.f,0.f},{0.f,0.f}};
#pragma unroll 4
        for (int d4 = 0; d4 < 16; d4++) {
            float4 q0v = *(const float4*)&qs[rb + 0][d4 * 4];
            float4 q1v = *(const float4*)&qs[rb + 1][d4 * 4];
            float4 q2v = *(const float4*)&qs[rb + 2][d4 * 4];
            float4 q3v = *(const float4*)&qs[rb + 3][d4 * 4];
            const float* qa[4] = {(float*)&q0v, (float*)&q1v, (float*)&q2v, (float*)&q3v};
#pragma unroll
            for (int dd = 0; dd < 4; dd++) {
                float2 t = *(const float2*)&tile[(d4 * 4 + dd) * ATS_K + k0];
#pragma unroll
                for (int r = 0; r < 4; r++) {
                    s[r][0] += qa[r][dd] * t.x;
                    s[r][1] += qa[r][dd] * t.y;
                }
            }
        }
#pragma unroll
        for (int r = 0; r < 4; r++) {
            sc[rb + r][kt * 64 + k0]     = s[r][0];
            sc[rb + r][kt * 64 + k0 + 1] = s[r][1];
        }
    }

    float inv[4];
#pragma unroll
    for (int rr = 0; rr < 4; rr++) {
        int r = rb + rr;
        float m = -1e30f;
        for (int i = lane; i < 1024; i += 32) m = fmaxf(m, sc[r][i]);
#pragma unroll
        for (int off = 16; off; off >>= 1) m = fmaxf(m, __shfl_xor_sync(0xffffffffu, m, off));
        float sum = 0.f;
        for (int i = lane; i < 1024; i += 32) {
            float p = __expf(sc[r][i] - m);
            sc[r][i] = p;
            sum += p;
        }
#pragma unroll
        for (int off = 16; off; off >>= 1) sum += __shfl_xor_sync(0xffffffffu, sum, off);
        inv[rr] = 1.0f / sum;
    }

    int d0 = lane, d1 = lane + 32;
    float a[4][2] = {{0.f,0.f},{0.f,0.f},{0.f,0.f},{0.f,0.f}};
    for (int vt = 0; vt < 16; vt++) {
        __syncthreads();
        for (int i4 = tid; i4 < 1024; i4 += 128) {
            int key = i4 >> 4, ds = i4 & 15;
            float4 v = *(const float4*)(qkv + (size_t)(b * SEQ + vt * 64 + key) * D3 + 2 * DM + hoff + ds * 4);
            *(float4*)&tile[key * ATS_V + ds * 4] = v;
        }
        __syncthreads();
#pragma unroll 4
        for (int k4 = 0; k4 < 16; k4++) {
            float4 p0v = *(const float4*)&sc[rb + 0][vt * 64 + k4 * 4];
            float4 p1v = *(const float4*)&sc[rb + 1][vt * 64 + k4 * 4];
            float4 p2v = *(const float4*)&sc[rb + 2][vt * 64 + k4 * 4];
            float4 p3v = *(const float4*)&sc[rb + 3][vt * 64 + k4 * 4];
            const float* pa[4] = {(float*)&p0v, (float*)&p1v, (float*)&p2v, (float*)&p3v};
#pragma unroll
            for (int kk = 0; kk < 4; kk++) {
                int key = k4 * 4 + kk;
                float v0 = tile[key * ATS_V + d0];
                float v1 = tile[key * ATS_V + d1];
#pragma unroll
                for (int r = 0; r < 4; r++) {
                    a[r][0] += pa[r][kk] * v0;
                    a[r][1] += pa[r][kk] * v1;
                }
            }
        }
    }
    size_t base = (size_t)(b * SEQ + q0 + rb) * DM + hoff;
#pragma unroll
    for (int rr = 0; rr < 4; rr++) {
        float r0 = a[rr][0] * inv[rr], r1 = a[rr][1] * inv[rr];
        __half h0 = __float2half_rn(r0);
        __half h1 = __float2half_rn(r1);
        oh[base + rr * DM + d0] = h0;
        oh[base + rr * DM + d1] = h1;
        ol[base + rr * DM + d0] = __float2half_rn(r0 - __half2float(h0));
        ol[base + rr * DM + d1] = __float2half_rn(r1 - __half2float(h1));
    }
}

// ============================ LN / router / combine / lb ============================
__device__ __forceinline__ float blk_sum(float v, float* red) {
    int tid = threadIdx.x;
    red[tid] = v;
    __syncthreads();
#pragma unroll
    for (int s = 128; s > 0; s >>= 1) {
        if (tid < s) red[tid] += red[tid + s];
        __syncthreads();
    }
    float r = red[0];
    __syncthreads();
    return r;
}

// x1 = LN(a + b); also writes fp16 hi/lo split of x1
__global__ __launch_bounds__(256) void add_ln_split_kernel(
    const float* __restrict__ a, const float* __restrict__ b,
    const float* __restrict__ g, const float* __restrict__ bb,
    float* __restrict__ out,
    __half* __restrict__ oh, __half* __restrict__ ol)
{
    __shared__ float red[256];
    size_t t = blockIdx.x;
    int tid = threadIdx.x;
    float v[4];
    float s = 0.f;
#pragma unroll
    for (int i = 0; i < 4; i++) {
        int d = tid + i * 256;
        v[i] = a[t * DM + d] + b[t * DM + d];
        s += v[i];
    }
    float mu = blk_sum(s, red) * (1.0f / DM);
    float sq = 0.f;
#pragma unroll
    for (int i = 0; i < 4; i++) { float c = v[i] - mu; sq += c * c; }
    float var = blk_sum(sq, red) * (1.0f / DM);
    float rstd = rsqrtf(var + 1e-5f);
#pragma unroll
    for (int i = 0; i < 4; i++) {
        int d = tid + i * 256;
        float y = (v[i] - mu) * rstd * g[d] + bb[d];
        out[t * DM + d] = y;
        __half hi = __float2half_rn(y);
        oh[t * DM + d] = hi;
        ol[t * DM + d] = __float2half_rn(y - __half2float(hi));
    }
}

__global__ __launch_bounds__(256) void router_kernel(
    const float* __restrict__ x1, const float* __restrict__ rw,
    const float* __restrict__ rb)
{
    __shared__ float logits[NEXP];
    size_t t = blockIdx.x;
    int tid = threadIdx.x;
    int w = tid >> 5, lane = tid & 31;
    if (w < NEXP) {
        float s = 0.f;
        for (int k = lane; k < DM; k += 32)
            s += x1[t * DM + k] * rw[(size_t)w * DM + k];
#pragma unroll
        for (int off = 16; off; off >>= 1) s += __shfl_xor_sync(0xffffffffu, s, off);
        if (lane == 0) logits[w] = s + rb[w];
    }
    __syncthreads();
    if (tid == 0) {
        float p[NEXP];
        float mx = logits[0];
#pragma unroll
        for (int e = 1; e < NEXP; e++) mx = fmaxf(mx, logits[e]);
        float sum = 0.f;
#pragma unroll
        for (int e = 0; e < NEXP; e++) { p[e] = expf(logits[e] - mx); sum += p[e]; }
        float invs = 1.0f / sum;
#pragma unroll
        for (int e = 0; e < NEXP; e++) {
            p[e] *= invs;
            atomicAdd(&d_Psum[e], p[e]);
        }
        int i0 = 0;
#pragma unroll
        for (int e = 1; e < NEXP; e++) if (p[e] > p[i0]) i0 = e;
        int i1 = (i0 == 0) ? 1 : 0;
#pragma unroll
        for (int e = 0; e < NEXP; e++) if (e != i0 && p[e] > p[i1]) i1 = e;
        float gsum = p[i0] + p[i1];

        int pos0 = atomicAdd(&d_count[i0], 1);
        d_list[i0 * TOK + pos0] = (int)t;
        d_slot[t * 2 + 0] = i0 * TOK + pos0;
        d_gate[t * 2 + 0] = p[i0] / gsum;

        int pos1 = atomicAdd(&d_count[i1], 1);
        d_list[i1 * TOK + pos1] = (int)t;
        d_slot[t * 2 + 1] = i1 * TOK + pos1;
        d_gate[t * 2 + 1] = p[i1] / gsum;
    }
}

__global__ __launch_bounds__(256) void combine_ln_kernel(
    const float* __restrict__ Y, const float* __restrict__ x1,
    const float* __restrict__ g, const float* __restrict__ bb,
    float* __restrict__ out)
{
    __shared__ float red[256];
    size_t t = blockIdx.x;
    int tid = threadIdx.x;
    int sl0 = d_slot[t * 2 + 0], sl1 = d_slot[t * 2 + 1];
    size_t r0 = (size_t)d_off[sl0 / TOK] + (sl0 % TOK);
    size_t r1 = (size_t)d_off[sl1 / TOK] + (sl1 % TOK);
    float g0 = d_gate[t * 2 + 0], g1 = d_gate[t * 2 + 1];
    float v[4];
    float s = 0.f;
#pragma unroll
    for (int i = 0; i < 4; i++) {
        int d = tid + i * 256;
        float y = g0 * Y[r0 * DM + d] + g1 * Y[r1 * DM + d];
        v[i] = x1[t * DM + d] + y;
        s += v[i];
    }
    float mu = blk_sum(s, red) * (1.0f / DM);
    float sq = 0.f;
#pragma unroll
    for (int i = 0; i < 4; i++) { float c = v[i] - mu; sq += c * c; }
    float var = blk_sum(sq, red) * (1.0f / DM);
    float rstd = rsqrtf(var + 1e-5f);
#pragma unroll
    for (int i = 0; i < 4; i++) {
        int d = tid + i * 256;
        out[t * DM + d] = (v[i] - mu) * rstd * g[d] + bb[d];
    }
}

__global__ void lb_kernel(float* __restrict__ out, int out_size) {
    if (out_size > TOK * DM) {
        float lb = 0.f;
#pragma unroll
        for (int e = 0; e < NEXP; e++) {
            float f = (float)d_count[e] / (float)(TOK * 2);
            float P = d_Psum[e] / (float)TOK;
            lb += f * P;
        }
        out[out_size - 1] = (float)NEXP * lb;
    }
}

// ============================ launch ============================
extern "C" void kernel_launch(void* const* d_in, const int* in_sizes, int n_in,
                              void* d_out, int out_size)
{
    const float* src   = (const float*)d_in[0];
    const float* in_w  = (const float*)d_in[1];
    const float* in_b  = (const float*)d_in[2];
    const float* out_w = (const float*)d_in[3];
    const float* out_b = (const float*)d_in[4];
    const float* ln1g  = (const float*)d_in[5];
    const float* ln1b  = (const float*)d_in[6];
    const float* rw    = (const float*)d_in[7];
    const float* rb    = (const float*)d_in[8];
    const float* w1    = (const float*)d_in[9];
    const float* b1    = (const float*)d_in[10];
    const float* w2    = (const float*)d_in[11];
    const float* b2    = (const float*)d_in[12];
    const float* ln2g  = (const float*)d_in[13];
    const float* ln2b  = (const float*)d_in[14];
    float* out = (float*)d_out;

#define GETP(T, sym) ({ void* _p; cudaGetSymbolAddress(&_p, sym); (T*)_p; })
    float* qkv  = GETP(float, g_qkv);
    float* proj = GETP(float, g_proj);
    float* x1   = GETP(float, g_x1);
    float* Y    = GETP(float, g_Y);
    __half* srch  = GETP(__half, g_srch);
    __half* srcl  = GETP(__half, g_srcl);
    __half* attnh = GETP(__half, g_attnh);
    __half* attnl = GETP(__half, g_attnl);
    __half* wqkv  = GETP(__half, g_wqkv);
    __half* wo    = GETP(__half, g_wo);
    __half* x1h = GETP(__half, g_x1h);
    __half* x1l = GETP(__half, g_x1l);
    __half* w1t = GETP(__half, g_w1t);
    __half* w2t = GETP(__half, g_w2t);
    __half* Hh  = GETP(__half, g_Hh);
    __half* Hl  = GETP(__half, g_Hl);
    int* cnt  = GETP(int, d_count);
    int* offp = GETP(int, d_off);
    int* list = GETP(int, d_list);

    static bool attr_done = false;
    if (!attr_done) {
        cudaFuncSetAttribute(hgemm<0>, cudaFuncAttributeMaxDynamicSharedMemorySize, MOE_SMEM);
        cudaFuncSetAttribute(hgemm<1>, cudaFuncAttributeMaxDynamicSharedMemorySize, MOE_SMEM);
        cudaFuncSetAttribute(hgemm<2>, cudaFuncAttributeMaxDynamicSharedMemorySize, MOE_SMEM);
        cudaFuncSetAttribute(attn_kernel, cudaFuncAttributeMaxDynamicSharedMemorySize, ATTN_SMEM);
        attr_done = true;
    }

    init_kernel<<<1, 32>>>();

    // conversions (src + weights)
    split_cvt_h_kernel<<<(TOK * DM / 4 + 255) / 256, 256>>>(src, srch, srcl, TOK * DM / 4);
    cvt_h_kernel<<<(D3 * DM / 4 + 255) / 256, 256>>>(in_w, wqkv, D3 * DM / 4);
    cvt_h_kernel<<<(DM * DM / 4 + 255) / 256, 256>>>(out_w, wo, DM * DM / 4);
    transpose_half_kernel<<<dim3(DFF / 32, DM / 32, NEXP), dim3(32, 8)>>>(w1, w1t, DM, DFF);
    transpose_half_kernel<<<dim3(DM / 32, DFF / 32, NEXP), dim3(32, 8)>>>(w2, w2t, DFF, DM);

    // QKV = src @ in_w^T + b (fp16 2-term)
    hgemm<0><<<dim3(D3 / BN, TOK / BM), 256, MOE_SMEM>>>(
        srch, srcl, wqkv, in_b, qkv, nullptr, nullptr,
        nullptr, nullptr, nullptr, TOK, D3, DM);

    // attention (writes fp16 split)
    attn_kernel<<<dim3(NB * NHEAD, SEQ / 16), 128, ATTN_SMEM>>>(qkv, attnh, attnl);

    // proj = attn @ out_w^T + b (fp16 2-term)
    hgemm<0><<<dim3(DM / BN, TOK / BM), 256, MOE_SMEM>>>(
        attnh, attnl, wo, out_b, proj, nullptr, nullptr,
        nullptr, nullptr, nullptr, TOK, DM, DM);

    // x1 = LN(src + proj), with fused fp16 split
    add_ln_split_kernel<<<TOK, 256>>>(src, proj, ln1g, ln1b, x1, x1h, x1l);

    router_kernel<<<TOK, 256>>>(x1, rw, rb);
    offsets_kernel<<<1, 32>>>();

    // H = relu(gather(x1) @ w1 + b1)  [fp16 2-term, fp16-split out]
    hgemm<1><<<dim3(DFF / BN, TOK / BM, NEXP), 256, MOE_SMEM>>>(
        x1h, x1l, w1t, b1, nullptr, Hh, Hl, cnt, offp, list, 0, DFF, DM);
    // Y = H @ w2 + b2  [fp16 2-term, fp32 out]
    hgemm<2><<<dim3(DM / BN, TOK / BM, NEXP), 256, MOE_SMEM>>>(
        Hh, Hl, w2t, b2, Y, nullptr, nullptr, cnt, offp, nullptr, 0, DM, DFF);

    combine_ln_kernel<<<TOK, 256>>>(Y, x1, ln2g, ln2b, out);
    lb_kernel<<<1, 1>>>(out, out_size);
}

// round 8
// speedup vs baseline: 4.1496x; 1.2334x over previous
#include <cuda_runtime.h>
#include <cuda_bf16.h>
#include <cuda_fp16.h>
#include <cstdint>
#include <math.h>

// Problem constants
#define TOK   4096          // B*S
#define DM    1024          // d_model
#define D3    3072          // 3*d_model
#define NHEAD 16
#define DH    64
#define DFF   4096
#define NEXP  8
#define SEQ   1024
#define NB    4
#define TOTROWS (2*TOK)     // packed expert rows (top-2)

// ============================ scratch globals ============================
__device__ __align__(16) float g_qkv[(size_t)TOK * D3];
__device__ __align__(16) float g_proj[(size_t)TOK * DM];
__device__ __align__(16) float g_x1[(size_t)TOK * DM];
__device__ __align__(16) float g_Y[(size_t)TOTROWS * DM];

__device__ __align__(16) __half g_srch[(size_t)TOK * DM];
__device__ __align__(16) __half g_attnh[(size_t)TOK * DM];
__device__ __align__(16) __half g_wqkv[(size_t)D3 * DM];
__device__ __align__(16) __half g_wo[(size_t)DM * DM];
__device__ __align__(16) __half g_x1h[(size_t)TOK * DM];
__device__ __align__(16) __half g_w1t[(size_t)NEXP * DFF * DM];
__device__ __align__(16) __half g_w2t[(size_t)NEXP * DM * DFF];
__device__ __align__(16) __half g_Hh[(size_t)TOTROWS * DFF];

__device__ int   d_count[NEXP];
__device__ int   d_off[NEXP];
__device__ float d_Psum[NEXP];
__device__ int   d_list[NEXP * TOK];
__device__ int   d_slot[TOK * 2];
__device__ float d_gate[TOK * 2];

// ============================ PTX helpers (sm_80-level only) =================
__device__ __forceinline__ uint32_t smem_u32(const void* p) {
    uint32_t a;
    asm("{ .reg .u64 t; cvta.to.shared.u64 t, %1; cvt.u32.u64 %0, t; }"
        : "=r"(a) : "l"(p));
    return a;
}
__device__ __forceinline__ void cp16(uint32_t dst, const void* src, int sz) {
    asm volatile("cp.async.cg.shared.global [%0], [%1], 16, %2;"
                 :: "r"(dst), "l"(src), "r"(sz) : "memory");
}
#define CP_COMMIT() asm volatile("cp.async.commit_group;" ::: "memory")
template<int N_>
__device__ __forceinline__ void cp_wait() {
    asm volatile("cp.async.wait_group %0;" :: "n"(N_) : "memory");
}
__device__ __forceinline__ void ldsm4(uint32_t* r, uint32_t addr) {
    asm volatile("ldmatrix.sync.aligned.m8n8.x4.shared.b16 {%0,%1,%2,%3}, [%4];"
                 : "=r"(r[0]), "=r"(r[1]), "=r"(r[2]), "=r"(r[3]) : "r"(addr));
}
__device__ __forceinline__ void mma16816h(float* c, const uint32_t* a, const uint32_t* b) {
    asm volatile("mma.sync.aligned.m16n8k16.row.col.f32.f16.f16.f32 "
                 "{%0,%1,%2,%3}, {%4,%5,%6,%7}, {%8,%9}, {%0,%1,%2,%3};"
                 : "+f"(c[0]), "+f"(c[1]), "+f"(c[2]), "+f"(c[3])
                 : "r"(a[0]), "r"(a[1]), "r"(a[2]), "r"(a[3]),
                   "r"(b[0]), "r"(b[1]));
}

// ============================ unified fp16 GEMM (single-term, BK=64) =========
// C = A[M,K] @ B[N,K]^T + bias.
// MODE 0: dense (M=Mfix), fp32 out.
// MODE 1: expert gather A rows via list, relu, fp16 out.
// MODE 2: expert offset A rows, fp32 out.
// stage: A 128 rows x 128B (seg^row swizzle), B 128 rows x 128B. 3 stages.
#define BM 128
#define BN 128
#define MBK 64
#define HA_BYTES 16384
#define HSTG_BYTES 32768
#define HNSTG 3
#define HGEMM_SMEM (HNSTG * HSTG_BYTES)

template<int MODE>
__global__ __launch_bounds__(256, 2) void hgemm(
    const __half* __restrict__ AH, const __half* __restrict__ BH,
    const float* __restrict__ biasBase,
    float* __restrict__ Cf, __half* __restrict__ CH,
    const int* __restrict__ counts, const int* __restrict__ offs,
    const int* __restrict__ listBase,
    int Mfix, int N, int K)
{
    extern __shared__ __half smh[];
    const int tid = threadIdx.x;
    const int lane = tid & 31, wid = tid >> 5;
    const int wm = wid & 3, wn = wid >> 2;
    const int g = lane >> 2, tig = lane & 3;
    const int m0 = blockIdx.y * BM, n0 = blockIdx.x * BN;
    const int e = blockIdx.z;

    int M = Mfix;
    const __half* bhp = BH;
    const float* bias = biasBase;
    const int* lst = nullptr;
    int arow0 = 0, crow0 = 0;
    if (MODE == 1) {
        M = counts[e];
        bhp += (size_t)e * N * K;
        bias += (size_t)e * N;
        lst = listBase + e * TOK;
        crow0 = offs[e];
    } else if (MODE == 2) {
        M = counts[e];
        bhp += (size_t)e * N * K;
        bias += (size_t)e * N;
        arow0 = offs[e]; crow0 = offs[e];
    }
    if (m0 >= M) return;

    const uint32_t sb = smem_u32(smh);

    float acc[2][8][4];
#pragma unroll
    for (int mt = 0; mt < 2; mt++)
#pragma unroll
        for (int nt = 0; nt < 8; nt++)
#pragma unroll
            for (int i = 0; i < 4; i++) acc[mt][nt][i] = 0.0f;

    auto load_stage = [&](int st, int k0) {
        uint32_t sbase = sb + st * HSTG_BYTES;
#pragma unroll
        for (int i = 0; i < 8; i++) {
            int u = tid + i * 256;              // 0..2047
            int isB = u >> 10;
            int idx = u & 1023;
            int row = idx >> 3, seg = idx & 7;
            uint32_t dst = sbase + isB * HA_BYTES + row * 128
                         + (uint32_t)((seg ^ (row & 7)) << 4);
            if (!isB) {
                int gr = m0 + row;
                size_t arow; int sz;
                if (MODE == 0) {
                    arow = (size_t)gr; sz = 16;
                } else if (MODE == 1) {
                    bool ok = gr < M;
                    arow = ok ? (size_t)lst[gr] : 0; sz = ok ? 16 : 0;
                } else {
                    bool ok = gr < M;
                    arow = (size_t)(arow0 + (ok ? gr : 0)); sz = ok ? 16 : 0;
                }
                cp16(dst, AH + arow * (size_t)K + k0 + seg * 8, sz);
            } else {
                cp16(dst, bhp + (size_t)(n0 + row) * K + k0 + seg * 8, 16);
            }
        }
    };

    const int a_row_in = (lane & 15);
    const int a_seg_in = (lane >> 4);
    const int b_row_in = (lane & 7) + ((lane & 16) ? 8 : 0);
    const int b_seg_in = (lane & 8) ? 1 : 0;

    auto compute = [&](int st) {
        uint32_t sA = sb + st * HSTG_BYTES;
        uint32_t sB = sA + HA_BYTES;
#pragma unroll
        for (int ks = 0; ks < 4; ks++) {
            const int kseg = ks * 2;
            uint32_t ah[2][4];
#pragma unroll
            for (int mt = 0; mt < 2; mt++) {
                int row = wm * 32 + mt * 16 + a_row_in;
                int sl = kseg + a_seg_in;
                ldsm4(ah[mt], sA + row * 128 + ((sl ^ (row & 7)) << 4));
            }
#pragma unroll
            for (int ntp = 0; ntp < 4; ntp++) {
                int row = wn * 64 + ntp * 16 + b_row_in;
                int sl = kseg + b_seg_in;
                uint32_t bh[4];
                ldsm4(bh, sB + row * 128 + ((sl ^ (row & 7)) << 4));
#pragma unroll
                for (int half = 0; half < 2; half++) {
                    int nt = ntp * 2 + half;
#pragma unroll
                    for (int mt = 0; mt < 2; mt++)
                        mma16816h(acc[mt][nt], ah[mt], bh + half * 2);
                }
            }
        }
    };

    const int nk = K / MBK;   // >= 16
    load_stage(0, 0);
    CP_COMMIT();
    load_stage(1, MBK);
    CP_COMMIT();
    for (int c = 0; c < nk; c++) {
        cp_wait<1>();
        __syncthreads();
        compute(c % HNSTG);
        int cn = c + 2;
        if (cn < nk) load_stage(cn % HNSTG, cn * MBK);
        CP_COMMIT();
    }

#pragma unroll
    for (int nt = 0; nt < 8; nt++) {
        int col = n0 + wn * 64 + nt * 8 + 2 * tig;
        float b0 = bias[col], b1 = bias[col + 1];
#pragma unroll
        for (int mt = 0; mt < 2; mt++) {
            int r0 = m0 + wm * 32 + mt * 16 + g;
            float* c = acc[mt][nt];
#pragma unroll
            for (int hh = 0; hh < 2; hh++) {
                int r = r0 + hh * 8;
                if (MODE == 0 || r < M) {
                    float v0 = c[hh * 2 + 0] + b0;
                    float v1 = c[hh * 2 + 1] + b1;
                    size_t o = (size_t)(crow0 + r) * N + col;
                    if (MODE == 1) {
                        v0 = fmaxf(v0, 0.0f); v1 = fmaxf(v1, 0.0f);
                        *(__half2*)(CH + o) = __halves2half2(
                            __float2half_rn(v0), __float2half_rn(v1));
                    } else {
                        *(float2*)(Cf + o) = make_float2(v0, v1);
                    }
                }
            }
        }
    }
}

// ============================ small kernels ============================
__global__ void init_kernel() {
    int i = threadIdx.x;
    if (i < NEXP) { d_count[i] = 0; d_Psum[i] = 0.0f; }
}

__global__ void offsets_kernel() {
    if (threadIdx.x == 0) {
        int a = 0;
#pragma unroll
        for (int e = 0; e < NEXP; e++) { d_off[e] = a; a += d_count[e]; }
    }
}

// fp32 -> fp16
__global__ __launch_bounds__(256) void cvt_h_kernel(
    const float* __restrict__ x, __half* __restrict__ h, int n4)
{
    int i = blockIdx.x * 256 + threadIdx.x;
    if (i >= n4) return;
    float4 v = ((const float4*)x)[i];
    __half hv[4] = {__float2half_rn(v.x), __float2half_rn(v.y),
                    __float2half_rn(v.z), __float2half_rn(v.w)};
    *(uint2*)(h + i * 4) = *(uint2*)hv;
}

// per-expert transpose to fp16: W[e][K][N] -> T[e][N][K]
__global__ __launch_bounds__(256) void transpose_half_kernel(
    const float* __restrict__ W, __half* __restrict__ Th, int K, int N)
{
    __shared__ float t[32][33];
    int e = blockIdx.z;
    const float* w = W + (size_t)e * K * N;
    __half* th = Th + (size_t)e * N * K;
    int n0 = blockIdx.x * 32, k0 = blockIdx.y * 32;
    int x = threadIdx.x, y = threadIdx.y;
#pragma unroll
    for (int i = 0; i < 32; i += 8)
        t[y + i][x] = w[(size_t)(k0 + y + i) * N + n0 + x];
    __syncthreads();
#pragma unroll
    for (int i = 0; i < 32; i += 8)
        th[(size_t)(n0 + y + i) * K + k0 + x] = __float2half_rn(t[x][y + i]);
}

// ============================ attention ============================
#define ATS_K 66
#define ATS_V 68
#define TILE_FLOATS (64 * ATS_V)
#define ATTN_SMEM ((TILE_FLOATS + 16 * 1024 + 16 * 64) * 4)

__global__ __launch_bounds__(128) void attn_kernel(
    const float* __restrict__ qkv, __half* __restrict__ oh)
{
    extern __shared__ float sm[];
    float* tile = sm;
    float (*sc)[1024] = (float(*)[1024])(sm + TILE_FLOATS);
    float (*qs)[64]   = (float(*)[64])(sm + TILE_FLOATS + 16 * 1024);

    int bh = blockIdx.x;
    int b = bh >> 4, h = bh & 15;
    int tid = threadIdx.x, w = tid >> 5, lane = tid & 31;
    int q0 = blockIdx.y * 16;
    int hoff = h * DH;
    int rb = w * 4;

    for (int i4 = tid; i4 < 256; i4 += 128) {
        int r = i4 >> 4, ds = i4 & 15;
        float4 v = *(const float4*)(qkv + (size_t)(b * SEQ + q0 + r) * D3 + hoff + ds * 4);
        float4* dst = (float4*)&qs[r][ds * 4];
        *dst = make_float4(v.x * 0.125f, v.y * 0.125f, v.z * 0.125f, v.w * 0.125f);
    }

    int k0 = 2 * lane;
    for (int kt = 0; kt < 16; kt++) {
        __syncthreads();
        for (int i4 = tid; i4 < 1024; i4 += 128) {
            int key = i4 >> 4, ds = i4 & 15;
            float4 v = *(const float4*)(qkv + (size_t)(b * SEQ + kt * 64 + key) * D3 + DM + hoff + ds * 4);
            tile[(ds * 4 + 0) * ATS_K + key] = v.x;
            tile[(ds * 4 + 1) * ATS_K + key] = v.y;
            tile[(ds * 4 + 2) * ATS_K + key] = v.z;
            tile[(ds * 4 + 3) * ATS_K + key] = v.w;
        }
        __syncthreads();
        float s[4][2] = {{0.f,0.f},{0.f,0.f},{0.f,0.f},{0.f,0.f}};
#pragma unroll 4
        for (int d4 = 0; d4 < 16; d4++) {
            float4 q0v = *(const float4*)&qs[rb + 0][d4 * 4];
            float4 q1v = *(const float4*)&qs[rb + 1][d4 * 4];
            float4 q2v = *(const float4*)&qs[rb + 2][d4 * 4];
            float4 q3v = *(const float4*)&qs[rb + 3][d4 * 4];
            const float* qa[4] = {(float*)&q0v, (float*)&q1v, (float*)&q2v, (float*)&q3v};
#pragma unroll
            for (int dd = 0; dd < 4; dd++) {
                float2 t = *(const float2*)&tile[(d4 * 4 + dd) * ATS_K + k0];
#pragma unroll
                for (int r = 0; r < 4; r++) {
                    s[r][0] += qa[r][dd] * t.x;
                    s[r][1] += qa[r][dd] * t.y;
                }
            }
        }
#pragma unroll
        for (int r = 0; r < 4; r++) {
            sc[rb + r][kt * 64 + k0]     = s[r][0];
            sc[rb + r][kt * 64 + k0 + 1] = s[r][1];
        }
    }

    float inv[4];
#pragma unroll
    for (int rr = 0; rr < 4; rr++) {
        int r = rb + rr;
        float m = -1e30f;
        for (int i = lane; i < 1024; i += 32) m = fmaxf(m, sc[r][i]);
#pragma unroll
        for (int off = 16; off; off >>= 1) m = fmaxf(m, __shfl_xor_sync(0xffffffffu, m, off));
        float sum = 0.f;
        for (int i = lane; i < 1024; i += 32) {
            float p = __expf(sc[r][i] - m);
            sc[r][i] = p;
            sum += p;
        }
#pragma unroll
        for (int off = 16; off; off >>= 1) sum += __shfl_xor_sync(0xffffffffu, sum, off);
        inv[rr] = 1.0f / sum;
    }

    int d0 = lane, d1 = lane + 32;
    float a[4][2] = {{0.f,0.f},{0.f,0.f},{0.f,0.f},{0.f,0.f}};
    for (int vt = 0; vt < 16; vt++) {
        __syncthreads();
        for (int i4 = tid; i4 < 1024; i4 += 128) {
            int key = i4 >> 4, ds = i4 & 15;
            float4 v = *(const float4*)(qkv + (size_t)(b * SEQ + vt * 64 + key) * D3 + 2 * DM + hoff + ds * 4);
            *(float4*)&tile[key * ATS_V + ds * 4] = v;
        }
        __syncthreads();
#pragma unroll 4
        for (int k4 = 0; k4 < 16; k4++) {
            float4 p0v = *(const float4*)&sc[rb + 0][vt * 64 + k4 * 4];
            float4 p1v = *(const float4*)&sc[rb + 1][vt * 64 + k4 * 4];
            float4 p2v = *(const float4*)&sc[rb + 2][vt * 64 + k4 * 4];
            float4 p3v = *(const float4*)&sc[rb + 3][vt * 64 + k4 * 4];
            const float* pa[4] = {(float*)&p0v, (float*)&p1v, (float*)&p2v, (float*)&p3v};
#pragma unroll
            for (int kk = 0; kk < 4; kk++) {
                int key = k4 * 4 + kk;
                float v0 = tile[key * ATS_V + d0];
                float v1 = tile[key * ATS_V + d1];
#pragma unroll
                for (int r = 0; r < 4; r++) {
                    a[r][0] += pa[r][kk] * v0;
                    a[r][1] += pa[r][kk] * v1;
                }
            }
        }
    }
    size_t base = (size_t)(b * SEQ + q0 + rb) * DM + hoff;
#pragma unroll
    for (int rr = 0; rr < 4; rr++) {
        oh[base + rr * DM + d0] = __float2half_rn(a[rr][0] * inv[rr]);
        oh[base + rr * DM + d1] = __float2half_rn(a[rr][1] * inv[rr]);
    }
}

// ============================ LN / router / combine / lb ============================
__device__ __forceinline__ float blk_sum(float v, float* red) {
    int tid = threadIdx.x;
    red[tid] = v;
    __syncthreads();
#pragma unroll
    for (int s = 128; s > 0; s >>= 1) {
        if (tid < s) red[tid] += red[tid + s];
        __syncthreads();
    }
    float r = red[0];
    __syncthreads();
    return r;
}

// x1 = LN(a + b); also writes fp16 of x1
__global__ __launch_bounds__(256) void add_ln_split_kernel(
    const float* __restrict__ a, const float* __restrict__ b,
    const float* __restrict__ g, const float* __restrict__ bb,
    float* __restrict__ out, __half* __restrict__ oh)
{
    __shared__ float red[256];
    size_t t = blockIdx.x;
    int tid = threadIdx.x;
    float v[4];
    float s = 0.f;
#pragma unroll
    for (int i = 0; i < 4; i++) {
        int d = tid + i * 256;
        v[i] = a[t * DM + d] + b[t * DM + d];
        s += v[i];
    }
    float mu = blk_sum(s, red) * (1.0f / DM);
    float sq = 0.f;
#pragma unroll
    for (int i = 0; i < 4; i++) { float c = v[i] - mu; sq += c * c; }
    float var = blk_sum(sq, red) * (1.0f / DM);
    float rstd = rsqrtf(var + 1e-5f);
#pragma unroll
    for (int i = 0; i < 4; i++) {
        int d = tid + i * 256;
        float y = (v[i] - mu) * rstd * g[d] + bb[d];
        out[t * DM + d] = y;
        oh[t * DM + d] = __float2half_rn(y);
    }
}

__global__ __launch_bounds__(256) void router_kernel(
    const float* __restrict__ x1, const float* __restrict__ rw,
    const float* __restrict__ rb)
{
    __shared__ float logits[NEXP];
    size_t t = blockIdx.x;
    int tid = threadIdx.x;
    int w = tid >> 5, lane = tid & 31;
    if (w < NEXP) {
        float s = 0.f;
        for (int k = lane; k < DM; k += 32)
            s += x1[t * DM + k] * rw[(size_t)w * DM + k];
#pragma unroll
        for (int off = 16; off; off >>= 1) s += __shfl_xor_sync(0xffffffffu, s, off);
        if (lane == 0) logits[w] = s + rb[w];
    }
    __syncthreads();
    if (tid == 0) {
        float p[NEXP];
        float mx = logits[0];
#pragma unroll
        for (int e = 1; e < NEXP; e++) mx = fmaxf(mx, logits[e]);
        float sum = 0.f;
#pragma unroll
        for (int e = 0; e < NEXP; e++) { p[e] = expf(logits[e] - mx); sum += p[e]; }
        float invs = 1.0f / sum;
#pragma unroll
        for (int e = 0; e < NEXP; e++) {
            p[e] *= invs;
            atomicAdd(&d_Psum[e], p[e]);
        }
        int i0 = 0;
#pragma unroll
        for (int e = 1; e < NEXP; e++) if (p[e] > p[i0]) i0 = e;
        int i1 = (i0 == 0) ? 1 : 0;
#pragma unroll
        for (int e = 0; e < NEXP; e++) if (e != i0 && p[e] > p[i1]) i1 = e;
        float gsum = p[i0] + p[i1];

        int pos0 = atomicAdd(&d_count[i0], 1);
        d_list[i0 * TOK + pos0] = (int)t;
        d_slot[t * 2 + 0] = i0 * TOK + pos0;
        d_gate[t * 2 + 0] = p[i0] / gsum;

        int pos1 = atomicAdd(&d_count[i1], 1);
        d_list[i1 * TOK + pos1] = (int)t;
        d_slot[t * 2 + 1] = i1 * TOK + pos1;
        d_gate[t * 2 + 1] = p[i1] / gsum;
    }
}

__global__ __launch_bounds__(256) void combine_ln_kernel(
    const float* __restrict__ Y, const float* __restrict__ x1,
    const float* __restrict__ g, const float* __restrict__ bb,
    float* __restrict__ out)
{
    __shared__ float red[256];
    size_t t = blockIdx.x;
    int tid = threadIdx.x;
    int sl0 = d_slot[t * 2 + 0], sl1 = d_slot[t * 2 + 1];
    size_t r0 = (size_t)d_off[sl0 / TOK] + (sl0 % TOK);
    size_t r1 = (size_t)d_off[sl1 / TOK] + (sl1 % TOK);
    float g0 = d_gate[t * 2 + 0], g1 = d_gate[t * 2 + 1];
    float v[4];
    float s = 0.f;
#pragma unroll
    for (int i = 0; i < 4; i++) {
        int d = tid + i * 256;
        float y = g0 * Y[r0 * DM + d] + g1 * Y[r1 * DM + d];
        v[i] = x1[t * DM + d] + y;
        s += v[i];
    }
    float mu = blk_sum(s, red) * (1.0f / DM);
    float sq = 0.f;
#pragma unroll
    for (int i = 0; i < 4; i++) { float c = v[i] - mu; sq += c * c; }
    float var = blk_sum(sq, red) * (1.0f / DM);
    float rstd = rsqrtf(var + 1e-5f);
#pragma unroll
    for (int i = 0; i < 4; i++) {
        int d = tid + i * 256;
        out[t * DM + d] = (v[i] - mu) * rstd * g[d] + bb[d];
    }
}

__global__ void lb_kernel(float* __restrict__ out, int out_size) {
    if (out_size > TOK * DM) {
        float lb = 0.f;
#pragma unroll
        for (int e = 0; e < NEXP; e++) {
            float f = (float)d_count[e] / (float)(TOK * 2);
            float P = d_Psum[e] / (float)TOK;
            lb += f * P;
        }
        out[out_size - 1] = (float)NEXP * lb;
    }
}

// ============================ launch ============================
extern "C" void kernel_launch(void* const* d_in, const int* in_sizes, int n_in,
                              void* d_out, int out_size)
{
    const float* src   = (const float*)d_in[0];
    const float* in_w  = (const float*)d_in[1];
    const float* in_b  = (const float*)d_in[2];
    const float* out_w = (const float*)d_in[3];
    const float* out_b = (const float*)d_in[4];
    const float* ln1g  = (const float*)d_in[5];
    const float* ln1b  = (const float*)d_in[6];
    const float* rw    = (const float*)d_in[7];
    const float* rb    = (const float*)d_in[8];
    const float* w1    = (const float*)d_in[9];
    const float* b1    = (const float*)d_in[10];
    const float* w2    = (const float*)d_in[11];
    const float* b2    = (const float*)d_in[12];
    const float* ln2g  = (const float*)d_in[13];
    const float* ln2b  = (const float*)d_in[14];
    float* out = (float*)d_out;

#define GETP(T, sym) ({ void* _p; cudaGetSymbolAddress(&_p, sym); (T*)_p; })
    float* qkv  = GETP(float, g_qkv);
    float* proj = GETP(float, g_proj);
    float* x1   = GETP(float, g_x1);
    float* Y    = GETP(float, g_Y);
    __half* srch  = GETP(__half, g_srch);
    __half* attnh = GETP(__half, g_attnh);
    __half* wqkv  = GETP(__half, g_wqkv);
    __half* wo    = GETP(__half, g_wo);
    __half* x1h = GETP(__half, g_x1h);
    __half* w1t = GETP(__half, g_w1t);
    __half* w2t = GETP(__half, g_w2t);
    __half* Hh  = GETP(__half, g_Hh);
    int* cnt  = GETP(int, d_count);
    int* offp = GETP(int, d_off);
    int* list = GETP(int, d_list);

    static bool attr_done = false;
    if (!attr_done) {
        cudaFuncSetAttribute(hgemm<0>, cudaFuncAttributeMaxDynamicSharedMemorySize, HGEMM_SMEM);
        cudaFuncSetAttribute(hgemm<1>, cudaFuncAttributeMaxDynamicSharedMemorySize, HGEMM_SMEM);
        cudaFuncSetAttribute(hgemm<2>, cudaFuncAttributeMaxDynamicSharedMemorySize, HGEMM_SMEM);
        cudaFuncSetAttribute(attn_kernel, cudaFuncAttributeMaxDynamicSharedMemorySize, ATTN_SMEM);
        attr_done = true;
    }

    init_kernel<<<1, 32>>>();

    // conversions (src + weights)
    cvt_h_kernel<<<(TOK * DM / 4 + 255) / 256, 256>>>(src, srch, TOK * DM / 4);
    cvt_h_kernel<<<(D3 * DM / 4 + 255) / 256, 256>>>(in_w, wqkv, D3 * DM / 4);
    cvt_h_kernel<<<(DM * DM / 4 + 255) / 256, 256>>>(out_w, wo, DM * DM / 4);
    transpose_half_kernel<<<dim3(DFF / 32, DM / 32, NEXP), dim3(32, 8)>>>(w1, w1t, DM, DFF);
    transpose_half_kernel<<<dim3(DM / 32, DFF / 32, NEXP), dim3(32, 8)>>>(w2, w2t, DFF, DM);

    // QKV = src @ in_w^T + b
    hgemm<0><<<dim3(D3 / BN, TOK / BM), 256, HGEMM_SMEM>>>(
        srch, wqkv, in_b, qkv, nullptr, nullptr, nullptr, nullptr, TOK, D3, DM);

    // attention (writes fp16)
    attn_kernel<<<dim3(NB * NHEAD, SEQ / 16), 128, ATTN_SMEM>>>(qkv, attnh);

    // proj = attn @ out_w^T + b
    hgemm<0><<<dim3(DM / BN, TOK / BM), 256, HGEMM_SMEM>>>(
        attnh, wo, out_b, proj, nullptr, nullptr, nullptr, nullptr, TOK, DM, DM);

    // x1 = LN(src + proj), with fused fp16 cvt
    add_ln_split_kernel<<<TOK, 256>>>(src, proj, ln1g, ln1b, x1, x1h);

    router_kernel<<<TOK, 256>>>(x1, rw, rb);
    offsets_kernel<<<1, 32>>>();

    // H = relu(gather(x1) @ w1 + b1)  [fp16 out]
    hgemm<1><<<dim3(DFF / BN, TOK / BM, NEXP), 256, HGEMM_SMEM>>>(
        x1h, w1t, b1, nullptr, Hh, cnt, offp, list, 0, DFF, DM);
    // Y = H @ w2 + b2  [fp32 out]
    hgemm<2><<<dim3(DM / BN, TOK / BM, NEXP), 256, HGEMM_SMEM>>>(
        Hh, w2t, b2, Y, nullptr, cnt, offp, nullptr, 0, DM, DFF);

    combine_ln_kernel<<<TOK, 256>>>(Y, x1, ln2g, ln2b, out);
    lb_kernel<<<1, 1>>>(out, out_size);
}

// round 9
// speedup vs baseline: 4.2005x; 1.0123x over previous
#include <cuda_runtime.h>
#include <cuda_bf16.h>
#include <cuda_fp16.h>
#include <cstdint>
#include <math.h>

// Problem constants
#define TOK   4096          // B*S
#define DM    1024          // d_model
#define D3    3072          // 3*d_model
#define NHEAD 16
#define DH    64
#define DFF   4096
#define NEXP  8
#define SEQ   1024
#define NB    4
#define TOTROWS (2*TOK)     // packed expert rows (top-2)

// ============================ scratch globals ============================
__device__ __align__(16) float g_qkv[(size_t)TOK * D3];
__device__ __align__(16) float g_proj[(size_t)TOK * DM];
__device__ __align__(16) float g_x1[(size_t)TOK * DM];
__device__ __align__(16) float g_Y[(size_t)TOTROWS * DM];

__device__ __align__(16) __half g_srch[(size_t)TOK * DM];
__device__ __align__(16) __half g_attnh[(size_t)TOK * DM];
__device__ __align__(16) __half g_wqkv[(size_t)D3 * DM];
__device__ __align__(16) __half g_wo[(size_t)DM * DM];
__device__ __align__(16) __half g_x1h[(size_t)TOK * DM];
__device__ __align__(16) __half g_w1t[(size_t)NEXP * DFF * DM];
__device__ __align__(16) __half g_w2t[(size_t)NEXP * DM * DFF];
__device__ __align__(16) __half g_Hh[(size_t)TOTROWS * DFF];

__device__ int   d_count[NEXP];
__device__ int   d_off[NEXP];
__device__ float d_Psum[NEXP];
__device__ int   d_list[NEXP * TOK];
__device__ int   d_slot[TOK * 2];
__device__ float d_gate[TOK * 2];

// ============================ PTX helpers (sm_80-level only) =================
__device__ __forceinline__ uint32_t smem_u32(const void* p) {
    uint32_t a;
    asm("{ .reg .u64 t; cvta.to.shared.u64 t, %1; cvt.u32.u64 %0, t; }"
        : "=r"(a) : "l"(p));
    return a;
}
__device__ __forceinline__ void cp16(uint32_t dst, const void* src, int sz) {
    asm volatile("cp.async.cg.shared.global [%0], [%1], 16, %2;"
                 :: "r"(dst), "l"(src), "r"(sz) : "memory");
}
#define CP_COMMIT() asm volatile("cp.async.commit_group;" ::: "memory")
template<int N_>
__device__ __forceinline__ void cp_wait() {
    asm volatile("cp.async.wait_group %0;" :: "n"(N_) : "memory");
}
__device__ __forceinline__ void ldsm4(uint32_t* r, uint32_t addr) {
    asm volatile("ldmatrix.sync.aligned.m8n8.x4.shared.b16 {%0,%1,%2,%3}, [%4];"
                 : "=r"(r[0]), "=r"(r[1]), "=r"(r[2]), "=r"(r[3]) : "r"(addr));
}
__device__ __forceinline__ void mma16816h(float* c, const uint32_t* a, const uint32_t* b) {
    asm volatile("mma.sync.aligned.m16n8k16.row.col.f32.f16.f16.f32 "
                 "{%0,%1,%2,%3}, {%4,%5,%6,%7}, {%8,%9}, {%0,%1,%2,%3};"
                 : "+f"(c[0]), "+f"(c[1]), "+f"(c[2]), "+f"(c[3])
                 : "r"(a[0]), "r"(a[1]), "r"(a[2]), "r"(a[3]),
                   "r"(b[0]), "r"(b[1]));
}

// ============================ unified fp16 GEMM (single-term, BK=64) =========
#define BM 128
#define BN 128
#define MBK 64
#define HA_BYTES 16384
#define HSTG_BYTES 32768
#define HNSTG 3
#define HGEMM_SMEM (HNSTG * HSTG_BYTES)

template<int MODE>
__global__ __launch_bounds__(256, 2) void hgemm(
    const __half* __restrict__ AH, const __half* __restrict__ BH,
    const float* __restrict__ biasBase,
    float* __restrict__ Cf, __half* __restrict__ CH,
    const int* __restrict__ counts, const int* __restrict__ offs,
    const int* __restrict__ listBase,
    int Mfix, int N, int K)
{
    extern __shared__ __half smh[];
    const int tid = threadIdx.x;
    const int lane = tid & 31, wid = tid >> 5;
    const int wm = wid & 3, wn = wid >> 2;
    const int g = lane >> 2, tig = lane & 3;
    const int m0 = blockIdx.y * BM, n0 = blockIdx.x * BN;
    const int e = blockIdx.z;

    int M = Mfix;
    const __half* bhp = BH;
    const float* bias = biasBase;
    const int* lst = nullptr;
    int arow0 = 0, crow0 = 0;
    if (MODE == 1) {
        M = counts[e];
        bhp += (size_t)e * N * K;
        bias += (size_t)e * N;
        lst = listBase + e * TOK;
        crow0 = offs[e];
    } else if (MODE == 2) {
        M = counts[e];
        bhp += (size_t)e * N * K;
        bias += (size_t)e * N;
        arow0 = offs[e]; crow0 = offs[e];
    }
    if (m0 >= M) return;

    const uint32_t sb = smem_u32(smh);

    float acc[2][8][4];
#pragma unroll
    for (int mt = 0; mt < 2; mt++)
#pragma unroll
        for (int nt = 0; nt < 8; nt++)
#pragma unroll
            for (int i = 0; i < 4; i++) acc[mt][nt][i] = 0.0f;

    auto load_stage = [&](int st, int k0) {
        uint32_t sbase = sb + st * HSTG_BYTES;
#pragma unroll
        for (int i = 0; i < 8; i++) {
            int u = tid + i * 256;              // 0..2047
            int isB = u >> 10;
            int idx = u & 1023;
            int row = idx >> 3, seg = idx & 7;
            uint32_t dst = sbase + isB * HA_BYTES + row * 128
                         + (uint32_t)((seg ^ (row & 7)) << 4);
            if (!isB) {
                int gr = m0 + row;
                size_t arow; int sz;
                if (MODE == 0) {
                    arow = (size_t)gr; sz = 16;
                } else if (MODE == 1) {
                    bool ok = gr < M;
                    arow = ok ? (size_t)lst[gr] : 0; sz = ok ? 16 : 0;
                } else {
                    bool ok = gr < M;
                    arow = (size_t)(arow0 + (ok ? gr : 0)); sz = ok ? 16 : 0;
                }
                cp16(dst, AH + arow * (size_t)K + k0 + seg * 8, sz);
            } else {
                cp16(dst, bhp + (size_t)(n0 + row) * K + k0 + seg * 8, 16);
            }
        }
    };

    const int a_row_in = (lane & 15);
    const int a_seg_in = (lane >> 4);
    const int b_row_in = (lane & 7) + ((lane & 16) ? 8 : 0);
    const int b_seg_in = (lane & 8) ? 1 : 0;

    auto compute = [&](int st) {
        uint32_t sA = sb + st * HSTG_BYTES;
        uint32_t sB = sA + HA_BYTES;
#pragma unroll
        for (int ks = 0; ks < 4; ks++) {
            const int kseg = ks * 2;
            uint32_t ah[2][4];
#pragma unroll
            for (int mt = 0; mt < 2; mt++) {
                int row = wm * 32 + mt * 16 + a_row_in;
                int sl = kseg + a_seg_in;
                ldsm4(ah[mt], sA + row * 128 + ((sl ^ (row & 7)) << 4));
            }
#pragma unroll
            for (int ntp = 0; ntp < 4; ntp++) {
                int row = wn * 64 + ntp * 16 + b_row_in;
                int sl = kseg + b_seg_in;
                uint32_t bh[4];
                ldsm4(bh, sB + row * 128 + ((sl ^ (row & 7)) << 4));
#pragma unroll
                for (int half = 0; half < 2; half++) {
                    int nt = ntp * 2 + half;
#pragma unroll
                    for (int mt = 0; mt < 2; mt++)
                        mma16816h(acc[mt][nt], ah[mt], bh + half * 2);
                }
            }
        }
    };

    const int nk = K / MBK;
    load_stage(0, 0);
    CP_COMMIT();
    load_stage(1, MBK);
    CP_COMMIT();
    for (int c = 0; c < nk; c++) {
        cp_wait<1>();
        __syncthreads();
        compute(c % HNSTG);
        int cn = c + 2;
        if (cn < nk) load_stage(cn % HNSTG, cn * MBK);
        CP_COMMIT();
    }

#pragma unroll
    for (int nt = 0; nt < 8; nt++) {
        int col = n0 + wn * 64 + nt * 8 + 2 * tig;
        float b0 = bias[col], b1 = bias[col + 1];
#pragma unroll
        for (int mt = 0; mt < 2; mt++) {
            int r0 = m0 + wm * 32 + mt * 16 + g;
            float* c = acc[mt][nt];
#pragma unroll
            for (int hh = 0; hh < 2; hh++) {
                int r = r0 + hh * 8;
                if (MODE == 0 || r < M) {
                    float v0 = c[hh * 2 + 0] + b0;
                    float v1 = c[hh * 2 + 1] + b1;
                    size_t o = (size_t)(crow0 + r) * N + col;
                    if (MODE == 1) {
                        v0 = fmaxf(v0, 0.0f); v1 = fmaxf(v1, 0.0f);
                        *(__half2*)(CH + o) = __halves2half2(
                            __float2half_rn(v0), __float2half_rn(v1));
                    } else {
                        *(float2*)(Cf + o) = make_float2(v0, v1);
                    }
                }
            }
        }
    }
}

// ============================ small kernels ============================
__global__ void init_kernel() {
    int i = threadIdx.x;
    if (i < NEXP) { d_count[i] = 0; d_Psum[i] = 0.0f; }
}

__global__ void offsets_kernel() {
    if (threadIdx.x == 0) {
        int a = 0;
#pragma unroll
        for (int e = 0; e < NEXP; e++) { d_off[e] = a; a += d_count[e]; }
    }
}

// fp32 -> fp16
__global__ __launch_bounds__(256) void cvt_h_kernel(
    const float* __restrict__ x, __half* __restrict__ h, int n4)
{
    int i = blockIdx.x * 256 + threadIdx.x;
    if (i >= n4) return;
    float4 v = ((const float4*)x)[i];
    __half hv[4] = {__float2half_rn(v.x), __float2half_rn(v.y),
                    __float2half_rn(v.z), __float2half_rn(v.w)};
    *(uint2*)(h + i * 4) = *(uint2*)hv;
}

// per-expert transpose to fp16: W[e][K][N] -> T[e][N][K]
__global__ __launch_bounds__(256) void transpose_half_kernel(
    const float* __restrict__ W, __half* __restrict__ Th, int K, int N)
{
    __shared__ float t[32][33];
    int e = blockIdx.z;
    const float* w = W + (size_t)e * K * N;
    __half* th = Th + (size_t)e * N * K;
    int n0 = blockIdx.x * 32, k0 = blockIdx.y * 32;
    int x = threadIdx.x, y = threadIdx.y;
#pragma unroll
    for (int i = 0; i < 32; i += 8)
        t[y + i][x] = w[(size_t)(k0 + y + i) * N + n0 + x];
    __syncthreads();
#pragma unroll
    for (int i = 0; i < 32; i += 8)
        th[(size_t)(n0 + y + i) * K + k0 + x] = __float2half_rn(t[x][y + i]);
}

// ============================ attention ============================
#define ATS_K 66
#define ATS_V 68
#define TILE_FLOATS (64 * ATS_V)
#define ATTN_SMEM ((TILE_FLOATS + 16 * 1024 + 16 * 64) * 4)

__global__ __launch_bounds__(128) void attn_kernel(
    const float* __restrict__ qkv, __half* __restrict__ oh)
{
    extern __shared__ float sm[];
    float* tile = sm;
    float (*sc)[1024] = (float(*)[1024])(sm + TILE_FLOATS);
    float (*qs)[64]   = (float(*)[64])(sm + TILE_FLOATS + 16 * 1024);

    int bh = blockIdx.x;
    int b = bh >> 4, h = bh & 15;
    int tid = threadIdx.x, w = tid >> 5, lane = tid & 31;
    int q0 = blockIdx.y * 16;
    int hoff = h * DH;
    int rb = w * 4;

    for (int i4 = tid; i4 < 256; i4 += 128) {
        int r = i4 >> 4, ds = i4 & 15;
        float4 v = *(const float4*)(qkv + (size_t)(b * SEQ + q0 + r) * D3 + hoff + ds * 4);
        float4* dst = (float4*)&qs[r][ds * 4];
        *dst = make_float4(v.x * 0.125f, v.y * 0.125f, v.z * 0.125f, v.w * 0.125f);
    }

    int k0 = 2 * lane;
    for (int kt = 0; kt < 16; kt++) {
        __syncthreads();
        for (int i4 = tid; i4 < 1024; i4 += 128) {
            int key = i4 >> 4, ds = i4 & 15;
            float4 v = *(const float4*)(qkv + (size_t)(b * SEQ + kt * 64 + key) * D3 + DM + hoff + ds * 4);
            tile[(ds * 4 + 0) * ATS_K + key] = v.x;
            tile[(ds * 4 + 1) * ATS_K + key] = v.y;
            tile[(ds * 4 + 2) * ATS_K + key] = v.z;
            tile[(ds * 4 + 3) * ATS_K + key] = v.w;
        }
        __syncthreads();
        float s[4][2] = {{0.f,0.f},{0.f,0.f},{0.f,0.f},{0.f,0.f}};
#pragma unroll 4
        for (int d4 = 0; d4 < 16; d4++) {
            float4 q0v = *(const float4*)&qs[rb + 0][d4 * 4];
            float4 q1v = *(const float4*)&qs[rb + 1][d4 * 4];
            float4 q2v = *(const float4*)&qs[rb + 2][d4 * 4];
            float4 q3v = *(const float4*)&qs[rb + 3][d4 * 4];
            const float* qa[4] = {(float*)&q0v, (float*)&q1v, (float*)&q2v, (float*)&q3v};
#pragma unroll
            for (int dd = 0; dd < 4; dd++) {
                float2 t = *(const float2*)&tile[(d4 * 4 + dd) * ATS_K + k0];
#pragma unroll
                for (int r = 0; r < 4; r++) {
                    s[r][0] += qa[r][dd] * t.x;
                    s[r][1] += qa[r][dd] * t.y;
                }
            }
        }
#pragma unroll
        for (int r = 0; r < 4; r++) {
            sc[rb + r][kt * 64 + k0]     = s[r][0];
            sc[rb + r][kt * 64 + k0 + 1] = s[r][1];
        }
    }

    float inv[4];
#pragma unroll
    for (int rr = 0; rr < 4; rr++) {
        int r = rb + rr;
        float m = -1e30f;
        for (int i = lane; i < 1024; i += 32) m = fmaxf(m, sc[r][i]);
#pragma unroll
        for (int off = 16; off; off >>= 1) m = fmaxf(m, __shfl_xor_sync(0xffffffffu, m, off));
        float sum = 0.f;
        for (int i = lane; i < 1024; i += 32) {
            float p = __expf(sc[r][i] - m);
            sc[r][i] = p;
            sum += p;
        }
#pragma unroll
        for (int off = 16; off; off >>= 1) sum += __shfl_xor_sync(0xffffffffu, sum, off);
        inv[rr] = 1.0f / sum;
    }

    int d0 = lane, d1 = lane + 32;
    float a[4][2] = {{0.f,0.f},{0.f,0.f},{0.f,0.f},{0.f,0.f}};
    for (int vt = 0; vt < 16; vt++) {
        __syncthreads();
        for (int i4 = tid; i4 < 1024; i4 += 128) {
            int key = i4 >> 4, ds = i4 & 15;
            float4 v = *(const float4*)(qkv + (size_t)(b * SEQ + vt * 64 + key) * D3 + 2 * DM + hoff + ds * 4);
            *(float4*)&tile[key * ATS_V + ds * 4] = v;
        }
        __syncthreads();
#pragma unroll 4
        for (int k4 = 0; k4 < 16; k4++) {
            float4 p0v = *(const float4*)&sc[rb + 0][vt * 64 + k4 * 4];
            float4 p1v = *(const float4*)&sc[rb + 1][vt * 64 + k4 * 4];
            float4 p2v = *(const float4*)&sc[rb + 2][vt * 64 + k4 * 4];
            float4 p3v = *(const float4*)&sc[rb + 3][vt * 64 + k4 * 4];
            const float* pa[4] = {(float*)&p0v, (float*)&p1v, (float*)&p2v, (float*)&p3v};
#pragma unroll
            for (int kk = 0; kk < 4; kk++) {
                int key = k4 * 4 + kk;
                float v0 = tile[key * ATS_V + d0];
                float v1 = tile[key * ATS_V + d1];
#pragma unroll
                for (int r = 0; r < 4; r++) {
                    a[r][0] += pa[r][kk] * v0;
                    a[r][1] += pa[r][kk] * v1;
                }
            }
        }
    }
    size_t base = (size_t)(b * SEQ + q0 + rb) * DM + hoff;
#pragma unroll
    for (int rr = 0; rr < 4; rr++) {
        oh[base + rr * DM + d0] = __float2half_rn(a[rr][0] * inv[rr]);
        oh[base + rr * DM + d1] = __float2half_rn(a[rr][1] * inv[rr]);
    }
}

// ============================ LN / router / combine / lb ============================
__device__ __forceinline__ float blk_sum(float v, float* red) {
    int tid = threadIdx.x;
    red[tid] = v;
    __syncthreads();
#pragma unroll
    for (int s = 128; s > 0; s >>= 1) {
        if (tid < s) red[tid] += red[tid + s];
        __syncthreads();
    }
    float r = red[0];
    __syncthreads();
    return r;
}

__global__ __launch_bounds__(256) void add_ln_split_kernel(
    const float* __restrict__ a, const float* __restrict__ b,
    const float* __restrict__ g, const float* __restrict__ bb,
    float* __restrict__ out, __half* __restrict__ oh)
{
    __shared__ float red[256];
    size_t t = blockIdx.x;
    int tid = threadIdx.x;
    float v[4];
    float s = 0.f;
#pragma unroll
    for (int i = 0; i < 4; i++) {
        int d = tid + i * 256;
        v[i] = a[t * DM + d] + b[t * DM + d];
        s += v[i];
    }
    float mu = blk_sum(s, red) * (1.0f / DM);
    float sq = 0.f;
#pragma unroll
    for (int i = 0; i < 4; i++) { float c = v[i] - mu; sq += c * c; }
    float var = blk_sum(sq, red) * (1.0f / DM);
    float rstd = rsqrtf(var + 1e-5f);
#pragma unroll
    for (int i = 0; i < 4; i++) {
        int d = tid + i * 256;
        float y = (v[i] - mu) * rstd * g[d] + bb[d];
        out[t * DM + d] = y;
        oh[t * DM + d] = __float2half_rn(y);
    }
}

__global__ __launch_bounds__(256) void router_kernel(
    const float* __restrict__ x1, const float* __restrict__ rw,
    const float* __restrict__ rb)
{
    __shared__ float logits[NEXP];
    size_t t = blockIdx.x;
    int tid = threadIdx.x;
    int w = tid >> 5, lane = tid & 31;
    if (w < NEXP) {
        float s = 0.f;
        for (int k = lane; k < DM; k += 32)
            s += x1[t * DM + k] * rw[(size_t)w * DM + k];
#pragma unroll
        for (int off = 16; off; off >>= 1) s += __shfl_xor_sync(0xffffffffu, s, off);
        if (lane == 0) logits[w] = s + rb[w];
    }
    __syncthreads();
    if (tid == 0) {
        float p[NEXP];
        float mx = logits[0];
#pragma unroll
        for (int e = 1; e < NEXP; e++) mx = fmaxf(mx, logits[e]);
        float sum = 0.f;
#pragma unroll
        for (int e = 0; e < NEXP; e++) { p[e] = expf(logits[e] - mx); sum += p[e]; }
        float invs = 1.0f / sum;
#pragma unroll
        for (int e = 0; e < NEXP; e++) {
            p[e] *= invs;
            atomicAdd(&d_Psum[e], p[e]);
        }
        int i0 = 0;
#pragma unroll
        for (int e = 1; e < NEXP; e++) if (p[e] > p[i0]) i0 = e;
        int i1 = (i0 == 0) ? 1 : 0;
#pragma unroll
        for (int e = 0; e < NEXP; e++) if (e != i0 && p[e] > p[i1]) i1 = e;
        float gsum = p[i0] + p[i1];

        int pos0 = atomicAdd(&d_count[i0], 1);
        d_list[i0 * TOK + pos0] = (int)t;
        d_slot[t * 2 + 0] = i0 * TOK + pos0;
        d_gate[t * 2 + 0] = p[i0] / gsum;

        int pos1 = atomicAdd(&d_count[i1], 1);
        d_list[i1 * TOK + pos1] = (int)t;
        d_slot[t * 2 + 1] = i1 * TOK + pos1;
        d_gate[t * 2 + 1] = p[i1] / gsum;
    }
}

__global__ __launch_bounds__(256) void combine_ln_kernel(
    const float* __restrict__ Y, const float* __restrict__ x1,
    const float* __restrict__ g, const float* __restrict__ bb,
    float* __restrict__ out)
{
    __shared__ float red[256];
    size_t t = blockIdx.x;
    int tid = threadIdx.x;
    int sl0 = d_slot[t * 2 + 0], sl1 = d_slot[t * 2 + 1];
    size_t r0 = (size_t)d_off[sl0 / TOK] + (sl0 % TOK);
    size_t r1 = (size_t)d_off[sl1 / TOK] + (sl1 % TOK);
    float g0 = d_gate[t * 2 + 0], g1 = d_gate[t * 2 + 1];
    float v[4];
    float s = 0.f;
#pragma unroll
    for (int i = 0; i < 4; i++) {
        int d = tid + i * 256;
        float y = g0 * Y[r0 * DM + d] + g1 * Y[r1 * DM + d];
        v[i] = x1[t * DM + d] + y;
        s += v[i];
    }
    float mu = blk_sum(s, red) * (1.0f / DM);
    float sq = 0.f;
#pragma unroll
    for (int i = 0; i < 4; i++) { float c = v[i] - mu; sq += c * c; }
    float var = blk_sum(sq, red) * (1.0f / DM);
    float rstd = rsqrtf(var + 1e-5f);
#pragma unroll
    for (int i = 0; i < 4; i++) {
        int d = tid + i * 256;
        out[t * DM + d] = (v[i] - mu) * rstd * g[d] + bb[d];
    }
}

__global__ void lb_kernel(float* __restrict__ out, int out_size) {
    if (out_size > TOK * DM) {
        float lb = 0.f;
#pragma unroll
        for (int e = 0; e < NEXP; e++) {
            float f = (float)d_count[e] / (float)(TOK * 2);
            float P = d_Psum[e] / (float)TOK;
            lb += f * P;
        }
        out[out_size - 1] = (float)NEXP * lb;
    }
}

// ============================ launch ============================
extern "C" void kernel_launch(void* const* d_in, const int* in_sizes, int n_in,
                              void* d_out, int out_size)
{
    const float* src   = (const float*)d_in[0];
    const float* in_w  = (const float*)d_in[1];
    const float* in_b  = (const float*)d_in[2];
    const float* out_w = (const float*)d_in[3];
    const float* out_b = (const float*)d_in[4];
    const float* ln1g  = (const float*)d_in[5];
    const float* ln1b  = (const float*)d_in[6];
    const float* rw    = (const float*)d_in[7];
    const float* rb    = (const float*)d_in[8];
    const float* w1    = (const float*)d_in[9];
    const float* b1    = (const float*)d_in[10];
    const float* w2    = (const float*)d_in[11];
    const float* b2    = (const float*)d_in[12];
    const float* ln2g  = (const float*)d_in[13];
    const float* ln2b  = (const float*)d_in[14];
    float* out = (float*)d_out;

#define GETP(T, sym) ({ void* _p; cudaGetSymbolAddress(&_p, sym); (T*)_p; })
    float* qkv  = GETP(float, g_qkv);
    float* proj = GETP(float, g_proj);
    float* x1   = GETP(float, g_x1);
    float* Y    = GETP(float, g_Y);
    __half* srch  = GETP(__half, g_srch);
    __half* attnh = GETP(__half, g_attnh);
    __half* wqkv  = GETP(__half, g_wqkv);
    __half* wo    = GETP(__half, g_wo);
    __half* x1h = GETP(__half, g_x1h);
    __half* w1t = GETP(__half, g_w1t);
    __half* w2t = GETP(__half, g_w2t);
    __half* Hh  = GETP(__half, g_Hh);
    int* cnt  = GETP(int, d_count);
    int* offp = GETP(int, d_off);
    int* list = GETP(int, d_list);

    static cudaStream_t s_side = nullptr;
    static cudaEvent_t ev_fork, ev_wo, ev_w1, ev_w2;
    static bool attr_done = false;
    if (!attr_done) {
        cudaFuncSetAttribute(hgemm<0>, cudaFuncAttributeMaxDynamicSharedMemorySize, HGEMM_SMEM);
        cudaFuncSetAttribute(hgemm<1>, cudaFuncAttributeMaxDynamicSharedMemorySize, HGEMM_SMEM);
        cudaFuncSetAttribute(hgemm<2>, cudaFuncAttributeMaxDynamicSharedMemorySize, HGEMM_SMEM);
        cudaFuncSetAttribute(attn_kernel, cudaFuncAttributeMaxDynamicSharedMemorySize, ATTN_SMEM);
        cudaStreamCreateWithFlags(&s_side, cudaStreamNonBlocking);
        cudaEventCreateWithFlags(&ev_fork, cudaEventDisableTiming);
        cudaEventCreateWithFlags(&ev_wo, cudaEventDisableTiming);
        cudaEventCreateWithFlags(&ev_w1, cudaEventDisableTiming);
        cudaEventCreateWithFlags(&ev_w2, cudaEventDisableTiming);
        attr_done = true;
    }

    init_kernel<<<1, 32>>>();

    // main-stream conversions needed immediately
    cvt_h_kernel<<<(TOK * DM / 4 + 255) / 256, 256>>>(src, srch, TOK * DM / 4);
    cvt_h_kernel<<<(D3 * DM / 4 + 255) / 256, 256>>>(in_w, wqkv, D3 * DM / 4);

    // fork side stream for weight prep (independent of attention chain)
    cudaEventRecord(ev_fork, 0);
    cudaStreamWaitEvent(s_side, ev_fork, 0);
    cvt_h_kernel<<<(DM * DM / 4 + 255) / 256, 256, 0, s_side>>>(out_w, wo, DM * DM / 4);
    cudaEventRecord(ev_wo, s_side);
    transpose_half_kernel<<<dim3(DFF / 32, DM / 32, NEXP), dim3(32, 8), 0, s_side>>>(w1, w1t, DM, DFF);
    cudaEventRecord(ev_w1, s_side);
    transpose_half_kernel<<<dim3(DM / 32, DFF / 32, NEXP), dim3(32, 8), 0, s_side>>>(w2, w2t, DFF, DM);
    cudaEventRecord(ev_w2, s_side);

    // QKV = src @ in_w^T + b
    hgemm<0><<<dim3(D3 / BN, TOK / BM), 256, HGEMM_SMEM>>>(
        srch, wqkv, in_b, qkv, nullptr, nullptr, nullptr, nullptr, TOK, D3, DM);

    // attention (writes fp16)
    attn_kernel<<<dim3(NB * NHEAD, SEQ / 16), 128, ATTN_SMEM>>>(qkv, attnh);

    // proj = attn @ out_w^T + b  (needs wo)
    cudaStreamWaitEvent(0, ev_wo, 0);
    hgemm<0><<<dim3(DM / BN, TOK / BM), 256, HGEMM_SMEM>>>(
        attnh, wo, out_b, proj, nullptr, nullptr, nullptr, nullptr, TOK, DM, DM);

    // x1 = LN(src + proj), with fused fp16 cvt
    add_ln_split_kernel<<<TOK, 256>>>(src, proj, ln1g, ln1b, x1, x1h);

    router_kernel<<<TOK, 256>>>(x1, rw, rb);
    offsets_kernel<<<1, 32>>>();

    // H = relu(gather(x1) @ w1 + b1)  (needs w1t)
    cudaStreamWaitEvent(0, ev_w1, 0);
    hgemm<1><<<dim3(DFF / BN, TOK / BM, NEXP), 256, HGEMM_SMEM>>>(
        x1h, w1t, b1, nullptr, Hh, cnt, offp, list, 0, DFF, DM);
    // Y = H @ w2 + b2  (needs w2t)
    cudaStreamWaitEvent(0, ev_w2, 0);
    hgemm<2><<<dim3(DM / BN, TOK / BM, NEXP), 256, HGEMM_SMEM>>>(
        Hh, w2t, b2, Y, nullptr, cnt, offp, nullptr, 0, DM, DFF);

    combine_ln_kernel<<<TOK, 256>>>(Y, x1, ln2g, ln2b, out);
    lb_kernel<<<1, 1>>>(out, out_size);
}

// round 10
// speedup vs baseline: 8.8749x; 2.1128x over previous
#include <cuda_runtime.h>
#include <cuda_bf16.h>
#include <cuda_fp16.h>
#include <cstdint>
#include <math.h>

// Problem constants
#define TOK   4096          // B*S
#define DM    1024          // d_model
#define D3    3072          // 3*d_model
#define NHEAD 16
#define DH    64
#define DFF   4096
#define NEXP  8
#define SEQ   1024
#define NB    4
#define TOTROWS (2*TOK)     // packed expert rows (top-2)

// ============================ scratch globals ============================
__device__ __align__(16) float g_proj[(size_t)TOK * DM];
__device__ __align__(16) float g_x1[(size_t)TOK * DM];
__device__ __align__(16) float g_Y[(size_t)TOTROWS * DM];

__device__ __align__(16) __half g_qkvh[(size_t)TOK * D3];
__device__ __align__(16) __half g_srch[(size_t)TOK * DM];
__device__ __align__(16) __half g_attnh[(size_t)TOK * DM];
__device__ __align__(16) __half g_wqkv[(size_t)D3 * DM];
__device__ __align__(16) __half g_wo[(size_t)DM * DM];
__device__ __align__(16) __half g_x1h[(size_t)TOK * DM];
__device__ __align__(16) __half g_w1t[(size_t)NEXP * DFF * DM];
__device__ __align__(16) __half g_w2t[(size_t)NEXP * DM * DFF];
__device__ __align__(16) __half g_Hh[(size_t)TOTROWS * DFF];

__device__ int   d_count[NEXP];
__device__ int   d_off[NEXP];
__device__ float d_Psum[NEXP];
__device__ int   d_list[NEXP * TOK];
__device__ int   d_slot[TOK * 2];
__device__ float d_gate[TOK * 2];

// ============================ PTX helpers (sm_80-level only) =================
__device__ __forceinline__ uint32_t smem_u32(const void* p) {
    uint32_t a;
    asm("{ .reg .u64 t; cvta.to.shared.u64 t, %1; cvt.u32.u64 %0, t; }"
        : "=r"(a) : "l"(p));
    return a;
}
__device__ __forceinline__ void cp16(uint32_t dst, const void* src, int sz) {
    asm volatile("cp.async.cg.shared.global [%0], [%1], 16, %2;"
                 :: "r"(dst), "l"(src), "r"(sz) : "memory");
}
#define CP_COMMIT() asm volatile("cp.async.commit_group;" ::: "memory")
template<int N_>
__device__ __forceinline__ void cp_wait() {
    asm volatile("cp.async.wait_group %0;" :: "n"(N_) : "memory");
}
__device__ __forceinline__ void ldsm4(uint32_t* r, uint32_t addr) {
    asm volatile("ldmatrix.sync.aligned.m8n8.x4.shared.b16 {%0,%1,%2,%3}, [%4];"
                 : "=r"(r[0]), "=r"(r[1]), "=r"(r[2]), "=r"(r[3]) : "r"(addr));
}
__device__ __forceinline__ void ldsm4t(uint32_t* r, uint32_t addr) {
    asm volatile("ldmatrix.sync.aligned.m8n8.x4.trans.shared.b16 {%0,%1,%2,%3}, [%4];"
                 : "=r"(r[0]), "=r"(r[1]), "=r"(r[2]), "=r"(r[3]) : "r"(addr));
}
__device__ __forceinline__ void mma16816h(float* c, const uint32_t* a, const uint32_t* b) {
    asm volatile("mma.sync.aligned.m16n8k16.row.col.f32.f16.f16.f32 "
                 "{%0,%1,%2,%3}, {%4,%5,%6,%7}, {%8,%9}, {%0,%1,%2,%3};"
                 : "+f"(c[0]), "+f"(c[1]), "+f"(c[2]), "+f"(c[3])
                 : "r"(a[0]), "r"(a[1]), "r"(a[2]), "r"(a[3]),
                   "r"(b[0]), "r"(b[1]));
}

// ============================ unified fp16 GEMM (single-term, BK=64) =========
// MODE 0: dense fp32 out. MODE 1: expert gather + relu + fp16 out.
// MODE 2: expert offset rows, fp32 out. MODE 3: dense fp16 out (no relu).
#define BM 128
#define BN 128
#define MBK 64
#define HA_BYTES 16384
#define HSTG_BYTES 32768
#define HNSTG 3
#define HGEMM_SMEM (HNSTG * HSTG_BYTES)

template<int MODE>
__global__ __launch_bounds__(256, 2) void hgemm(
    const __half* __restrict__ AH, const __half* __restrict__ BH,
    const float* __restrict__ biasBase,
    float* __restrict__ Cf, __half* __restrict__ CH,
    const int* __restrict__ counts, const int* __restrict__ offs,
    const int* __restrict__ listBase,
    int Mfix, int N, int K)
{
    extern __shared__ __half smh[];
    const int tid = threadIdx.x;
    const int lane = tid & 31, wid = tid >> 5;
    const int wm = wid & 3, wn = wid >> 2;
    const int g = lane >> 2, tig = lane & 3;
    const int m0 = blockIdx.y * BM, n0 = blockIdx.x * BN;
    const int e = blockIdx.z;

    int M = Mfix;
    const __half* bhp = BH;
    const float* bias = biasBase;
    const int* lst = nullptr;
    int arow0 = 0, crow0 = 0;
    if (MODE == 1) {
        M = counts[e];
        bhp += (size_t)e * N * K;
        bias += (size_t)e * N;
        lst = listBase + e * TOK;
        crow0 = offs[e];
    } else if (MODE == 2) {
        M = counts[e];
        bhp += (size_t)e * N * K;
        bias += (size_t)e * N;
        arow0 = offs[e]; crow0 = offs[e];
    }
    if (m0 >= M) return;

    const uint32_t sb = smem_u32(smh);

    float acc[2][8][4];
#pragma unroll
    for (int mt = 0; mt < 2; mt++)
#pragma unroll
        for (int nt = 0; nt < 8; nt++)
#pragma unroll
            for (int i = 0; i < 4; i++) acc[mt][nt][i] = 0.0f;

    auto load_stage = [&](int st, int k0) {
        uint32_t sbase = sb + st * HSTG_BYTES;
#pragma unroll
        for (int i = 0; i < 8; i++) {
            int u = tid + i * 256;
            int isB = u >> 10;
            int idx = u & 1023;
            int row = idx >> 3, seg = idx & 7;
            uint32_t dst = sbase + isB * HA_BYTES + row * 128
                         + (uint32_t)((seg ^ (row & 7)) << 4);
            if (!isB) {
                int gr = m0 + row;
                size_t arow; int sz;
                if (MODE == 0 || MODE == 3) {
                    arow = (size_t)gr; sz = 16;
                } else if (MODE == 1) {
                    bool ok = gr < M;
                    arow = ok ? (size_t)lst[gr] : 0; sz = ok ? 16 : 0;
                } else {
                    bool ok = gr < M;
                    arow = (size_t)(arow0 + (ok ? gr : 0)); sz = ok ? 16 : 0;
                }
                cp16(dst, AH + arow * (size_t)K + k0 + seg * 8, sz);
            } else {
                cp16(dst, bhp + (size_t)(n0 + row) * K + k0 + seg * 8, 16);
            }
        }
    };

    const int a_row_in = (lane & 15);
    const int a_seg_in = (lane >> 4);
    const int b_row_in = (lane & 7) + ((lane & 16) ? 8 : 0);
    const int b_seg_in = (lane & 8) ? 1 : 0;

    auto compute = [&](int st) {
        uint32_t sA = sb + st * HSTG_BYTES;
        uint32_t sB = sA + HA_BYTES;
#pragma unroll
        for (int ks = 0; ks < 4; ks++) {
            const int kseg = ks * 2;
            uint32_t ah[2][4];
#pragma unroll
            for (int mt = 0; mt < 2; mt++) {
                int row = wm * 32 + mt * 16 + a_row_in;
                int sl = kseg + a_seg_in;
                ldsm4(ah[mt], sA + row * 128 + ((sl ^ (row & 7)) << 4));
            }
#pragma unroll
            for (int ntp = 0; ntp < 4; ntp++) {
                int row = wn * 64 + ntp * 16 + b_row_in;
                int sl = kseg + b_seg_in;
                uint32_t bh[4];
                ldsm4(bh, sB + row * 128 + ((sl ^ (row & 7)) << 4));
#pragma unroll
                for (int half = 0; half < 2; half++) {
                    int nt = ntp * 2 + half;
#pragma unroll
                    for (int mt = 0; mt < 2; mt++)
                        mma16816h(acc[mt][nt], ah[mt], bh + half * 2);
                }
            }
        }
    };

    const int nk = K / MBK;
    load_stage(0, 0);
    CP_COMMIT();
    load_stage(1, MBK);
    CP_COMMIT();
    for (int c = 0; c < nk; c++) {
        cp_wait<1>();
        __syncthreads();
        compute(c % HNSTG);
        int cn = c + 2;
        if (cn < nk) load_stage(cn % HNSTG, cn * MBK);
        CP_COMMIT();
    }

#pragma unroll
    for (int nt = 0; nt < 8; nt++) {
        int col = n0 + wn * 64 + nt * 8 + 2 * tig;
        float b0 = bias[col], b1 = bias[col + 1];
#pragma unroll
        for (int mt = 0; mt < 2; mt++) {
            int r0 = m0 + wm * 32 + mt * 16 + g;
            float* c = acc[mt][nt];
#pragma unroll
            for (int hh = 0; hh < 2; hh++) {
                int r = r0 + hh * 8;
                if (MODE == 0 || MODE == 3 || r < M) {
                    float v0 = c[hh * 2 + 0] + b0;
                    float v1 = c[hh * 2 + 1] + b1;
                    size_t o = (size_t)(crow0 + r) * N + col;
                    if (MODE == 1) {
                        v0 = fmaxf(v0, 0.0f); v1 = fmaxf(v1, 0.0f);
                        *(__half2*)(CH + o) = __halves2half2(
                            __float2half_rn(v0), __float2half_rn(v1));
                    } else if (MODE == 3) {
                        *(__half2*)(CH + o) = __halves2half2(
                            __float2half_rn(v0), __float2half_rn(v1));
                    } else {
                        *(float2*)(Cf + o) = make_float2(v0, v1);
                    }
                }
            }
        }
    }
}

// ============================ flash attention (tensor core, fp16) ============
// One block = one (b,h) x 64 query rows. 4 warps x 16 rows each.
// Loop over 8 key-tiles of 128. Online softmax in fp32.
#define FA_Q_BYTES 8192
#define FA_KV_BYTES 16384
#define FA_SMEM (FA_Q_BYTES + 2 * FA_KV_BYTES)

__global__ __launch_bounds__(128) void fa_kernel(
    const __half* __restrict__ qkv, __half* __restrict__ oh)
{
    extern __shared__ __half fsm[];
    const uint32_t sQ = smem_u32(fsm);
    const uint32_t sK = sQ + FA_Q_BYTES;
    const uint32_t sV = sK + FA_KV_BYTES;

    const int bh = blockIdx.x;
    const int b = bh >> 4, h = bh & 15;
    const int qt = blockIdx.y;
    const int tid = threadIdx.x;
    const int lane = tid & 31, w = tid >> 5;
    const int g = lane >> 2, tig = lane & 3;
    const int hoff = h * DH;
    const size_t tq0 = (size_t)(b * SEQ + qt * 64);

    // ---- load Q tile (64 rows x 64 halves, swizzled 128B rows) ----
    for (int i = tid; i < 512; i += 128) {
        int row = i >> 3, seg = i & 7;
        uint32_t dst = sQ + row * 128 + (uint32_t)((seg ^ (row & 7)) << 4);
        cp16(dst, qkv + (tq0 + row) * D3 + hoff + seg * 8, 16);
    }
    CP_COMMIT();
    cp_wait<0>();
    __syncthreads();

    // Q fragments: rows w*16 + (lane&15)
    uint32_t qa[4][4];
    {
        int row = w * 16 + (lane & 15);
        uint32_t base = sQ + row * 128;
#pragma unroll
        for (int ks = 0; ks < 4; ks++) {
            int sl = ks * 2 + (lane >> 4);
            ldsm4(qa[ks], base + ((sl ^ (row & 7)) << 4));
        }
    }

    const int b_row_in = (lane & 7) + ((lane & 16) ? 8 : 0);
    const int b_seg_in = (lane & 8) ? 1 : 0;

    float o[8][4];
#pragma unroll
    for (int dt = 0; dt < 8; dt++)
#pragma unroll
        for (int i = 0; i < 4; i++) o[dt][i] = 0.0f;
    float m0 = -1e30f, m1 = -1e30f, l0 = 0.0f, l1 = 0.0f;

    for (int kt = 0; kt < 8; kt++) {
        __syncthreads();   // previous iter done reading K/V
        // load K,V tiles: 128 rows x 64 halves each
        const size_t tk0 = (size_t)(b * SEQ + kt * 128);
        for (int i = tid; i < 1024; i += 128) {
            int row = i >> 3, seg = i & 7;
            uint32_t sw = (uint32_t)((seg ^ (row & 7)) << 4);
            cp16(sK + row * 128 + sw, qkv + (tk0 + row) * D3 + DM + hoff + seg * 8, 16);
            cp16(sV + row * 128 + sw, qkv + (tk0 + row) * D3 + 2 * DM + hoff + seg * 8, 16);
        }
        CP_COMMIT();
        cp_wait<0>();
        __syncthreads();

        // ---- scores: 16 rows x 128 keys ----
        float sc[16][4];
#pragma unroll
        for (int nt = 0; nt < 16; nt++)
#pragma unroll
            for (int i = 0; i < 4; i++) sc[nt][i] = 0.0f;
#pragma unroll
        for (int ks = 0; ks < 4; ks++) {
#pragma unroll
            for (int ntp = 0; ntp < 8; ntp++) {
                int row = ntp * 16 + b_row_in;
                int sl = ks * 2 + b_seg_in;
                uint32_t kb[4];
                ldsm4(kb, sK + row * 128 + ((sl ^ (row & 7)) << 4));
                mma16816h(sc[ntp * 2 + 0], qa[ks], kb + 0);
                mma16816h(sc[ntp * 2 + 1], qa[ks], kb + 2);
            }
        }

        // ---- online softmax update (scale = 0.125 on scores) ----
        float mx0 = -1e30f, mx1 = -1e30f;
#pragma unroll
        for (int nt = 0; nt < 16; nt++) {
            mx0 = fmaxf(mx0, fmaxf(sc[nt][0], sc[nt][1]));
            mx1 = fmaxf(mx1, fmaxf(sc[nt][2], sc[nt][3]));
        }
        mx0 = fmaxf(mx0, __shfl_xor_sync(0xffffffffu, mx0, 1));
        mx0 = fmaxf(mx0, __shfl_xor_sync(0xffffffffu, mx0, 2));
        mx1 = fmaxf(mx1, __shfl_xor_sync(0xffffffffu, mx1, 1));
        mx1 = fmaxf(mx1, __shfl_xor_sync(0xffffffffu, mx1, 2));
        float m0n = fmaxf(m0, mx0 * 0.125f);
        float m1n = fmaxf(m1, mx1 * 0.125f);
        float f0 = __expf(m0 - m0n);
        float f1 = __expf(m1 - m1n);
        m0 = m0n; m1 = m1n;
        l0 *= f0; l1 *= f1;
#pragma unroll
        for (int dt = 0; dt < 8; dt++) {
            o[dt][0] *= f0; o[dt][1] *= f0;
            o[dt][2] *= f1; o[dt][3] *= f1;
        }

        // ---- P (fp16) x V ----
#pragma unroll
        for (int kk = 0; kk < 8; kk++) {
            float p00 = __expf(sc[2 * kk][0] * 0.125f - m0);
            float p01 = __expf(sc[2 * kk][1] * 0.125f - m0);
            float p02 = __expf(sc[2 * kk][2] * 0.125f - m1);
            float p03 = __expf(sc[2 * kk][3] * 0.125f - m1);
            float p10 = __expf(sc[2 * kk + 1][0] * 0.125f - m0);
            float p11 = __expf(sc[2 * kk + 1][1] * 0.125f - m0);
            float p12 = __expf(sc[2 * kk + 1][2] * 0.125f - m1);
            float p13 = __expf(sc[2 * kk + 1][3] * 0.125f - m1);
            l0 += p00 + p01 + p10 + p11;
            l1 += p02 + p03 + p12 + p13;
            uint32_t pa[4];
            __half2 h0 = __halves2half2(__float2half_rn(p00), __float2half_rn(p01));
            __half2 h1 = __halves2half2(__float2half_rn(p02), __float2half_rn(p03));
            __half2 h2 = __halves2half2(__float2half_rn(p10), __float2half_rn(p11));
            __half2 h3 = __halves2half2(__float2half_rn(p12), __float2half_rn(p13));
            pa[0] = *(uint32_t*)&h0;
            pa[1] = *(uint32_t*)&h1;
            pa[2] = *(uint32_t*)&h2;
            pa[3] = *(uint32_t*)&h3;
#pragma unroll
            for (int dp = 0; dp < 4; dp++) {
                int row = kk * 16 + (lane & 15);
                int seg = dp * 2 + (lane >> 4);
                uint32_t vb[4];
                ldsm4t(vb, sV + row * 128 + ((seg ^ (row & 7)) << 4));
                mma16816h(o[dp * 2 + 0], pa, vb + 0);
                mma16816h(o[dp * 2 + 1], pa, vb + 2);
            }
        }
    }

    // ---- finalize ----
    l0 += __shfl_xor_sync(0xffffffffu, l0, 1);
    l0 += __shfl_xor_sync(0xffffffffu, l0, 2);
    l1 += __shfl_xor_sync(0xffffffffu, l1, 1);
    l1 += __shfl_xor_sync(0xffffffffu, l1, 2);
    float inv0 = 1.0f / l0, inv1 = 1.0f / l1;

    size_t r0 = tq0 + w * 16 + g;
    size_t r1 = r0 + 8;
#pragma unroll
    for (int dt = 0; dt < 8; dt++) {
        int col = hoff + dt * 8 + 2 * tig;
        *(__half2*)(oh + r0 * DM + col) = __halves2half2(
            __float2half_rn(o[dt][0] * inv0), __float2half_rn(o[dt][1] * inv0));
        *(__half2*)(oh + r1 * DM + col) = __halves2half2(
            __float2half_rn(o[dt][2] * inv1), __float2half_rn(o[dt][3] * inv1));
    }
}

// ============================ small kernels ============================
__global__ void init_kernel() {
    int i = threadIdx.x;
    if (i < NEXP) { d_count[i] = 0; d_Psum[i] = 0.0f; }
}

__global__ void offsets_kernel() {
    if (threadIdx.x == 0) {
        int a = 0;
#pragma unroll
        for (int e = 0; e < NEXP; e++) { d_off[e] = a; a += d_count[e]; }
    }
}

__global__ __launch_bounds__(256) void cvt_h_kernel(
    const float* __restrict__ x, __half* __restrict__ h, int n4)
{
    int i = blockIdx.x * 256 + threadIdx.x;
    if (i >= n4) return;
    float4 v = ((const float4*)x)[i];
    __half hv[4] = {__float2half_rn(v.x), __float2half_rn(v.y),
                    __float2half_rn(v.z), __float2half_rn(v.w)};
    *(uint2*)(h + i * 4) = *(uint2*)hv;
}

__global__ __launch_bounds__(256) void transpose_half_kernel(
    const float* __restrict__ W, __half* __restrict__ Th, int K, int N)
{
    __shared__ float t[32][33];
    int e = blockIdx.z;
    const float* w = W + (size_t)e * K * N;
    __half* th = Th + (size_t)e * N * K;
    int n0 = blockIdx.x * 32, k0 = blockIdx.y * 32;
    int x = threadIdx.x, y = threadIdx.y;
#pragma unroll
    for (int i = 0; i < 32; i += 8)
        t[y + i][x] = w[(size_t)(k0 + y + i) * N + n0 + x];
    __syncthreads();
#pragma unroll
    for (int i = 0; i < 32; i += 8)
        th[(size_t)(n0 + y + i) * K + k0 + x] = __float2half_rn(t[x][y + i]);
}

// ============================ LN / router / combine / lb ============================
__device__ __forceinline__ float blk_sum(float v, float* red) {
    int tid = threadIdx.x;
    red[tid] = v;
    __syncthreads();
#pragma unroll
    for (int s = 128; s > 0; s >>= 1) {
        if (tid < s) red[tid] += red[tid + s];
        __syncthreads();
    }
    float r = red[0];
    __syncthreads();
    return r;
}

__global__ __launch_bounds__(256) void add_ln_split_kernel(
    const float* __restrict__ a, const float* __restrict__ b,
    const float* __restrict__ g, const float* __restrict__ bb,
    float* __restrict__ out, __half* __restrict__ oh)
{
    __shared__ float red[256];
    size_t t = blockIdx.x;
    int tid = threadIdx.x;
    float v[4];
    float s = 0.f;
#pragma unroll
    for (int i = 0; i < 4; i++) {
        int d = tid + i * 256;
        v[i] = a[t * DM + d] + b[t * DM + d];
        s += v[i];
    }
    float mu = blk_sum(s, red) * (1.0f / DM);
    float sq = 0.f;
#pragma unroll
    for (int i = 0; i < 4; i++) { float c = v[i] - mu; sq += c * c; }
    float var = blk_sum(sq, red) * (1.0f / DM);
    float rstd = rsqrtf(var + 1e-5f);
#pragma unroll
    for (int i = 0; i < 4; i++) {
        int d = tid + i * 256;
        float y = (v[i] - mu) * rstd * g[d] + bb[d];
        out[t * DM + d] = y;
        oh[t * DM + d] = __float2half_rn(y);
    }
}

__global__ __launch_bounds__(256) void router_kernel(
    const float* __restrict__ x1, const float* __restrict__ rw,
    const float* __restrict__ rb)
{
    __shared__ float logits[NEXP];
    size_t t = blockIdx.x;
    int tid = threadIdx.x;
    int w = tid >> 5, lane = tid & 31;
    if (w < NEXP) {
        float s = 0.f;
        for (int k = lane; k < DM; k += 32)
            s += x1[t * DM + k] * rw[(size_t)w * DM + k];
#pragma unroll
        for (int off = 16; off; off >>= 1) s += __shfl_xor_sync(0xffffffffu, s, off);
        if (lane == 0) logits[w] = s + rb[w];
    }
    __syncthreads();
    if (tid == 0) {
        float p[NEXP];
        float mx = logits[0];
#pragma unroll
        for (int e = 1; e < NEXP; e++) mx = fmaxf(mx, logits[e]);
        float sum = 0.f;
#pragma unroll
        for (int e = 0; e < NEXP; e++) { p[e] = expf(logits[e] - mx); sum += p[e]; }
        float invs = 1.0f / sum;
#pragma unroll
        for (int e = 0; e < NEXP; e++) {
            p[e] *= invs;
            atomicAdd(&d_Psum[e], p[e]);
        }
        int i0 = 0;
#pragma unroll
        for (int e = 1; e < NEXP; e++) if (p[e] > p[i0]) i0 = e;
        int i1 = (i0 == 0) ? 1 : 0;
#pragma unroll
        for (int e = 0; e < NEXP; e++) if (e != i0 && p[e] > p[i1]) i1 = e;
        float gsum = p[i0] + p[i1];

        int pos0 = atomicAdd(&d_count[i0], 1);
        d_list[i0 * TOK + pos0] = (int)t;
        d_slot[t * 2 + 0] = i0 * TOK + pos0;
        d_gate[t * 2 + 0] = p[i0] / gsum;

        int pos1 = atomicAdd(&d_count[i1], 1);
        d_list[i1 * TOK + pos1] = (int)t;
        d_slot[t * 2 + 1] = i1 * TOK + pos1;
        d_gate[t * 2 + 1] = p[i1] / gsum;
    }
}

__global__ __launch_bounds__(256) void combine_ln_kernel(
    const float* __restrict__ Y, const float* __restrict__ x1,
    const float* __restrict__ g, const float* __restrict__ bb,
    float* __restrict__ out)
{
    __shared__ float red[256];
    size_t t = blockIdx.x;
    int tid = threadIdx.x;
    int sl0 = d_slot[t * 2 + 0], sl1 = d_slot[t * 2 + 1];
    size_t r0 = (size_t)d_off[sl0 / TOK] + (sl0 % TOK);
    size_t r1 = (size_t)d_off[sl1 / TOK] + (sl1 % TOK);
    float g0 = d_gate[t * 2 + 0], g1 = d_gate[t * 2 + 1];
    float v[4];
    float s = 0.f;
#pragma unroll
    for (int i = 0; i < 4; i++) {
        int d = tid + i * 256;
        float y = g0 * Y[r0 * DM + d] + g1 * Y[r1 * DM + d];
        v[i] = x1[t * DM + d] + y;
        s += v[i];
    }
    float mu = blk_sum(s, red) * (1.0f / DM);
    float sq = 0.f;
#pragma unroll
    for (int i = 0; i < 4; i++) { float c = v[i] - mu; sq += c * c; }
    float var = blk_sum(sq, red) * (1.0f / DM);
    float rstd = rsqrtf(var + 1e-5f);
#pragma unroll
    for (int i = 0; i < 4; i++) {
        int d = tid + i * 256;
        out[t * DM + d] = (v[i] - mu) * rstd * g[d] + bb[d];
    }
}

__global__ void lb_kernel(float* __restrict__ out, int out_size) {
    if (out_size > TOK * DM) {
        float lb = 0.f;
#pragma unroll
        for (int e = 0; e < NEXP; e++) {
            float f = (float)d_count[e] / (float)(TOK * 2);
            float P = d_Psum[e] / (float)TOK;
            lb += f * P;
        }
        out[out_size - 1] = (float)NEXP * lb;
    }
}

// ============================ launch ============================
extern "C" void kernel_launch(void* const* d_in, const int* in_sizes, int n_in,
                              void* d_out, int out_size)
{
    const float* src   = (const float*)d_in[0];
    const float* in_w  = (const float*)d_in[1];
    const float* in_b  = (const float*)d_in[2];
    const float* out_w = (const float*)d_in[3];
    const float* out_b = (const float*)d_in[4];
    const float* ln1g  = (const float*)d_in[5];
    const float* ln1b  = (const float*)d_in[6];
    const float* rw    = (const float*)d_in[7];
    const float* rb    = (const float*)d_in[8];
    const float* w1    = (const float*)d_in[9];
    const float* b1    = (const float*)d_in[10];
    const float* w2    = (const float*)d_in[11];
    const float* b2    = (const float*)d_in[12];
    const float* ln2g  = (const float*)d_in[13];
    const float* ln2b  = (const float*)d_in[14];
    float* out = (float*)d_out;

#define GETP(T, sym) ({ void* _p; cudaGetSymbolAddress(&_p, sym); (T*)_p; })
    float* proj = GETP(float, g_proj);
    float* x1   = GETP(float, g_x1);
    float* Y    = GETP(float, g_Y);
    __half* qkvh  = GETP(__half, g_qkvh);
    __half* srch  = GETP(__half, g_srch);
    __half* attnh = GETP(__half, g_attnh);
    __half* wqkv  = GETP(__half, g_wqkv);
    __half* wo    = GETP(__half, g_wo);
    __half* x1h = GETP(__half, g_x1h);
    __half* w1t = GETP(__half, g_w1t);
    __half* w2t = GETP(__half, g_w2t);
    __half* Hh  = GETP(__half, g_Hh);
    int* cnt  = GETP(int, d_count);
    int* offp = GETP(int, d_off);
    int* list = GETP(int, d_list);

    static cudaStream_t s_side = nullptr;
    static cudaEvent_t ev_fork, ev_wo, ev_w1, ev_w2;
    static bool attr_done = false;
    if (!attr_done) {
        cudaFuncSetAttribute(hgemm<0>, cudaFuncAttributeMaxDynamicSharedMemorySize, HGEMM_SMEM);
        cudaFuncSetAttribute(hgemm<1>, cudaFuncAttributeMaxDynamicSharedMemorySize, HGEMM_SMEM);
        cudaFuncSetAttribute(hgemm<2>, cudaFuncAttributeMaxDynamicSharedMemorySize, HGEMM_SMEM);
        cudaFuncSetAttribute(hgemm<3>, cudaFuncAttributeMaxDynamicSharedMemorySize, HGEMM_SMEM);
        cudaFuncSetAttribute(fa_kernel, cudaFuncAttributeMaxDynamicSharedMemorySize, FA_SMEM);
        cudaStreamCreateWithFlags(&s_side, cudaStreamNonBlocking);
        cudaEventCreateWithFlags(&ev_fork, cudaEventDisableTiming);
        cudaEventCreateWithFlags(&ev_wo, cudaEventDisableTiming);
        cudaEventCreateWithFlags(&ev_w1, cudaEventDisableTiming);
        cudaEventCreateWithFlags(&ev_w2, cudaEventDisableTiming);
        attr_done = true;
    }

    init_kernel<<<1, 32>>>();

    // main-stream conversions needed immediately
    cvt_h_kernel<<<(TOK * DM / 4 + 255) / 256, 256>>>(src, srch, TOK * DM / 4);
    cvt_h_kernel<<<(D3 * DM / 4 + 255) / 256, 256>>>(in_w, wqkv, D3 * DM / 4);

    // fork side stream for weight prep
    cudaEventRecord(ev_fork, 0);
    cudaStreamWaitEvent(s_side, ev_fork, 0);
    cvt_h_kernel<<<(DM * DM / 4 + 255) / 256, 256, 0, s_side>>>(out_w, wo, DM * DM / 4);
    cudaEventRecord(ev_wo, s_side);
    transpose_half_kernel<<<dim3(DFF / 32, DM / 32, NEXP), dim3(32, 8), 0, s_side>>>(w1, w1t, DM, DFF);
    cudaEventRecord(ev_w1, s_side);
    transpose_half_kernel<<<dim3(DM / 32, DFF / 32, NEXP), dim3(32, 8), 0, s_side>>>(w2, w2t, DFF, DM);
    cudaEventRecord(ev_w2, s_side);

    // QKV = src @ in_w^T + b  (fp16 out)
    hgemm<3><<<dim3(D3 / BN, TOK / BM), 256, HGEMM_SMEM>>>(
        srch, wqkv, in_b, nullptr, qkvh, nullptr, nullptr, nullptr, TOK, D3, DM);

    // flash attention (fp16 in/out)
    fa_kernel<<<dim3(NB * NHEAD, SEQ / 64), 128, FA_SMEM>>>(qkvh, attnh);

    // proj = attn @ out_w^T + b
    cudaStreamWaitEvent(0, ev_wo, 0);
    hgemm<0><<<dim3(DM / BN, TOK / BM), 256, HGEMM_SMEM>>>(
        attnh, wo, out_b, proj, nullptr, nullptr, nullptr, nullptr, TOK, DM, DM);

    // x1 = LN(src + proj), with fused fp16 cvt
    add_ln_split_kernel<<<TOK, 256>>>(src, proj, ln1g, ln1b, x1, x1h);

    router_kernel<<<TOK, 256>>>(x1, rw, rb);
    offsets_kernel<<<1, 32>>>();

    // H = relu(gather(x1) @ w1 + b1)
    cudaStreamWaitEvent(0, ev_w1, 0);
    hgemm<1><<<dim3(DFF / BN, TOK / BM, NEXP), 256, HGEMM_SMEM>>>(
        x1h, w1t, b1, nullptr, Hh, cnt, offp, list, 0, DFF, DM);
    // Y = H @ w2 + b2
    cudaStreamWaitEvent(0, ev_w2, 0);
    hgemm<2><<<dim3(DM / BN, TOK / BM, NEXP), 256, HGEMM_SMEM>>>(
        Hh, w2t, b2, Y, nullptr, cnt, offp, nullptr, 0, DM, DFF);

    combine_ln_kernel<<<TOK, 256>>>(Y, x1, ln2g, ln2b, out);
    lb_kernel<<<1, 1>>>(out, out_size);
}